// round 1
// baseline (speedup 1.0000x reference)
#include <cuda_runtime.h>
#include <cuda_bf16.h>
#include <math_constants.h>

// Problem constants (fixed by reference setup_inputs)
#define Nn   50000
#define Ee   800000
#define E2   (Ee + Nn)
#define Fdim 128
#define D1   256   // 4 heads x 64
#define D2   128   // 1 head x 128
#define D3   64    // GCN out
#define Bb   512
#define NCc  10
#define NB_SCAN ((Nn + 1023) / 1024)

// ---------------- scratch (device globals; no allocation allowed) -----------
__device__ __align__(16) int   g_deg[Nn];
__device__ __align__(16) int   g_rowstart[Nn + 1];
__device__ __align__(16) int   g_cursor[Nn];
__device__ __align__(16) int   g_col[E2];
__device__ __align__(16) int   g_partials[NB_SCAN + 1];

__device__ __align__(16) float g_h1[(size_t)Nn * D1];
__device__ __align__(16) float g_x1[(size_t)Nn * D1];
__device__ __align__(16) float g_h2[(size_t)Nn * D2];
__device__ __align__(16) float g_x2[(size_t)Nn * D2];
__device__ __align__(16) float g_h3[(size_t)Nn * D3];
__device__ __align__(16) float g_x3[(size_t)Nn * D3];
__device__ __align__(16) float g_scs1[Nn * 4];
__device__ __align__(16) float g_scd1[Nn * 4];
__device__ __align__(16) float g_scs2[Nn];
__device__ __align__(16) float g_scd2[Nn];
__device__ __align__(16) float g_dis[Nn];
__device__ __align__(16) float g_pool[Bb * D3];
__device__ __align__(16) float g_cnt[Bb];

// ---------------- small helpers ---------------------------------------------
__device__ __forceinline__ float lrelu(float v, float s) { return v > 0.f ? v : s * v; }

// ---------------- CSR build --------------------------------------------------
__global__ void k_init_deg(int* deg, int n) {
    int i = blockIdx.x * blockDim.x + threadIdx.x;
    if (i < n) deg[i] = 1;  // self-loop
}

__global__ void k_deg_scatter(const int* __restrict__ dst, int* deg, int e) {
    int i = blockIdx.x * blockDim.x + threadIdx.x;
    if (i < e) atomicAdd(&deg[dst[i]], 1);
}

__global__ void k_scan_block(const int* __restrict__ deg, int* __restrict__ rowstart,
                             int* __restrict__ partials, int n) {
    __shared__ int s[1024];
    int t = threadIdx.x;
    int gi = blockIdx.x * 1024 + t;
    int v = (gi < n) ? deg[gi] : 0;
    s[t] = v;
    __syncthreads();
#pragma unroll
    for (int off = 1; off < 1024; off <<= 1) {
        int xv = (t >= off) ? s[t - off] : 0;
        __syncthreads();
        s[t] += xv;
        __syncthreads();
    }
    if (gi < n) rowstart[gi] = s[t];          // block-inclusive
    if (t == 1023) partials[blockIdx.x] = s[t];
}

__global__ void k_scan_partials(int* partials, int* rowstart, int nb, int n) {
    if (threadIdx.x == 0) {
        int run = 0;
        for (int i = 0; i < nb; i++) { int v = partials[i]; partials[i] = run; run += v; }
        rowstart[n] = run;  // total = N + E
    }
}

__global__ void k_scan_finalize(const int* __restrict__ deg, int* __restrict__ rowstart,
                                const int* __restrict__ partials, int n) {
    int gi = blockIdx.x * 1024 + threadIdx.x;
    if (gi < n) rowstart[gi] = rowstart[gi] - deg[gi] + partials[blockIdx.x];
}

__global__ void k_fill_self(const int* __restrict__ rowstart, int* __restrict__ col,
                            int* __restrict__ cursor, int n) {
    int i = blockIdx.x * blockDim.x + threadIdx.x;
    if (i < n) { int rs = rowstart[i]; col[rs] = i; cursor[i] = rs + 1; }
}

__global__ void k_scatter_edges(const int* __restrict__ src, const int* __restrict__ dst,
                                int* cursor, int* __restrict__ col, int e) {
    int i = blockIdx.x * blockDim.x + threadIdx.x;
    if (i < e) {
        int pos = atomicAdd(&cursor[dst[i]], 1);
        col[pos] = src[i];
    }
}

// ---------------- fp32 tiled GEMM: C[M,Ncol] = A[M,K] @ B[K,Ncol] ------------
// BM=BN=64, BK=16, 256 threads, 4x4 register tile. Ncol, K multiples of {64,16}.
__global__ void __launch_bounds__(256) k_gemm(const float* __restrict__ A,
                                              const float* __restrict__ Bm,
                                              float* __restrict__ C,
                                              int M, int Ncol, int K) {
    __shared__ float As[16][68];
    __shared__ float Bs[16][68];
    int tid = threadIdx.x;
    int tx = tid & 15, ty = tid >> 4;
    int bm0 = blockIdx.x * 64, bn0 = blockIdx.y * 64;

    int ar  = tid >> 2, ak4 = (tid & 3) << 2;   // A loader: row, k-quad
    int bk  = tid >> 4, bc4 = (tid & 15) << 2;  // B loader: k, col-quad

    float acc[4][4] = {};
    for (int kt = 0; kt < K; kt += 16) {
        float4 av = make_float4(0.f, 0.f, 0.f, 0.f);
        int arow = bm0 + ar;
        if (arow < M) av = *(const float4*)(A + (size_t)arow * K + kt + ak4);
        As[ak4 + 0][ar] = av.x; As[ak4 + 1][ar] = av.y;
        As[ak4 + 2][ar] = av.z; As[ak4 + 3][ar] = av.w;
        float4 bv = *(const float4*)(Bm + (size_t)(kt + bk) * Ncol + bn0 + bc4);
        *(float4*)(&Bs[bk][bc4]) = bv;
        __syncthreads();
#pragma unroll
        for (int kk = 0; kk < 16; kk++) {
            float4 a = *(const float4*)(&As[kk][ty << 2]);
            float4 b = *(const float4*)(&Bs[kk][tx << 2]);
            float ax[4] = {a.x, a.y, a.z, a.w};
            float bx[4] = {b.x, b.y, b.z, b.w};
#pragma unroll
            for (int i = 0; i < 4; i++)
#pragma unroll
                for (int j = 0; j < 4; j++) acc[i][j] += ax[i] * bx[j];
        }
        __syncthreads();
    }
#pragma unroll
    for (int i = 0; i < 4; i++) {
        int row = bm0 + (ty << 2) + i;
        if (row < M) {
            float4 o = make_float4(acc[i][0], acc[i][1], acc[i][2], acc[i][3]);
            *(float4*)(C + (size_t)row * Ncol + bn0 + (tx << 2)) = o;
        }
    }
}

// ---------------- GAT attention scores ---------------------------------------
template <int HEADS, int CH>
__global__ void k_scores(const float* __restrict__ h, const float* __restrict__ a_src,
                         const float* __restrict__ a_dst, float* __restrict__ scs,
                         float* __restrict__ scd, int n) {
    int node = blockIdx.x * 8 + (threadIdx.x >> 5);
    int lane = threadIdx.x & 31;
    if (node >= n) return;
    const int D = HEADS * CH;
#pragma unroll
    for (int hd = 0; hd < HEADS; hd++) {
        float ps = 0.f, pd = 0.f;
#pragma unroll
        for (int jj = 0; jj < CH / 32; jj++) {
            int cc = lane + 32 * jj;
            float hv = h[(size_t)node * D + hd * CH + cc];
            ps += hv * a_src[hd * CH + cc];
            pd += hv * a_dst[hd * CH + cc];
        }
#pragma unroll
        for (int off = 16; off; off >>= 1) {
            ps += __shfl_xor_sync(0xffffffffu, ps, off);
            pd += __shfl_xor_sync(0xffffffffu, pd, off);
        }
        if (lane == 0) { scs[node * HEADS + hd] = ps; scd[node * HEADS + hd] = pd; }
    }
}

// ---------------- GAT aggregation (softmax over incoming edges + scatter) ----
template <int HEADS, int CH>
__global__ void k_gat_agg(const float* __restrict__ h, const float* __restrict__ scs,
                          const float* __restrict__ scd_arr,
                          const float* __restrict__ bias,
                          const float* __restrict__ bn_g, const float* __restrict__ bn_b,
                          const int* __restrict__ rowstart, const int* __restrict__ col,
                          float* __restrict__ xout, int n) {
    const int D = HEADS * CH, PER = D / 32;
    int node = blockIdx.x * 8 + (threadIdx.x >> 5);
    int lane = threadIdx.x & 31;
    if (node >= n) return;
    int rs = rowstart[node], re = rowstart[node + 1];

    float scd[HEADS];
#pragma unroll
    for (int hd = 0; hd < HEADS; hd++) scd[hd] = scd_arr[node * HEADS + hd];

    // pass 1: per-head max over edges
    float m[HEADS];
#pragma unroll
    for (int hd = 0; hd < HEADS; hd++) m[hd] = -1e30f;
    for (int k = rs + lane; k < re; k += 32) {
        int s = col[k];
#pragma unroll
        for (int hd = 0; hd < HEADS; hd++) {
            float e = scs[s * HEADS + hd] + scd[hd];
            e = lrelu(e, 0.2f);
            m[hd] = fmaxf(m[hd], e);
        }
    }
#pragma unroll
    for (int hd = 0; hd < HEADS; hd++)
#pragma unroll
        for (int off = 16; off; off >>= 1)
            m[hd] = fmaxf(m[hd], __shfl_xor_sync(0xffffffffu, m[hd], off));

    // pass 2: exp-sum
    float ssum[HEADS] = {};
    for (int k = rs + lane; k < re; k += 32) {
        int s = col[k];
#pragma unroll
        for (int hd = 0; hd < HEADS; hd++) {
            float e = scs[s * HEADS + hd] + scd[hd];
            e = lrelu(e, 0.2f);
            ssum[hd] += __expf(e - m[hd]);
        }
    }
#pragma unroll
    for (int hd = 0; hd < HEADS; hd++) {
#pragma unroll
        for (int off = 16; off; off >>= 1)
            ssum[hd] += __shfl_xor_sync(0xffffffffu, ssum[hd], off);
        ssum[hd] = 1.f / (ssum[hd] + 1e-16f);
    }

    // pass 3: weighted aggregate (whole warp walks edges serially; coalesced row gather)
    float acc[PER] = {};
    for (int k = rs; k < re; k++) {
        int s = col[k];
        float al[HEADS];
#pragma unroll
        for (int hd = 0; hd < HEADS; hd++) {
            float e = scs[s * HEADS + hd] + scd[hd];
            e = lrelu(e, 0.2f);
            al[hd] = __expf(e - m[hd]) * ssum[hd];
        }
        const float* hp = h + (size_t)s * D;
#pragma unroll
        for (int j = 0; j < PER; j++) acc[j] += hp[lane + 32 * j] * al[(32 * j) / CH];
    }

    // epilogue: + bias, LeakyReLU(0.01), BatchNorm(eval)
    const float inv_bn = rsqrtf(1.0f + 1e-5f);
#pragma unroll
    for (int j = 0; j < PER; j++) {
        int c = lane + 32 * j;
        float t = acc[j] + bias[c];
        t = lrelu(t, 0.01f);
        xout[(size_t)node * D + c] = t * (bn_g[c] * inv_bn) + bn_b[c];
    }
}

// ---------------- GCN --------------------------------------------------------
__global__ void k_dis(const int* __restrict__ rowstart, float* __restrict__ dis, int n) {
    int i = blockIdx.x * blockDim.x + threadIdx.x;
    if (i < n) {
        int d = rowstart[i + 1] - rowstart[i];
        dis[i] = (d > 0) ? rsqrtf((float)d) : 0.f;
    }
}

__global__ void k_gcn_agg(const float* __restrict__ h, const float* __restrict__ dis,
                          const float* __restrict__ bg,
                          const int* __restrict__ rowstart, const int* __restrict__ col,
                          float* __restrict__ xout, int n) {
    int node = blockIdx.x * 8 + (threadIdx.x >> 5);
    int lane = threadIdx.x & 31;
    if (node >= n) return;
    int rs = rowstart[node], re = rowstart[node + 1];
    float wi = dis[node];
    float acc0 = 0.f, acc1 = 0.f;
    for (int k = rs; k < re; k++) {
        int s = col[k];
        float w = dis[s] * wi;
        const float* hp = h + (size_t)s * D3;
        acc0 += hp[lane] * w;
        acc1 += hp[lane + 32] * w;
    }
    float t0 = lrelu(acc0 + bg[lane], 0.01f);
    float t1 = lrelu(acc1 + bg[lane + 32], 0.01f);
    xout[(size_t)node * D3 + lane] = t0;
    xout[(size_t)node * D3 + lane + 32] = t1;
}

// ---------------- pooling + MLP ----------------------------------------------
__global__ void k_zero(float* p, int n) {
    int i = blockIdx.x * blockDim.x + threadIdx.x;
    if (i < n) p[i] = 0.f;
}

__global__ void k_pool(const float* __restrict__ x3, const int* __restrict__ batch,
                       float* pool, float* cnt, int n) {
    int node = blockIdx.x * 8 + (threadIdx.x >> 5);
    int lane = threadIdx.x & 31;
    if (node >= n) return;
    int b = batch[node];
    atomicAdd(&pool[b * D3 + lane], x3[(size_t)node * D3 + lane]);
    atomicAdd(&pool[b * D3 + lane + 32], x3[(size_t)node * D3 + lane + 32]);
    if (lane == 0) atomicAdd(&cnt[b], 1.f);
}

__global__ void __launch_bounds__(128) k_mlp(const float* __restrict__ pool,
                                             const float* __restrict__ cnt,
                                             const float* __restrict__ l1W,
                                             const float* __restrict__ l1b,
                                             const float* __restrict__ g3,
                                             const float* __restrict__ b3,
                                             const float* __restrict__ l2W,
                                             const float* __restrict__ l2b,
                                             float* __restrict__ out) {
    int b = blockIdx.x;
    int t = threadIdx.x;
    __shared__ float sp[64];
    __shared__ float sy[128];
    if (t < 64) sp[t] = pool[b * D3 + t] / fmaxf(cnt[b], 1.f);
    __syncthreads();
    float v = l1b[t];
#pragma unroll
    for (int k = 0; k < 64; k++) v += sp[k] * l1W[k * 128 + t];
    v = v * (g3[t] * rsqrtf(1.0f + 1e-5f)) + b3[t];
    v = lrelu(v, 0.01f);
    sy[t] = v;
    __syncthreads();
    if (t < NCc) {
        float o = l2b[t];
#pragma unroll
        for (int k = 0; k < 128; k++) o += sy[k] * l2W[k * NCc + t];
        out[b * NCc + t] = o;
    }
}

// ---------------- launch -----------------------------------------------------
extern "C" void kernel_launch(void* const* d_in, const int* in_sizes, int n_in,
                              void* d_out, int out_size) {
    const float* x      = (const float*)d_in[0];
    const int*   ei     = (const int*)d_in[1];
    const int*   batch  = (const int*)d_in[2];
    const float* W1     = (const float*)d_in[3];
    const float* a_src1 = (const float*)d_in[4];
    const float* a_dst1 = (const float*)d_in[5];
    const float* b1     = (const float*)d_in[6];
    const float* W2     = (const float*)d_in[7];
    const float* a_src2 = (const float*)d_in[8];
    const float* a_dst2 = (const float*)d_in[9];
    const float* b2     = (const float*)d_in[10];
    const float* Wg     = (const float*)d_in[11];
    const float* bg     = (const float*)d_in[12];
    const float* bn1g   = (const float*)d_in[13];
    const float* bn1b   = (const float*)d_in[14];
    const float* bn2g   = (const float*)d_in[15];
    const float* bn2b   = (const float*)d_in[16];
    const float* bn3g   = (const float*)d_in[17];
    const float* bn3b   = (const float*)d_in[18];
    const float* l1W    = (const float*)d_in[19];
    const float* l1b    = (const float*)d_in[20];
    const float* l2W    = (const float*)d_in[21];
    const float* l2b    = (const float*)d_in[22];
    float* out = (float*)d_out;

    int *deg, *rowstart, *cursor, *col, *partials;
    float *h1, *x1, *h2, *x2, *h3, *x3, *scs1, *scd1, *scs2, *scd2, *dis, *pool, *cnt;
    cudaGetSymbolAddress((void**)&deg, g_deg);
    cudaGetSymbolAddress((void**)&rowstart, g_rowstart);
    cudaGetSymbolAddress((void**)&cursor, g_cursor);
    cudaGetSymbolAddress((void**)&col, g_col);
    cudaGetSymbolAddress((void**)&partials, g_partials);
    cudaGetSymbolAddress((void**)&h1, g_h1);
    cudaGetSymbolAddress((void**)&x1, g_x1);
    cudaGetSymbolAddress((void**)&h2, g_h2);
    cudaGetSymbolAddress((void**)&x2, g_x2);
    cudaGetSymbolAddress((void**)&h3, g_h3);
    cudaGetSymbolAddress((void**)&x3, g_x3);
    cudaGetSymbolAddress((void**)&scs1, g_scs1);
    cudaGetSymbolAddress((void**)&scd1, g_scd1);
    cudaGetSymbolAddress((void**)&scs2, g_scs2);
    cudaGetSymbolAddress((void**)&scd2, g_scd2);
    cudaGetSymbolAddress((void**)&dis, g_dis);
    cudaGetSymbolAddress((void**)&pool, g_pool);
    cudaGetSymbolAddress((void**)&cnt, g_cnt);

    const int* src = ei;
    const int* dst = ei + Ee;

    // ---- CSR build (dst-indexed, self-loop first per row) ----
    k_init_deg<<<(Nn + 255) / 256, 256>>>(deg, Nn);
    k_deg_scatter<<<(Ee + 255) / 256, 256>>>(dst, deg, Ee);
    k_scan_block<<<NB_SCAN, 1024>>>(deg, rowstart, partials, Nn);
    k_scan_partials<<<1, 32>>>(partials, rowstart, NB_SCAN, Nn);
    k_scan_finalize<<<NB_SCAN, 1024>>>(deg, rowstart, partials, Nn);
    k_fill_self<<<(Nn + 255) / 256, 256>>>(rowstart, col, cursor, Nn);
    k_scatter_edges<<<(Ee + 255) / 256, 256>>>(src, dst, cursor, col, Ee);

    // ---- GAT layer 1: F(128) -> 4 heads x 64 ----
    k_gemm<<<dim3((Nn + 63) / 64, D1 / 64), 256>>>(x, W1, h1, Nn, D1, Fdim);
    k_scores<4, 64><<<(Nn + 7) / 8, 256>>>(h1, a_src1, a_dst1, scs1, scd1, Nn);
    k_gat_agg<4, 64><<<(Nn + 7) / 8, 256>>>(h1, scs1, scd1, b1, bn1g, bn1b,
                                            rowstart, col, x1, Nn);

    // ---- GAT layer 2: 256 -> 1 head x 128 ----
    k_gemm<<<dim3((Nn + 63) / 64, D2 / 64), 256>>>(x1, W2, h2, Nn, D2, D1);
    k_scores<1, 128><<<(Nn + 7) / 8, 256>>>(h2, a_src2, a_dst2, scs2, scd2, Nn);
    k_gat_agg<1, 128><<<(Nn + 7) / 8, 256>>>(h2, scs2, scd2, b2, bn2g, bn2b,
                                             rowstart, col, x2, Nn);

    // ---- GCN: 128 -> 64 ----
    k_gemm<<<dim3((Nn + 63) / 64, D3 / 64), 256>>>(x2, Wg, h3, Nn, D3, D2);
    k_dis<<<(Nn + 255) / 256, 256>>>(rowstart, dis, Nn);
    k_gcn_agg<<<(Nn + 7) / 8, 256>>>(h3, dis, bg, rowstart, col, x3, Nn);

    // ---- global mean pool + MLP head ----
    k_zero<<<(Bb * D3 + 255) / 256, 256>>>(pool, Bb * D3);
    k_zero<<<(Bb + 255) / 256, 256>>>(cnt, Bb);
    k_pool<<<(Nn + 7) / 8, 256>>>(x3, batch, pool, cnt, Nn);
    k_mlp<<<Bb, 128>>>(pool, cnt, l1W, l1b, bn3g, bn3b, l2W, l2b, out);
}

// round 3
// speedup vs baseline: 1.1366x; 1.1366x over previous
#include <cuda_runtime.h>
#include <cuda_bf16.h>
#include <math_constants.h>
#include <cstdint>

// Problem constants (fixed by reference setup_inputs)
#define Nn   50000
#define Ee   800000
#define E2   (Ee + Nn)
#define Fdim 128
#define D1   256   // 4 heads x 64
#define D2   128   // 1 head x 128
#define D3   64    // GCN out
#define Bb   512
#define NCc  10
#define NB_SCAN ((Nn + 1023) / 1024)

typedef unsigned int u32;

// ---------------- scratch (device globals; no allocation allowed) -----------
__device__ __align__(16) int   g_deg[Nn];
__device__ __align__(16) int   g_rowstart[Nn + 1];
__device__ __align__(16) int   g_cursor[Nn];
__device__ __align__(16) int   g_col[E2];
__device__ __align__(16) int   g_partials[NB_SCAN + 1];

__device__ __align__(16) float g_h1[(size_t)Nn * D1];
__device__ __align__(16) float g_x1[(size_t)Nn * D1];
__device__ __align__(16) float g_h2[(size_t)Nn * D2];
__device__ __align__(16) float g_x2[(size_t)Nn * D2];
__device__ __align__(16) float g_h3[(size_t)Nn * D3];
__device__ __align__(16) float g_x3[(size_t)Nn * D3];
__device__ __align__(16) float g_scs1[Nn * 4];
__device__ __align__(16) float g_scd1[Nn * 4];
__device__ __align__(16) float g_scs2[Nn];
__device__ __align__(16) float g_scd2[Nn];
__device__ __align__(16) float g_dis[Nn];
__device__ __align__(16) float g_pool[Bb * D3];
__device__ __align__(16) float g_cnt[Bb];

// ---------------- small helpers ---------------------------------------------
__device__ __forceinline__ float lrelu(float v, float s) { return v > 0.f ? v : s * v; }

__device__ __forceinline__ u32 f2tf32(float x) {
    u32 r;
    asm("cvt.rna.tf32.f32 %0, %1;" : "=r"(r) : "f"(x));
    return r;
}

__device__ __forceinline__ void mma_tf32(float* c, const u32* a, const u32* b) {
    asm volatile(
        "mma.sync.aligned.m16n8k8.row.col.f32.tf32.tf32.f32 "
        "{%0,%1,%2,%3}, {%4,%5,%6,%7}, {%8,%9}, {%0,%1,%2,%3};"
        : "+f"(c[0]), "+f"(c[1]), "+f"(c[2]), "+f"(c[3])
        : "r"(a[0]), "r"(a[1]), "r"(a[2]), "r"(a[3]), "r"(b[0]), "r"(b[1]));
}

// ---------------- CSR build --------------------------------------------------
__global__ void k_init_deg(int* deg, int n) {
    int i = blockIdx.x * blockDim.x + threadIdx.x;
    if (i < n) deg[i] = 1;  // self-loop
}

__global__ void k_deg_scatter(const int* __restrict__ dst, int* deg, int e) {
    int i = blockIdx.x * blockDim.x + threadIdx.x;
    if (i < e) atomicAdd(&deg[dst[i]], 1);
}

__global__ void k_scan_block(const int* __restrict__ deg, int* __restrict__ rowstart,
                             int* __restrict__ partials, int n) {
    __shared__ int s[1024];
    int t = threadIdx.x;
    int gi = blockIdx.x * 1024 + t;
    int v = (gi < n) ? deg[gi] : 0;
    s[t] = v;
    __syncthreads();
#pragma unroll
    for (int off = 1; off < 1024; off <<= 1) {
        int xv = (t >= off) ? s[t - off] : 0;
        __syncthreads();
        s[t] += xv;
        __syncthreads();
    }
    if (gi < n) rowstart[gi] = s[t];          // block-inclusive
    if (t == 1023) partials[blockIdx.x] = s[t];
}

// parallel exclusive scan of <=64 partials (one block, 64 threads)
__global__ void k_scan_partials(int* partials, int* rowstart, int nb, int n) {
    __shared__ int wsum[2];
    int t = threadIdx.x;
    int lane = t & 31, w = t >> 5;
    int orig = (t < nb) ? partials[t] : 0;
    int v = orig;
#pragma unroll
    for (int o = 1; o < 32; o <<= 1) {
        int xv = __shfl_up_sync(0xffffffffu, v, o);
        if (lane >= o) v += xv;
    }
    if (lane == 31) wsum[w] = v;
    __syncthreads();
    if (w == 1) v += wsum[0];
    if (t < nb) partials[t] = v - orig;   // exclusive
    if (t == 63) rowstart[n] = v;         // total (= N + E)
}

__global__ void k_scan_finalize(const int* __restrict__ deg, int* __restrict__ rowstart,
                                const int* __restrict__ partials, int n) {
    int gi = blockIdx.x * 1024 + threadIdx.x;
    if (gi < n) rowstart[gi] = rowstart[gi] - deg[gi] + partials[blockIdx.x];
}

__global__ void k_fill_self(const int* __restrict__ rowstart, int* __restrict__ col,
                            int* __restrict__ cursor, int n) {
    int i = blockIdx.x * blockDim.x + threadIdx.x;
    if (i < n) { int rs = rowstart[i]; col[rs] = i; cursor[i] = rs + 1; }
}

__global__ void k_scatter_edges(const int* __restrict__ src, const int* __restrict__ dst,
                                int* cursor, int* __restrict__ col, int e) {
    int i = blockIdx.x * blockDim.x + threadIdx.x;
    if (i < e) {
        int pos = atomicAdd(&cursor[dst[i]], 1);
        col[pos] = src[i];
    }
}

// ---------------- 3xTF32 tensor-core GEMM ------------------------------------
// C[M,N] = A[M,K] @ B[K,N].  BM=128, BN=64, BK=16, 256 threads (8 warps, 4x2),
// warp tile 32x32 (2 m-frags x 4 n-frags of m16n8k8). N mult of 64, K mult of 16.
// 3xTF32 split: acc += Ahi*Bhi + Ahi*Blo + Alo*Bhi  (fp32-grade accuracy).
__global__ void __launch_bounds__(256) k_gemm_tc(const float* __restrict__ A,
                                                 const float* __restrict__ B,
                                                 float* __restrict__ C,
                                                 int M, int N, int K) {
    // A tile [m][k], stride 20: frag-load bank = (4g+t) mod 32 -> conflict-free
    __shared__ u32 As_hi[128][20], As_lo[128][20];
    // B tile [k][n], stride 72: frag-load bank = (8t+g) mod 32 -> conflict-free
    __shared__ u32 Bs_hi[16][72], Bs_lo[16][72];

    int tid = threadIdx.x;
    int bm0 = blockIdx.x * 128, bn0 = blockIdx.y * 64;
    int w = tid >> 5, lane = tid & 31;
    int wm = (w & 3) * 32, wn = (w >> 2) * 32;
    int g = lane >> 2, t = lane & 3;

    float acc[2][4][4] = {};

    for (int kt = 0; kt < K; kt += 16) {
        // ---- load A tile 128x16 (2 float4 per thread) ----
#pragma unroll
        for (int i = 0; i < 2; i++) {
            int idx = tid + i * 256;
            int r = idx >> 2, c4 = (idx & 3) << 2;
            float4 v = make_float4(0.f, 0.f, 0.f, 0.f);
            int gr = bm0 + r;
            if (gr < M) v = *(const float4*)(A + (size_t)gr * K + kt + c4);
            u32 hx = f2tf32(v.x), hy = f2tf32(v.y), hz = f2tf32(v.z), hw = f2tf32(v.w);
            As_hi[r][c4 + 0] = hx; As_hi[r][c4 + 1] = hy;
            As_hi[r][c4 + 2] = hz; As_hi[r][c4 + 3] = hw;
            As_lo[r][c4 + 0] = f2tf32(v.x - __uint_as_float(hx));
            As_lo[r][c4 + 1] = f2tf32(v.y - __uint_as_float(hy));
            As_lo[r][c4 + 2] = f2tf32(v.z - __uint_as_float(hz));
            As_lo[r][c4 + 3] = f2tf32(v.w - __uint_as_float(hw));
        }
        // ---- load B tile 16x64 (1 float4 per thread) ----
        {
            int r = tid >> 4, c4 = (tid & 15) << 2;
            float4 v = *(const float4*)(B + (size_t)(kt + r) * N + bn0 + c4);
            u32 hx = f2tf32(v.x), hy = f2tf32(v.y), hz = f2tf32(v.z), hw = f2tf32(v.w);
            Bs_hi[r][c4 + 0] = hx; Bs_hi[r][c4 + 1] = hy;
            Bs_hi[r][c4 + 2] = hz; Bs_hi[r][c4 + 3] = hw;
            Bs_lo[r][c4 + 0] = f2tf32(v.x - __uint_as_float(hx));
            Bs_lo[r][c4 + 1] = f2tf32(v.y - __uint_as_float(hy));
            Bs_lo[r][c4 + 2] = f2tf32(v.z - __uint_as_float(hz));
            Bs_lo[r][c4 + 3] = f2tf32(v.w - __uint_as_float(hw));
        }
        __syncthreads();

#pragma unroll
        for (int kk = 0; kk < 2; kk++) {
            int k0 = kk * 8;
            u32 ah[2][4], al[2][4], bh[4][2], bl[4][2];
#pragma unroll
            for (int mt = 0; mt < 2; mt++) {
                int r = wm + mt * 16 + g;
                ah[mt][0] = As_hi[r][k0 + t];     ah[mt][1] = As_hi[r + 8][k0 + t];
                ah[mt][2] = As_hi[r][k0 + t + 4]; ah[mt][3] = As_hi[r + 8][k0 + t + 4];
                al[mt][0] = As_lo[r][k0 + t];     al[mt][1] = As_lo[r + 8][k0 + t];
                al[mt][2] = As_lo[r][k0 + t + 4]; al[mt][3] = As_lo[r + 8][k0 + t + 4];
            }
#pragma unroll
            for (int nt = 0; nt < 4; nt++) {
                int c = wn + nt * 8 + g;
                bh[nt][0] = Bs_hi[k0 + t][c]; bh[nt][1] = Bs_hi[k0 + t + 4][c];
                bl[nt][0] = Bs_lo[k0 + t][c]; bl[nt][1] = Bs_lo[k0 + t + 4][c];
            }
#pragma unroll
            for (int mt = 0; mt < 2; mt++)
#pragma unroll
                for (int nt = 0; nt < 4; nt++) {
                    mma_tf32(acc[mt][nt], ah[mt], bh[nt]);
                    mma_tf32(acc[mt][nt], ah[mt], bl[nt]);
                    mma_tf32(acc[mt][nt], al[mt], bh[nt]);
                }
        }
        __syncthreads();
    }

    // ---- store ----
#pragma unroll
    for (int mt = 0; mt < 2; mt++) {
        int r0 = bm0 + wm + mt * 16 + g;
#pragma unroll
        for (int nt = 0; nt < 4; nt++) {
            int c = bn0 + wn + nt * 8 + 2 * t;
            if (r0 < M)
                *(float2*)(C + (size_t)r0 * N + c) = make_float2(acc[mt][nt][0], acc[mt][nt][1]);
            if (r0 + 8 < M)
                *(float2*)(C + (size_t)(r0 + 8) * N + c) = make_float2(acc[mt][nt][2], acc[mt][nt][3]);
        }
    }
}

// ---------------- GAT attention scores ---------------------------------------
template <int HEADS, int CH>
__global__ void k_scores(const float* __restrict__ h, const float* __restrict__ a_src,
                         const float* __restrict__ a_dst, float* __restrict__ scs,
                         float* __restrict__ scd, int n) {
    int node = blockIdx.x * 8 + (threadIdx.x >> 5);
    int lane = threadIdx.x & 31;
    if (node >= n) return;
    const int D = HEADS * CH;
#pragma unroll
    for (int hd = 0; hd < HEADS; hd++) {
        float ps = 0.f, pd = 0.f;
#pragma unroll
        for (int jj = 0; jj < CH / 32; jj++) {
            int cc = lane + 32 * jj;
            float hv = h[(size_t)node * D + hd * CH + cc];
            ps += hv * a_src[hd * CH + cc];
            pd += hv * a_dst[hd * CH + cc];
        }
#pragma unroll
        for (int off = 16; off; off >>= 1) {
            ps += __shfl_xor_sync(0xffffffffu, ps, off);
            pd += __shfl_xor_sync(0xffffffffu, pd, off);
        }
        if (lane == 0) { scs[node * HEADS + hd] = ps; scd[node * HEADS + hd] = pd; }
    }
}

// ---------------- GAT aggregation (softmax over incoming edges + scatter) ----
template <int HEADS, int CH>
__global__ void k_gat_agg(const float* __restrict__ h, const float* __restrict__ scs,
                          const float* __restrict__ scd_arr,
                          const float* __restrict__ bias,
                          const float* __restrict__ bn_g, const float* __restrict__ bn_b,
                          const int* __restrict__ rowstart, const int* __restrict__ col,
                          float* __restrict__ xout, int n) {
    const int D = HEADS * CH, PER = D / 32;
    int node = blockIdx.x * 8 + (threadIdx.x >> 5);
    int lane = threadIdx.x & 31;
    if (node >= n) return;
    int rs = rowstart[node], re = rowstart[node + 1];

    float scd[HEADS];
#pragma unroll
    for (int hd = 0; hd < HEADS; hd++) scd[hd] = scd_arr[node * HEADS + hd];

    // pass 1: per-head max over edges
    float m[HEADS];
#pragma unroll
    for (int hd = 0; hd < HEADS; hd++) m[hd] = -1e30f;
    for (int k = rs + lane; k < re; k += 32) {
        int s = col[k];
#pragma unroll
        for (int hd = 0; hd < HEADS; hd++) {
            float e = scs[s * HEADS + hd] + scd[hd];
            e = lrelu(e, 0.2f);
            m[hd] = fmaxf(m[hd], e);
        }
    }
#pragma unroll
    for (int hd = 0; hd < HEADS; hd++)
#pragma unroll
        for (int off = 16; off; off >>= 1)
            m[hd] = fmaxf(m[hd], __shfl_xor_sync(0xffffffffu, m[hd], off));

    // pass 2: exp-sum
    float ssum[HEADS] = {};
    for (int k = rs + lane; k < re; k += 32) {
        int s = col[k];
#pragma unroll
        for (int hd = 0; hd < HEADS; hd++) {
            float e = scs[s * HEADS + hd] + scd[hd];
            e = lrelu(e, 0.2f);
            ssum[hd] += __expf(e - m[hd]);
        }
    }
#pragma unroll
    for (int hd = 0; hd < HEADS; hd++) {
#pragma unroll
        for (int off = 16; off; off >>= 1)
            ssum[hd] += __shfl_xor_sync(0xffffffffu, ssum[hd], off);
        ssum[hd] = 1.f / (ssum[hd] + 1e-16f);
    }

    // pass 3: weighted aggregate (whole warp walks edges; coalesced row gather)
    float acc[PER] = {};
    for (int k = rs; k < re; k++) {
        int s = col[k];
        float al[HEADS];
#pragma unroll
        for (int hd = 0; hd < HEADS; hd++) {
            float e = scs[s * HEADS + hd] + scd[hd];
            e = lrelu(e, 0.2f);
            al[hd] = __expf(e - m[hd]) * ssum[hd];
        }
        const float* hp = h + (size_t)s * D;
#pragma unroll
        for (int j = 0; j < PER; j++) acc[j] += hp[lane + 32 * j] * al[(32 * j) / CH];
    }

    // epilogue: + bias, LeakyReLU(0.01), BatchNorm(eval)
    const float inv_bn = rsqrtf(1.0f + 1e-5f);
#pragma unroll
    for (int j = 0; j < PER; j++) {
        int c = lane + 32 * j;
        float tt = acc[j] + bias[c];
        tt = lrelu(tt, 0.01f);
        xout[(size_t)node * D + c] = tt * (bn_g[c] * inv_bn) + bn_b[c];
    }
}

// ---------------- GCN --------------------------------------------------------
__global__ void k_dis(const int* __restrict__ rowstart, float* __restrict__ dis, int n) {
    int i = blockIdx.x * blockDim.x + threadIdx.x;
    if (i < n) {
        int d = rowstart[i + 1] - rowstart[i];
        dis[i] = (d > 0) ? rsqrtf((float)d) : 0.f;
    }
}

__global__ void k_gcn_agg(const float* __restrict__ h, const float* __restrict__ dis,
                          const float* __restrict__ bg,
                          const int* __restrict__ rowstart, const int* __restrict__ col,
                          float* __restrict__ xout, int n) {
    int node = blockIdx.x * 8 + (threadIdx.x >> 5);
    int lane = threadIdx.x & 31;
    if (node >= n) return;
    int rs = rowstart[node], re = rowstart[node + 1];
    float wi = dis[node];
    float acc0 = 0.f, acc1 = 0.f;
    for (int k = rs; k < re; k++) {
        int s = col[k];
        float w = dis[s] * wi;
        const float* hp = h + (size_t)s * D3;
        acc0 += hp[lane] * w;
        acc1 += hp[lane + 32] * w;
    }
    float t0 = lrelu(acc0 + bg[lane], 0.01f);
    float t1 = lrelu(acc1 + bg[lane + 32], 0.01f);
    xout[(size_t)node * D3 + lane] = t0;
    xout[(size_t)node * D3 + lane + 32] = t1;
}

// ---------------- pooling + MLP ----------------------------------------------
__global__ void k_zero2(float* p, int n, float* q, int m) {
    int i = blockIdx.x * blockDim.x + threadIdx.x;
    if (i < n) p[i] = 0.f;
    if (i < m) q[i] = 0.f;
}

__global__ void k_pool(const float* __restrict__ x3, const int* __restrict__ batch,
                       float* pool, float* cnt, int n) {
    int node = blockIdx.x * 8 + (threadIdx.x >> 5);
    int lane = threadIdx.x & 31;
    if (node >= n) return;
    int b = batch[node];
    atomicAdd(&pool[b * D3 + lane], x3[(size_t)node * D3 + lane]);
    atomicAdd(&pool[b * D3 + lane + 32], x3[(size_t)node * D3 + lane + 32]);
    if (lane == 0) atomicAdd(&cnt[b], 1.f);
}

__global__ void __launch_bounds__(128) k_mlp(const float* __restrict__ pool,
                                             const float* __restrict__ cnt,
                                             const float* __restrict__ l1W,
                                             const float* __restrict__ l1b,
                                             const float* __restrict__ g3,
                                             const float* __restrict__ b3,
                                             const float* __restrict__ l2W,
                                             const float* __restrict__ l2b,
                                             float* __restrict__ out) {
    int b = blockIdx.x;
    int t = threadIdx.x;
    __shared__ float sp[64];
    __shared__ float sy[128];
    if (t < 64) sp[t] = pool[b * D3 + t] / fmaxf(cnt[b], 1.f);
    __syncthreads();
    float v = l1b[t];
#pragma unroll
    for (int k = 0; k < 64; k++) v += sp[k] * l1W[k * 128 + t];
    v = v * (g3[t] * rsqrtf(1.0f + 1e-5f)) + b3[t];
    v = lrelu(v, 0.01f);
    sy[t] = v;
    __syncthreads();
    if (t < NCc) {
        float o = l2b[t];
#pragma unroll
        for (int k = 0; k < 128; k++) o += sy[k] * l2W[k * NCc + t];
        out[b * NCc + t] = o;
    }
}

// ---------------- launch -----------------------------------------------------
extern "C" void kernel_launch(void* const* d_in, const int* in_sizes, int n_in,
                              void* d_out, int out_size) {
    const float* x      = (const float*)d_in[0];
    const int*   ei     = (const int*)d_in[1];
    const int*   batch  = (const int*)d_in[2];
    const float* W1     = (const float*)d_in[3];
    const float* a_src1 = (const float*)d_in[4];
    const float* a_dst1 = (const float*)d_in[5];
    const float* b1     = (const float*)d_in[6];
    const float* W2     = (const float*)d_in[7];
    const float* a_src2 = (const float*)d_in[8];
    const float* a_dst2 = (const float*)d_in[9];
    const float* b2     = (const float*)d_in[10];
    const float* Wg     = (const float*)d_in[11];
    const float* bg     = (const float*)d_in[12];
    const float* bn1g   = (const float*)d_in[13];
    const float* bn1b   = (const float*)d_in[14];
    const float* bn2g   = (const float*)d_in[15];
    const float* bn2b   = (const float*)d_in[16];
    const float* bn3g   = (const float*)d_in[17];
    const float* bn3b   = (const float*)d_in[18];
    const float* l1W    = (const float*)d_in[19];
    const float* l1b    = (const float*)d_in[20];
    const float* l2W    = (const float*)d_in[21];
    const float* l2b    = (const float*)d_in[22];
    float* out = (float*)d_out;

    int *deg, *rowstart, *cursor, *col, *partials;
    float *h1, *x1, *h2, *x2, *h3, *x3, *scs1, *scd1, *scs2, *scd2, *dis, *pool, *cnt;
    cudaGetSymbolAddress((void**)&deg, g_deg);
    cudaGetSymbolAddress((void**)&rowstart, g_rowstart);
    cudaGetSymbolAddress((void**)&cursor, g_cursor);
    cudaGetSymbolAddress((void**)&col, g_col);
    cudaGetSymbolAddress((void**)&partials, g_partials);
    cudaGetSymbolAddress((void**)&h1, g_h1);
    cudaGetSymbolAddress((void**)&x1, g_x1);
    cudaGetSymbolAddress((void**)&h2, g_h2);
    cudaGetSymbolAddress((void**)&x2, g_x2);
    cudaGetSymbolAddress((void**)&h3, g_h3);
    cudaGetSymbolAddress((void**)&x3, g_x3);
    cudaGetSymbolAddress((void**)&scs1, g_scs1);
    cudaGetSymbolAddress((void**)&scd1, g_scd1);
    cudaGetSymbolAddress((void**)&scs2, g_scs2);
    cudaGetSymbolAddress((void**)&scd2, g_scd2);
    cudaGetSymbolAddress((void**)&dis, g_dis);
    cudaGetSymbolAddress((void**)&pool, g_pool);
    cudaGetSymbolAddress((void**)&cnt, g_cnt);

    const int* src = ei;
    const int* dst = ei + Ee;

    // ---- CSR build (dst-indexed, self-loop first per row) ----
    k_init_deg<<<(Nn + 255) / 256, 256>>>(deg, Nn);
    k_deg_scatter<<<(Ee + 255) / 256, 256>>>(dst, deg, Ee);
    k_scan_block<<<NB_SCAN, 1024>>>(deg, rowstart, partials, Nn);
    k_scan_partials<<<1, 64>>>(partials, rowstart, NB_SCAN, Nn);
    k_scan_finalize<<<NB_SCAN, 1024>>>(deg, rowstart, partials, Nn);
    k_fill_self<<<(Nn + 255) / 256, 256>>>(rowstart, col, cursor, Nn);
    k_scatter_edges<<<(Ee + 255) / 256, 256>>>(src, dst, cursor, col, Ee);

    // ---- GAT layer 1: F(128) -> 4 heads x 64 ----
    k_gemm_tc<<<dim3((Nn + 127) / 128, D1 / 64), 256>>>(x, W1, h1, Nn, D1, Fdim);
    k_scores<4, 64><<<(Nn + 7) / 8, 256>>>(h1, a_src1, a_dst1, scs1, scd1, Nn);
    k_gat_agg<4, 64><<<(Nn + 7) / 8, 256>>>(h1, scs1, scd1, b1, bn1g, bn1b,
                                            rowstart, col, x1, Nn);

    // ---- GAT layer 2: 256 -> 1 head x 128 ----
    k_gemm_tc<<<dim3((Nn + 127) / 128, D2 / 64), 256>>>(x1, W2, h2, Nn, D2, D1);
    k_scores<1, 128><<<(Nn + 7) / 8, 256>>>(h2, a_src2, a_dst2, scs2, scd2, Nn);
    k_gat_agg<1, 128><<<(Nn + 7) / 8, 256>>>(h2, scs2, scd2, b2, bn2g, bn2b,
                                             rowstart, col, x2, Nn);

    // ---- GCN: 128 -> 64 ----
    k_gemm_tc<<<dim3((Nn + 127) / 128, D3 / 64), 256>>>(x2, Wg, h3, Nn, D3, D2);
    k_dis<<<(Nn + 255) / 256, 256>>>(rowstart, dis, Nn);
    k_gcn_agg<<<(Nn + 7) / 8, 256>>>(h3, dis, bg, rowstart, col, x3, Nn);

    // ---- global mean pool + MLP head ----
    k_zero2<<<(Bb * D3 + 255) / 256, 256>>>(pool, Bb * D3, cnt, Bb);
    k_pool<<<(Nn + 7) / 8, 256>>>(x3, batch, pool, cnt, Nn);
    k_mlp<<<Bb, 128>>>(pool, cnt, l1W, l1b, bn3g, bn3b, l2W, l2b, out);
}

// round 4
// speedup vs baseline: 1.2623x; 1.1106x over previous
#include <cuda_runtime.h>
#include <cuda_bf16.h>
#include <math_constants.h>
#include <cstdint>

// Problem constants (fixed by reference setup_inputs)
#define Nn   50000
#define Ee   800000
#define E2   (Ee + Nn)
#define Fdim 128
#define D1   256   // 4 heads x 64
#define D2   128   // 1 head x 128
#define D3   64    // GCN out
#define Bb   512
#define NCc  10
#define NB_SCAN ((Nn + 1023) / 1024)

typedef unsigned int u32;

// ---------------- scratch (device globals; no allocation allowed) -----------
__device__ __align__(16) int   g_deg[Nn];
__device__ __align__(16) int   g_rowstart[Nn + 1];
__device__ __align__(16) int   g_cursor[Nn];
__device__ __align__(16) int   g_col[E2];
__device__ __align__(16) int   g_partials[NB_SCAN + 1];

__device__ __align__(16) float g_h1[(size_t)Nn * D1];
__device__ __align__(16) float g_x1[(size_t)Nn * D1];
__device__ __align__(16) float g_h2[(size_t)Nn * D2];
__device__ __align__(16) float g_x2[(size_t)Nn * D2];
__device__ __align__(16) float g_h3[(size_t)Nn * D3];
__device__ __align__(16) float g_x3[(size_t)Nn * D3];
__device__ __align__(16) float g_scs1[Nn * 4];
__device__ __align__(16) float g_scd1[Nn * 4];
__device__ __align__(16) float g_scs2[Nn];
__device__ __align__(16) float g_scd2[Nn];
__device__ __align__(16) float g_dis[Nn];
__device__ __align__(16) float g_pool[Bb * D3];
__device__ __align__(16) float g_cnt[Bb];

// ---------------- small helpers ---------------------------------------------
__device__ __forceinline__ float lrelu(float v, float s) { return v > 0.f ? v : s * v; }

__device__ __forceinline__ u32 f2tf32(float x) {
    u32 r;
    asm("cvt.rna.tf32.f32 %0, %1;" : "=r"(r) : "f"(x));
    return r;
}

__device__ __forceinline__ void mma_tf32(float* c, const u32* a, const u32* b) {
    asm volatile(
        "mma.sync.aligned.m16n8k8.row.col.f32.tf32.tf32.f32 "
        "{%0,%1,%2,%3}, {%4,%5,%6,%7}, {%8,%9}, {%0,%1,%2,%3};"
        : "+f"(c[0]), "+f"(c[1]), "+f"(c[2]), "+f"(c[3])
        : "r"(a[0]), "r"(a[1]), "r"(a[2]), "r"(a[3]), "r"(b[0]), "r"(b[1]));
}

// ---------------- CSR build --------------------------------------------------
__global__ void k_init_deg(int* deg, int n) {
    int i = blockIdx.x * blockDim.x + threadIdx.x;
    if (i < n) deg[i] = 1;  // self-loop
}

__global__ void k_deg_scatter(const int* __restrict__ dst, int* deg, int e) {
    int i = blockIdx.x * blockDim.x + threadIdx.x;
    if (i < e) atomicAdd(&deg[dst[i]], 1);
}

__global__ void k_scan_block(const int* __restrict__ deg, int* __restrict__ rowstart,
                             int* __restrict__ partials, int n) {
    __shared__ int s[1024];
    int t = threadIdx.x;
    int gi = blockIdx.x * 1024 + t;
    int v = (gi < n) ? deg[gi] : 0;
    s[t] = v;
    __syncthreads();
#pragma unroll
    for (int off = 1; off < 1024; off <<= 1) {
        int xv = (t >= off) ? s[t - off] : 0;
        __syncthreads();
        s[t] += xv;
        __syncthreads();
    }
    if (gi < n) rowstart[gi] = s[t];          // block-inclusive
    if (t == 1023) partials[blockIdx.x] = s[t];
}

// parallel exclusive scan of <=64 partials (one block, 64 threads)
__global__ void k_scan_partials(int* partials, int* rowstart, int nb, int n) {
    __shared__ int wsum[2];
    int t = threadIdx.x;
    int lane = t & 31, w = t >> 5;
    int orig = (t < nb) ? partials[t] : 0;
    int v = orig;
#pragma unroll
    for (int o = 1; o < 32; o <<= 1) {
        int xv = __shfl_up_sync(0xffffffffu, v, o);
        if (lane >= o) v += xv;
    }
    if (lane == 31) wsum[w] = v;
    __syncthreads();
    if (w == 1) v += wsum[0];
    if (t < nb) partials[t] = v - orig;   // exclusive
    if (t == 63) rowstart[n] = v;         // total (= N + E)
}

__global__ void k_scan_finalize(const int* __restrict__ deg, int* __restrict__ rowstart,
                                const int* __restrict__ partials, int n) {
    int gi = blockIdx.x * 1024 + threadIdx.x;
    if (gi < n) rowstart[gi] = rowstart[gi] - deg[gi] + partials[blockIdx.x];
}

// self-loop first per row; also compute GCN 1/sqrt(deg) here
__global__ void k_fill_self(const int* __restrict__ rowstart, int* __restrict__ col,
                            int* __restrict__ cursor, const int* __restrict__ deg,
                            float* __restrict__ dis, int n) {
    int i = blockIdx.x * blockDim.x + threadIdx.x;
    if (i < n) {
        int rs = rowstart[i];
        col[rs] = i;
        cursor[i] = rs + 1;
        dis[i] = rsqrtf((float)deg[i]);
    }
}

__global__ void k_scatter_edges(const int* __restrict__ src, const int* __restrict__ dst,
                                int* cursor, int* __restrict__ col, int e) {
    int i = blockIdx.x * blockDim.x + threadIdx.x;
    if (i < e) {
        int pos = atomicAdd(&cursor[dst[i]], 1);
        col[pos] = src[i];
    }
}

// ---------------- 3xTF32 tensor-core GEMM ------------------------------------
// C[M,N] = A[M,K] @ B[K,N].  BM=128, BN=64, BK=16, 256 threads (8 warps, 4x2),
// warp tile 32x32 (2 m-frags x 4 n-frags of m16n8k8). N mult of 64, K mult of 16.
__global__ void __launch_bounds__(256) k_gemm_tc(const float* __restrict__ A,
                                                 const float* __restrict__ B,
                                                 float* __restrict__ C,
                                                 int M, int N, int K) {
    __shared__ u32 As_hi[128][20], As_lo[128][20];
    __shared__ u32 Bs_hi[16][72], Bs_lo[16][72];

    int tid = threadIdx.x;
    int bm0 = blockIdx.x * 128, bn0 = blockIdx.y * 64;
    int w = tid >> 5, lane = tid & 31;
    int wm = (w & 3) * 32, wn = (w >> 2) * 32;
    int g = lane >> 2, t = lane & 3;

    float acc[2][4][4] = {};

    for (int kt = 0; kt < K; kt += 16) {
#pragma unroll
        for (int i = 0; i < 2; i++) {
            int idx = tid + i * 256;
            int r = idx >> 2, c4 = (idx & 3) << 2;
            float4 v = make_float4(0.f, 0.f, 0.f, 0.f);
            int gr = bm0 + r;
            if (gr < M) v = *(const float4*)(A + (size_t)gr * K + kt + c4);
            u32 hx = f2tf32(v.x), hy = f2tf32(v.y), hz = f2tf32(v.z), hw = f2tf32(v.w);
            As_hi[r][c4 + 0] = hx; As_hi[r][c4 + 1] = hy;
            As_hi[r][c4 + 2] = hz; As_hi[r][c4 + 3] = hw;
            As_lo[r][c4 + 0] = f2tf32(v.x - __uint_as_float(hx));
            As_lo[r][c4 + 1] = f2tf32(v.y - __uint_as_float(hy));
            As_lo[r][c4 + 2] = f2tf32(v.z - __uint_as_float(hz));
            As_lo[r][c4 + 3] = f2tf32(v.w - __uint_as_float(hw));
        }
        {
            int r = tid >> 4, c4 = (tid & 15) << 2;
            float4 v = *(const float4*)(B + (size_t)(kt + r) * N + bn0 + c4);
            u32 hx = f2tf32(v.x), hy = f2tf32(v.y), hz = f2tf32(v.z), hw = f2tf32(v.w);
            Bs_hi[r][c4 + 0] = hx; Bs_hi[r][c4 + 1] = hy;
            Bs_hi[r][c4 + 2] = hz; Bs_hi[r][c4 + 3] = hw;
            Bs_lo[r][c4 + 0] = f2tf32(v.x - __uint_as_float(hx));
            Bs_lo[r][c4 + 1] = f2tf32(v.y - __uint_as_float(hy));
            Bs_lo[r][c4 + 2] = f2tf32(v.z - __uint_as_float(hz));
            Bs_lo[r][c4 + 3] = f2tf32(v.w - __uint_as_float(hw));
        }
        __syncthreads();

#pragma unroll
        for (int kk = 0; kk < 2; kk++) {
            int k0 = kk * 8;
            u32 ah[2][4], al[2][4], bh[4][2], bl[4][2];
#pragma unroll
            for (int mt = 0; mt < 2; mt++) {
                int r = wm + mt * 16 + g;
                ah[mt][0] = As_hi[r][k0 + t];     ah[mt][1] = As_hi[r + 8][k0 + t];
                ah[mt][2] = As_hi[r][k0 + t + 4]; ah[mt][3] = As_hi[r + 8][k0 + t + 4];
                al[mt][0] = As_lo[r][k0 + t];     al[mt][1] = As_lo[r + 8][k0 + t];
                al[mt][2] = As_lo[r][k0 + t + 4]; al[mt][3] = As_lo[r + 8][k0 + t + 4];
            }
#pragma unroll
            for (int nt = 0; nt < 4; nt++) {
                int c = wn + nt * 8 + g;
                bh[nt][0] = Bs_hi[k0 + t][c]; bh[nt][1] = Bs_hi[k0 + t + 4][c];
                bl[nt][0] = Bs_lo[k0 + t][c]; bl[nt][1] = Bs_lo[k0 + t + 4][c];
            }
#pragma unroll
            for (int mt = 0; mt < 2; mt++)
#pragma unroll
                for (int nt = 0; nt < 4; nt++) {
                    mma_tf32(acc[mt][nt], ah[mt], bh[nt]);
                    mma_tf32(acc[mt][nt], ah[mt], bl[nt]);
                    mma_tf32(acc[mt][nt], al[mt], bh[nt]);
                }
        }
        __syncthreads();
    }

#pragma unroll
    for (int mt = 0; mt < 2; mt++) {
        int r0 = bm0 + wm + mt * 16 + g;
#pragma unroll
        for (int nt = 0; nt < 4; nt++) {
            int c = bn0 + wn + nt * 8 + 2 * t;
            if (r0 < M)
                *(float2*)(C + (size_t)r0 * N + c) = make_float2(acc[mt][nt][0], acc[mt][nt][1]);
            if (r0 + 8 < M)
                *(float2*)(C + (size_t)(r0 + 8) * N + c) = make_float2(acc[mt][nt][2], acc[mt][nt][3]);
        }
    }
}

// ---------------- GAT attention scores ---------------------------------------
template <int HEADS, int CH>
__global__ void k_scores(const float* __restrict__ h, const float* __restrict__ a_src,
                         const float* __restrict__ a_dst, float* __restrict__ scs,
                         float* __restrict__ scd, int n) {
    int node = blockIdx.x * 8 + (threadIdx.x >> 5);
    int lane = threadIdx.x & 31;
    if (node >= n) return;
    const int D = HEADS * CH;
#pragma unroll
    for (int hd = 0; hd < HEADS; hd++) {
        float ps = 0.f, pd = 0.f;
#pragma unroll
        for (int jj = 0; jj < CH / 32; jj++) {
            int cc = lane + 32 * jj;
            float hv = h[(size_t)node * D + hd * CH + cc];
            ps += hv * a_src[hd * CH + cc];
            pd += hv * a_dst[hd * CH + cc];
        }
#pragma unroll
        for (int off = 16; off; off >>= 1) {
            ps += __shfl_xor_sync(0xffffffffu, ps, off);
            pd += __shfl_xor_sync(0xffffffffu, pd, off);
        }
        if (lane == 0) { scs[node * HEADS + hd] = ps; scd[node * HEADS + hd] = pd; }
    }
}

// ---------------- GAT aggregation: single pass (no max shift) ----------------
// alpha = exp(e)/sum(exp(e)); accumulate w and w*h in one sweep over edges.
// 4 heads x 64ch: each lane owns two float4 chunks: c=4*lane (head lane/16)
// and c=128+4*lane (head 2+lane/16).
__global__ void k_gat_agg4(const float* __restrict__ h, const float* __restrict__ scs,
                           const float* __restrict__ scd_arr,
                           const float* __restrict__ bias,
                           const float* __restrict__ bn_g, const float* __restrict__ bn_b,
                           const int* __restrict__ rowstart, const int* __restrict__ col,
                           float* __restrict__ xout, int n) {
    int node = blockIdx.x * 8 + (threadIdx.x >> 5);
    int lane = threadIdx.x & 31;
    if (node >= n) return;
    int rs = rowstart[node], re = rowstart[node + 1];

    float4 scd4 = *(const float4*)(scd_arr + node * 4);
    bool lo = lane < 16;
    float scdA = lo ? scd4.x : scd4.y;
    float scdB = lo ? scd4.z : scd4.w;

    const float4* h4 = (const float4*)h;
    const float4* scs4 = (const float4*)scs;

    float4 accA = make_float4(0.f, 0.f, 0.f, 0.f);
    float4 accB = make_float4(0.f, 0.f, 0.f, 0.f);
    float wsA = 0.f, wsB = 0.f;

    for (int base = rs; base < re; base += 32) {
        int idx = base + lane;
        int ck = col[idx < re ? idx : re - 1];
        int cnt = min(32, re - base);
        for (int j = 0; j < cnt; j++) {
            int s = __shfl_sync(0xffffffffu, ck, j);
            float4 sv = scs4[s];
            float eA = lrelu((lo ? sv.x : sv.y) + scdA, 0.2f);
            float eB = lrelu((lo ? sv.z : sv.w) + scdB, 0.2f);
            float wa = __expf(eA), wb = __expf(eB);
            const float4* hp = h4 + (size_t)s * 64;
            float4 va = hp[lane];
            float4 vb = hp[lane + 32];
            accA.x += va.x * wa; accA.y += va.y * wa;
            accA.z += va.z * wa; accA.w += va.w * wa;
            accB.x += vb.x * wb; accB.y += vb.y * wb;
            accB.z += vb.z * wb; accB.w += vb.w * wb;
            wsA += wa; wsB += wb;
        }
    }

    float ia = 1.f / wsA, ib = 1.f / wsB;
    const float inv_bn = rsqrtf(1.0f + 1e-5f);
    float4 bA = ((const float4*)bias)[lane],  bB = ((const float4*)bias)[lane + 32];
    float4 gA = ((const float4*)bn_g)[lane],  gB = ((const float4*)bn_g)[lane + 32];
    float4 cA = ((const float4*)bn_b)[lane],  cB = ((const float4*)bn_b)[lane + 32];
    float4 oA, oB;
    oA.x = lrelu(accA.x * ia + bA.x, 0.01f) * (gA.x * inv_bn) + cA.x;
    oA.y = lrelu(accA.y * ia + bA.y, 0.01f) * (gA.y * inv_bn) + cA.y;
    oA.z = lrelu(accA.z * ia + bA.z, 0.01f) * (gA.z * inv_bn) + cA.z;
    oA.w = lrelu(accA.w * ia + bA.w, 0.01f) * (gA.w * inv_bn) + cA.w;
    oB.x = lrelu(accB.x * ib + bB.x, 0.01f) * (gB.x * inv_bn) + cB.x;
    oB.y = lrelu(accB.y * ib + bB.y, 0.01f) * (gB.y * inv_bn) + cB.y;
    oB.z = lrelu(accB.z * ib + bB.z, 0.01f) * (gB.z * inv_bn) + cB.z;
    oB.w = lrelu(accB.w * ib + bB.w, 0.01f) * (gB.w * inv_bn) + cB.w;
    ((float4*)xout)[(size_t)node * 64 + lane]      = oA;
    ((float4*)xout)[(size_t)node * 64 + lane + 32] = oB;
}

// 1 head x 128ch
__global__ void k_gat_agg1(const float* __restrict__ h, const float* __restrict__ scs,
                           const float* __restrict__ scd_arr,
                           const float* __restrict__ bias,
                           const float* __restrict__ bn_g, const float* __restrict__ bn_b,
                           const int* __restrict__ rowstart, const int* __restrict__ col,
                           float* __restrict__ xout, int n) {
    int node = blockIdx.x * 8 + (threadIdx.x >> 5);
    int lane = threadIdx.x & 31;
    if (node >= n) return;
    int rs = rowstart[node], re = rowstart[node + 1];

    float scd0 = scd_arr[node];
    const float4* h4 = (const float4*)h;

    float4 acc = make_float4(0.f, 0.f, 0.f, 0.f);
    float ws = 0.f;

    for (int base = rs; base < re; base += 32) {
        int idx = base + lane;
        int ck = col[idx < re ? idx : re - 1];
        int cnt = min(32, re - base);
        for (int j = 0; j < cnt; j++) {
            int s = __shfl_sync(0xffffffffu, ck, j);
            float e = lrelu(scs[s] + scd0, 0.2f);
            float wv = __expf(e);
            float4 v = h4[(size_t)s * 32 + lane];
            acc.x += v.x * wv; acc.y += v.y * wv;
            acc.z += v.z * wv; acc.w += v.w * wv;
            ws += wv;
        }
    }

    float inv = 1.f / ws;
    const float inv_bn = rsqrtf(1.0f + 1e-5f);
    float4 bA = ((const float4*)bias)[lane];
    float4 gA = ((const float4*)bn_g)[lane];
    float4 cA = ((const float4*)bn_b)[lane];
    float4 o;
    o.x = lrelu(acc.x * inv + bA.x, 0.01f) * (gA.x * inv_bn) + cA.x;
    o.y = lrelu(acc.y * inv + bA.y, 0.01f) * (gA.y * inv_bn) + cA.y;
    o.z = lrelu(acc.z * inv + bA.z, 0.01f) * (gA.z * inv_bn) + cA.z;
    o.w = lrelu(acc.w * inv + bA.w, 0.01f) * (gA.w * inv_bn) + cA.w;
    ((float4*)xout)[(size_t)node * 32 + lane] = o;
}

// ---------------- GCN --------------------------------------------------------
__global__ void k_gcn_agg(const float* __restrict__ h, const float* __restrict__ dis,
                          const float* __restrict__ bg,
                          const int* __restrict__ rowstart, const int* __restrict__ col,
                          float* __restrict__ xout, int n) {
    int node = blockIdx.x * 8 + (threadIdx.x >> 5);
    int lane = threadIdx.x & 31;
    if (node >= n) return;
    int rs = rowstart[node], re = rowstart[node + 1];
    float wi = dis[node];
    const float2* h2 = (const float2*)h;
    float2 acc = make_float2(0.f, 0.f);
    for (int base = rs; base < re; base += 32) {
        int idx = base + lane;
        int ck = col[idx < re ? idx : re - 1];
        int cnt = min(32, re - base);
        for (int j = 0; j < cnt; j++) {
            int s = __shfl_sync(0xffffffffu, ck, j);
            float w = dis[s] * wi;
            float2 v = h2[(size_t)s * 32 + lane];
            acc.x += v.x * w; acc.y += v.y * w;
        }
    }
    float2 bgv = ((const float2*)bg)[lane];
    float2 o;
    o.x = lrelu(acc.x + bgv.x, 0.01f);
    o.y = lrelu(acc.y + bgv.y, 0.01f);
    ((float2*)xout)[(size_t)node * 32 + lane] = o;
}

// ---------------- pooling + MLP ----------------------------------------------
__global__ void k_zero2(float* p, int n, float* q, int m) {
    int i = blockIdx.x * blockDim.x + threadIdx.x;
    if (i < n) p[i] = 0.f;
    if (i < m) q[i] = 0.f;
}

__global__ void k_pool(const float* __restrict__ x3, const int* __restrict__ batch,
                       float* pool, float* cnt, int n) {
    int node = blockIdx.x * 8 + (threadIdx.x >> 5);
    int lane = threadIdx.x & 31;
    if (node >= n) return;
    int b = batch[node];
    float2 v = ((const float2*)x3)[(size_t)node * 32 + lane];
    atomicAdd(&pool[b * D3 + 2 * lane], v.x);
    atomicAdd(&pool[b * D3 + 2 * lane + 1], v.y);
    if (lane == 0) atomicAdd(&cnt[b], 1.f);
}

__global__ void __launch_bounds__(128) k_mlp(const float* __restrict__ pool,
                                             const float* __restrict__ cnt,
                                             const float* __restrict__ l1W,
                                             const float* __restrict__ l1b,
                                             const float* __restrict__ g3,
                                             const float* __restrict__ b3,
                                             const float* __restrict__ l2W,
                                             const float* __restrict__ l2b,
                                             float* __restrict__ out) {
    int b = blockIdx.x;
    int t = threadIdx.x;
    __shared__ float sp[64];
    __shared__ float sy[128];
    if (t < 64) sp[t] = pool[b * D3 + t] / fmaxf(cnt[b], 1.f);
    __syncthreads();
    float v = l1b[t];
#pragma unroll
    for (int k = 0; k < 64; k++) v += sp[k] * l1W[k * 128 + t];
    v = v * (g3[t] * rsqrtf(1.0f + 1e-5f)) + b3[t];
    v = lrelu(v, 0.01f);
    sy[t] = v;
    __syncthreads();
    if (t < NCc) {
        float o = l2b[t];
#pragma unroll
        for (int k = 0; k < 128; k++) o += sy[k] * l2W[k * NCc + t];
        out[b * NCc + t] = o;
    }
}

// ---------------- launch -----------------------------------------------------
extern "C" void kernel_launch(void* const* d_in, const int* in_sizes, int n_in,
                              void* d_out, int out_size) {
    const float* x      = (const float*)d_in[0];
    const int*   ei     = (const int*)d_in[1];
    const int*   batch  = (const int*)d_in[2];
    const float* W1     = (const float*)d_in[3];
    const float* a_src1 = (const float*)d_in[4];
    const float* a_dst1 = (const float*)d_in[5];
    const float* b1     = (const float*)d_in[6];
    const float* W2     = (const float*)d_in[7];
    const float* a_src2 = (const float*)d_in[8];
    const float* a_dst2 = (const float*)d_in[9];
    const float* b2     = (const float*)d_in[10];
    const float* Wg     = (const float*)d_in[11];
    const float* bg     = (const float*)d_in[12];
    const float* bn1g   = (const float*)d_in[13];
    const float* bn1b   = (const float*)d_in[14];
    const float* bn2g   = (const float*)d_in[15];
    const float* bn2b   = (const float*)d_in[16];
    const float* bn3g   = (const float*)d_in[17];
    const float* bn3b   = (const float*)d_in[18];
    const float* l1W    = (const float*)d_in[19];
    const float* l1b    = (const float*)d_in[20];
    const float* l2W    = (const float*)d_in[21];
    const float* l2b    = (const float*)d_in[22];
    float* out = (float*)d_out;

    int *deg, *rowstart, *cursor, *col, *partials;
    float *h1, *x1, *h2, *x2, *h3, *x3, *scs1, *scd1, *scs2, *scd2, *dis, *pool, *cnt;
    cudaGetSymbolAddress((void**)&deg, g_deg);
    cudaGetSymbolAddress((void**)&rowstart, g_rowstart);
    cudaGetSymbolAddress((void**)&cursor, g_cursor);
    cudaGetSymbolAddress((void**)&col, g_col);
    cudaGetSymbolAddress((void**)&partials, g_partials);
    cudaGetSymbolAddress((void**)&h1, g_h1);
    cudaGetSymbolAddress((void**)&x1, g_x1);
    cudaGetSymbolAddress((void**)&h2, g_h2);
    cudaGetSymbolAddress((void**)&x2, g_x2);
    cudaGetSymbolAddress((void**)&h3, g_h3);
    cudaGetSymbolAddress((void**)&x3, g_x3);
    cudaGetSymbolAddress((void**)&scs1, g_scs1);
    cudaGetSymbolAddress((void**)&scd1, g_scd1);
    cudaGetSymbolAddress((void**)&scs2, g_scs2);
    cudaGetSymbolAddress((void**)&scd2, g_scd2);
    cudaGetSymbolAddress((void**)&dis, g_dis);
    cudaGetSymbolAddress((void**)&pool, g_pool);
    cudaGetSymbolAddress((void**)&cnt, g_cnt);

    const int* src = ei;
    const int* dst = ei + Ee;

    // one-time aux objects (created on the uncaptured correctness call)
    static cudaStream_t s2 = nullptr;
    static cudaEvent_t evFork = nullptr, evJoin = nullptr;
    if (!s2) {
        cudaStreamCreateWithFlags(&s2, cudaStreamNonBlocking);
        cudaEventCreateWithFlags(&evFork, cudaEventDisableTiming);
        cudaEventCreateWithFlags(&evJoin, cudaEventDisableTiming);
    }

    // ---- fork: CSR build on s2, GEMM1+scores on main stream ----
    cudaEventRecord(evFork, 0);
    cudaStreamWaitEvent(s2, evFork, 0);

    k_init_deg<<<(Nn + 255) / 256, 256, 0, s2>>>(deg, Nn);
    k_deg_scatter<<<(Ee + 255) / 256, 256, 0, s2>>>(dst, deg, Ee);
    k_scan_block<<<NB_SCAN, 1024, 0, s2>>>(deg, rowstart, partials, Nn);
    k_scan_partials<<<1, 64, 0, s2>>>(partials, rowstart, NB_SCAN, Nn);
    k_scan_finalize<<<NB_SCAN, 1024, 0, s2>>>(deg, rowstart, partials, Nn);
    k_fill_self<<<(Nn + 255) / 256, 256, 0, s2>>>(rowstart, col, cursor, deg, dis, Nn);
    k_scatter_edges<<<(Ee + 255) / 256, 256, 0, s2>>>(src, dst, cursor, col, Ee);
    k_zero2<<<(Bb * D3 + 255) / 256, 256, 0, s2>>>(pool, Bb * D3, cnt, Bb);
    cudaEventRecord(evJoin, s2);

    k_gemm_tc<<<dim3((Nn + 127) / 128, D1 / 64), 256>>>(x, W1, h1, Nn, D1, Fdim);
    k_scores<4, 64><<<(Nn + 7) / 8, 256>>>(h1, a_src1, a_dst1, scs1, scd1, Nn);

    cudaStreamWaitEvent(0, evJoin, 0);

    // ---- GAT layer 1 aggregation ----
    k_gat_agg4<<<(Nn + 7) / 8, 256>>>(h1, scs1, scd1, b1, bn1g, bn1b,
                                      rowstart, col, x1, Nn);

    // ---- GAT layer 2: 256 -> 1 head x 128 ----
    k_gemm_tc<<<dim3((Nn + 127) / 128, D2 / 64), 256>>>(x1, W2, h2, Nn, D2, D1);
    k_scores<1, 128><<<(Nn + 7) / 8, 256>>>(h2, a_src2, a_dst2, scs2, scd2, Nn);
    k_gat_agg1<<<(Nn + 7) / 8, 256>>>(h2, scs2, scd2, b2, bn2g, bn2b,
                                      rowstart, col, x2, Nn);

    // ---- GCN: 128 -> 64 ----
    k_gemm_tc<<<dim3((Nn + 127) / 128, D3 / 64), 256>>>(x2, Wg, h3, Nn, D3, D2);
    k_gcn_agg<<<(Nn + 7) / 8, 256>>>(h3, dis, bg, rowstart, col, x3, Nn);

    // ---- global mean pool + MLP head ----
    k_pool<<<(Nn + 7) / 8, 256>>>(x3, batch, pool, cnt, Nn);
    k_mlp<<<Bb, 128>>>(pool, cnt, l1W, l1b, bn3g, bn3b, l2W, l2b, out);
}

// round 5
// speedup vs baseline: 1.3147x; 1.0415x over previous
#include <cuda_runtime.h>
#include <cuda_fp16.h>
#include <math_constants.h>
#include <cstdint>

// Problem constants (fixed by reference setup_inputs)
#define Nn   50000
#define Ee   800000
#define E2   (Ee + Nn)
#define Fdim 128
#define D1   256   // 4 heads x 64
#define D2   128   // 1 head x 128
#define D3   64    // GCN out
#define Bb   512
#define NCc  10
#define NB_SCAN ((Nn + 1023) / 1024)

typedef unsigned int u32;

// ---------------- scratch (device globals; no allocation allowed) -----------
__device__ __align__(16) int   g_deg[Nn];
__device__ __align__(16) int   g_rowstart[Nn + 1];
__device__ __align__(16) int   g_cursor[Nn];
__device__ __align__(16) int   g_col[E2];
__device__ __align__(16) int   g_partials[NB_SCAN + 1];

__device__ __align__(16) __half g_h1[(size_t)Nn * D1];
__device__ __align__(16) float  g_x1[(size_t)Nn * D1];
__device__ __align__(16) __half g_h2[(size_t)Nn * D2];
__device__ __align__(16) float  g_x2[(size_t)Nn * D2];
__device__ __align__(16) __half g_h3[(size_t)Nn * D3];
__device__ __align__(16) float  g_x3[(size_t)Nn * D3];
__device__ __align__(16) float  g_scs1[Nn * 4];
__device__ __align__(16) float  g_scd1[Nn * 4];
__device__ __align__(16) float  g_scs2[Nn];
__device__ __align__(16) float  g_scd2[Nn];
__device__ __align__(16) float  g_dis[Nn];
__device__ __align__(16) float  g_pool[Bb * D3];
__device__ __align__(16) float  g_cnt[Bb];

// ---------------- small helpers ---------------------------------------------
__device__ __forceinline__ float lrelu(float v, float s) { return v > 0.f ? v : s * v; }

__device__ __forceinline__ u32 f2tf32(float x) {
    u32 r;
    asm("cvt.rna.tf32.f32 %0, %1;" : "=r"(r) : "f"(x));
    return r;
}

__device__ __forceinline__ void mma_tf32(float* c, const u32* a, const u32* b) {
    asm volatile(
        "mma.sync.aligned.m16n8k8.row.col.f32.tf32.tf32.f32 "
        "{%0,%1,%2,%3}, {%4,%5,%6,%7}, {%8,%9}, {%0,%1,%2,%3};"
        : "+f"(c[0]), "+f"(c[1]), "+f"(c[2]), "+f"(c[3])
        : "r"(a[0]), "r"(a[1]), "r"(a[2]), "r"(a[3]), "r"(b[0]), "r"(b[1]));
}

// ---------------- CSR build --------------------------------------------------
__global__ void k_init_deg(int* deg, int n) {
    int i = blockIdx.x * blockDim.x + threadIdx.x;
    if (i < n) deg[i] = 1;  // self-loop
}

__global__ void k_deg_scatter(const int* __restrict__ dst, int* deg, int e) {
    int i = blockIdx.x * blockDim.x + threadIdx.x;
    if (i < e) atomicAdd(&deg[dst[i]], 1);
}

__global__ void k_scan_block(const int* __restrict__ deg, int* __restrict__ rowstart,
                             int* __restrict__ partials, int n) {
    __shared__ int s[1024];
    int t = threadIdx.x;
    int gi = blockIdx.x * 1024 + t;
    int v = (gi < n) ? deg[gi] : 0;
    s[t] = v;
    __syncthreads();
#pragma unroll
    for (int off = 1; off < 1024; off <<= 1) {
        int xv = (t >= off) ? s[t - off] : 0;
        __syncthreads();
        s[t] += xv;
        __syncthreads();
    }
    if (gi < n) rowstart[gi] = s[t];          // block-inclusive
    if (t == 1023) partials[blockIdx.x] = s[t];
}

__global__ void k_scan_partials(int* partials, int* rowstart, int nb, int n) {
    __shared__ int wsum[2];
    int t = threadIdx.x;
    int lane = t & 31, w = t >> 5;
    int orig = (t < nb) ? partials[t] : 0;
    int v = orig;
#pragma unroll
    for (int o = 1; o < 32; o <<= 1) {
        int xv = __shfl_up_sync(0xffffffffu, v, o);
        if (lane >= o) v += xv;
    }
    if (lane == 31) wsum[w] = v;
    __syncthreads();
    if (w == 1) v += wsum[0];
    if (t < nb) partials[t] = v - orig;   // exclusive
    if (t == 63) rowstart[n] = v;         // total (= N + E)
}

__global__ void k_scan_finalize(const int* __restrict__ deg, int* __restrict__ rowstart,
                                const int* __restrict__ partials, int n) {
    int gi = blockIdx.x * 1024 + threadIdx.x;
    if (gi < n) rowstart[gi] = rowstart[gi] - deg[gi] + partials[blockIdx.x];
}

__global__ void k_fill_self(const int* __restrict__ rowstart, int* __restrict__ col,
                            int* __restrict__ cursor, const int* __restrict__ deg,
                            float* __restrict__ dis, int n) {
    int i = blockIdx.x * blockDim.x + threadIdx.x;
    if (i < n) {
        int rs = rowstart[i];
        col[rs] = i;
        cursor[i] = rs + 1;
        dis[i] = rsqrtf((float)deg[i]);
    }
}

__global__ void k_scatter_edges(const int* __restrict__ src, const int* __restrict__ dst,
                                int* cursor, int* __restrict__ col, int e) {
    int i = blockIdx.x * blockDim.x + threadIdx.x;
    if (i < e) {
        int pos = atomicAdd(&cursor[dst[i]], 1);
        col[pos] = src[i];
    }
}

// ---------------- 3xTF32 tensor-core GEMM, fp16 output -----------------------
// C[M,N] = A[M,K] @ B[K,N].  BM=128, BN=64, BK=16, 256 threads (8 warps, 4x2).
__global__ void __launch_bounds__(256) k_gemm_tc(const float* __restrict__ A,
                                                 const float* __restrict__ B,
                                                 __half* __restrict__ C,
                                                 int M, int N, int K) {
    __shared__ u32 As_hi[128][20], As_lo[128][20];
    __shared__ u32 Bs_hi[16][72], Bs_lo[16][72];

    int tid = threadIdx.x;
    int bm0 = blockIdx.x * 128, bn0 = blockIdx.y * 64;
    int w = tid >> 5, lane = tid & 31;
    int wm = (w & 3) * 32, wn = (w >> 2) * 32;
    int g = lane >> 2, t = lane & 3;

    float acc[2][4][4] = {};

    for (int kt = 0; kt < K; kt += 16) {
#pragma unroll
        for (int i = 0; i < 2; i++) {
            int idx = tid + i * 256;
            int r = idx >> 2, c4 = (idx & 3) << 2;
            float4 v = make_float4(0.f, 0.f, 0.f, 0.f);
            int gr = bm0 + r;
            if (gr < M) v = *(const float4*)(A + (size_t)gr * K + kt + c4);
            u32 hx = f2tf32(v.x), hy = f2tf32(v.y), hz = f2tf32(v.z), hw = f2tf32(v.w);
            As_hi[r][c4 + 0] = hx; As_hi[r][c4 + 1] = hy;
            As_hi[r][c4 + 2] = hz; As_hi[r][c4 + 3] = hw;
            As_lo[r][c4 + 0] = f2tf32(v.x - __uint_as_float(hx));
            As_lo[r][c4 + 1] = f2tf32(v.y - __uint_as_float(hy));
            As_lo[r][c4 + 2] = f2tf32(v.z - __uint_as_float(hz));
            As_lo[r][c4 + 3] = f2tf32(v.w - __uint_as_float(hw));
        }
        {
            int r = tid >> 4, c4 = (tid & 15) << 2;
            float4 v = *(const float4*)(B + (size_t)(kt + r) * N + bn0 + c4);
            u32 hx = f2tf32(v.x), hy = f2tf32(v.y), hz = f2tf32(v.z), hw = f2tf32(v.w);
            Bs_hi[r][c4 + 0] = hx; Bs_hi[r][c4 + 1] = hy;
            Bs_hi[r][c4 + 2] = hz; Bs_hi[r][c4 + 3] = hw;
            Bs_lo[r][c4 + 0] = f2tf32(v.x - __uint_as_float(hx));
            Bs_lo[r][c4 + 1] = f2tf32(v.y - __uint_as_float(hy));
            Bs_lo[r][c4 + 2] = f2tf32(v.z - __uint_as_float(hz));
            Bs_lo[r][c4 + 3] = f2tf32(v.w - __uint_as_float(hw));
        }
        __syncthreads();

#pragma unroll
        for (int kk = 0; kk < 2; kk++) {
            int k0 = kk * 8;
            u32 ah[2][4], al[2][4], bh[4][2], bl[4][2];
#pragma unroll
            for (int mt = 0; mt < 2; mt++) {
                int r = wm + mt * 16 + g;
                ah[mt][0] = As_hi[r][k0 + t];     ah[mt][1] = As_hi[r + 8][k0 + t];
                ah[mt][2] = As_hi[r][k0 + t + 4]; ah[mt][3] = As_hi[r + 8][k0 + t + 4];
                al[mt][0] = As_lo[r][k0 + t];     al[mt][1] = As_lo[r + 8][k0 + t];
                al[mt][2] = As_lo[r][k0 + t + 4]; al[mt][3] = As_lo[r + 8][k0 + t + 4];
            }
#pragma unroll
            for (int nt = 0; nt < 4; nt++) {
                int c = wn + nt * 8 + g;
                bh[nt][0] = Bs_hi[k0 + t][c]; bh[nt][1] = Bs_hi[k0 + t + 4][c];
                bl[nt][0] = Bs_lo[k0 + t][c]; bl[nt][1] = Bs_lo[k0 + t + 4][c];
            }
#pragma unroll
            for (int mt = 0; mt < 2; mt++)
#pragma unroll
                for (int nt = 0; nt < 4; nt++) {
                    mma_tf32(acc[mt][nt], ah[mt], bh[nt]);
                    mma_tf32(acc[mt][nt], ah[mt], bl[nt]);
                    mma_tf32(acc[mt][nt], al[mt], bh[nt]);
                }
        }
        __syncthreads();
    }

#pragma unroll
    for (int mt = 0; mt < 2; mt++) {
        int r0 = bm0 + wm + mt * 16 + g;
#pragma unroll
        for (int nt = 0; nt < 4; nt++) {
            int c = bn0 + wn + nt * 8 + 2 * t;
            if (r0 < M)
                *(__half2*)(C + (size_t)r0 * N + c) =
                    __floats2half2_rn(acc[mt][nt][0], acc[mt][nt][1]);
            if (r0 + 8 < M)
                *(__half2*)(C + (size_t)(r0 + 8) * N + c) =
                    __floats2half2_rn(acc[mt][nt][2], acc[mt][nt][3]);
        }
    }
}

// ---------------- GAT attention scores (fp16 h) -------------------------------
// 4 heads x 64: per head, lane covers 2 channels via one half2.
__global__ void k_scores4(const __half* __restrict__ h, const float* __restrict__ a_src,
                          const float* __restrict__ a_dst, float* __restrict__ scs,
                          float* __restrict__ scd, int n) {
    int node = blockIdx.x * 8 + (threadIdx.x >> 5);
    int lane = threadIdx.x & 31;
    if (node >= n) return;
#pragma unroll
    for (int hd = 0; hd < 4; hd++) {
        float2 hv = __half22float2(*(const __half2*)(h + (size_t)node * D1 + hd * 64 + 2 * lane));
        float2 as = *(const float2*)(a_src + hd * 64 + 2 * lane);
        float2 ad = *(const float2*)(a_dst + hd * 64 + 2 * lane);
        float ps = hv.x * as.x + hv.y * as.y;
        float pd = hv.x * ad.x + hv.y * ad.y;
#pragma unroll
        for (int off = 16; off; off >>= 1) {
            ps += __shfl_xor_sync(0xffffffffu, ps, off);
            pd += __shfl_xor_sync(0xffffffffu, pd, off);
        }
        if (lane == 0) { scs[node * 4 + hd] = ps; scd[node * 4 + hd] = pd; }
    }
}

// 1 head x 128: lane covers 4 channels via uint2 (4 halves).
__global__ void k_scores1(const __half* __restrict__ h, const float* __restrict__ a_src,
                          const float* __restrict__ a_dst, float* __restrict__ scs,
                          float* __restrict__ scd, int n) {
    int node = blockIdx.x * 8 + (threadIdx.x >> 5);
    int lane = threadIdx.x & 31;
    if (node >= n) return;
    uint2 raw = *(const uint2*)(h + (size_t)node * D2 + 4 * lane);
    float2 f0 = __half22float2(*(const __half2*)&raw.x);
    float2 f1 = __half22float2(*(const __half2*)&raw.y);
    float4 as = *(const float4*)(a_src + 4 * lane);
    float4 ad = *(const float4*)(a_dst + 4 * lane);
    float ps = f0.x * as.x + f0.y * as.y + f1.x * as.z + f1.y * as.w;
    float pd = f0.x * ad.x + f0.y * ad.y + f1.x * ad.z + f1.y * ad.w;
#pragma unroll
    for (int off = 16; off; off >>= 1) {
        ps += __shfl_xor_sync(0xffffffffu, ps, off);
        pd += __shfl_xor_sync(0xffffffffu, pd, off);
    }
    if (lane == 0) { scs[node] = ps; scd[node] = pd; }
}

// ---------------- GAT aggregation: single pass, fp16 gather -------------------
// 4 heads x 64ch. Lane owns channels [4*lane,4*lane+4) (chunk A) and +128 (B).
__global__ void k_gat_agg4(const __half* __restrict__ h, const float* __restrict__ scs,
                           const float* __restrict__ scd_arr,
                           const float* __restrict__ bias,
                           const float* __restrict__ bn_g, const float* __restrict__ bn_b,
                           const int* __restrict__ rowstart, const int* __restrict__ col,
                           float* __restrict__ xout, int n) {
    int node = blockIdx.x * 8 + (threadIdx.x >> 5);
    int lane = threadIdx.x & 31;
    if (node >= n) return;
    int rs = rowstart[node], re = rowstart[node + 1];

    float4 scd4 = *(const float4*)(scd_arr + node * 4);
    bool lo = lane < 16;
    float scdA = lo ? scd4.x : scd4.y;
    float scdB = lo ? scd4.z : scd4.w;

    const uint2* hu = (const uint2*)h;          // 4 halves per uint2; row = 64 uint2
    const float4* scs4 = (const float4*)scs;

    float4 accA = make_float4(0.f, 0.f, 0.f, 0.f);
    float4 accB = make_float4(0.f, 0.f, 0.f, 0.f);
    float wsA = 0.f, wsB = 0.f;

    for (int base = rs; base < re; base += 32) {
        int idx = base + lane;
        int ck = col[idx < re ? idx : re - 1];
        int cnt = min(32, re - base);
        for (int j = 0; j < cnt; j++) {
            int s = __shfl_sync(0xffffffffu, ck, j);
            float4 sv = scs4[s];
            float eA = lrelu((lo ? sv.x : sv.y) + scdA, 0.2f);
            float eB = lrelu((lo ? sv.z : sv.w) + scdB, 0.2f);
            float wa = __expf(eA), wb = __expf(eB);
            uint2 ra = hu[(size_t)s * 64 + lane];
            uint2 rb = hu[(size_t)s * 64 + 32 + lane];
            float2 a0 = __half22float2(*(const __half2*)&ra.x);
            float2 a1 = __half22float2(*(const __half2*)&ra.y);
            float2 b0 = __half22float2(*(const __half2*)&rb.x);
            float2 b1 = __half22float2(*(const __half2*)&rb.y);
            accA.x += a0.x * wa; accA.y += a0.y * wa;
            accA.z += a1.x * wa; accA.w += a1.y * wa;
            accB.x += b0.x * wb; accB.y += b0.y * wb;
            accB.z += b1.x * wb; accB.w += b1.y * wb;
            wsA += wa; wsB += wb;
        }
    }

    float ia = 1.f / wsA, ib = 1.f / wsB;
    const float inv_bn = rsqrtf(1.0f + 1e-5f);
    float4 bA = ((const float4*)bias)[lane],  bB = ((const float4*)bias)[lane + 32];
    float4 gA = ((const float4*)bn_g)[lane],  gB = ((const float4*)bn_g)[lane + 32];
    float4 cA = ((const float4*)bn_b)[lane],  cB = ((const float4*)bn_b)[lane + 32];
    float4 oA, oB;
    oA.x = lrelu(accA.x * ia + bA.x, 0.01f) * (gA.x * inv_bn) + cA.x;
    oA.y = lrelu(accA.y * ia + bA.y, 0.01f) * (gA.y * inv_bn) + cA.y;
    oA.z = lrelu(accA.z * ia + bA.z, 0.01f) * (gA.z * inv_bn) + cA.z;
    oA.w = lrelu(accA.w * ia + bA.w, 0.01f) * (gA.w * inv_bn) + cA.w;
    oB.x = lrelu(accB.x * ib + bB.x, 0.01f) * (gB.x * inv_bn) + cB.x;
    oB.y = lrelu(accB.y * ib + bB.y, 0.01f) * (gB.y * inv_bn) + cB.y;
    oB.z = lrelu(accB.z * ib + bB.z, 0.01f) * (gB.z * inv_bn) + cB.z;
    oB.w = lrelu(accB.w * ib + bB.w, 0.01f) * (gB.w * inv_bn) + cB.w;
    ((float4*)xout)[(size_t)node * 64 + lane]      = oA;
    ((float4*)xout)[(size_t)node * 64 + lane + 32] = oB;
}

// 1 head x 128ch, fp16 gather: lane owns channels [4*lane, 4*lane+4).
__global__ void k_gat_agg1(const __half* __restrict__ h, const float* __restrict__ scs,
                           const float* __restrict__ scd_arr,
                           const float* __restrict__ bias,
                           const float* __restrict__ bn_g, const float* __restrict__ bn_b,
                           const int* __restrict__ rowstart, const int* __restrict__ col,
                           float* __restrict__ xout, int n) {
    int node = blockIdx.x * 8 + (threadIdx.x >> 5);
    int lane = threadIdx.x & 31;
    if (node >= n) return;
    int rs = rowstart[node], re = rowstart[node + 1];

    float scd0 = scd_arr[node];
    const uint2* hu = (const uint2*)h;          // row = 32 uint2

    float4 acc = make_float4(0.f, 0.f, 0.f, 0.f);
    float ws = 0.f;

    for (int base = rs; base < re; base += 32) {
        int idx = base + lane;
        int ck = col[idx < re ? idx : re - 1];
        int cnt = min(32, re - base);
        for (int j = 0; j < cnt; j++) {
            int s = __shfl_sync(0xffffffffu, ck, j);
            float e = lrelu(scs[s] + scd0, 0.2f);
            float wv = __expf(e);
            uint2 r = hu[(size_t)s * 32 + lane];
            float2 f0 = __half22float2(*(const __half2*)&r.x);
            float2 f1 = __half22float2(*(const __half2*)&r.y);
            acc.x += f0.x * wv; acc.y += f0.y * wv;
            acc.z += f1.x * wv; acc.w += f1.y * wv;
            ws += wv;
        }
    }

    float inv = 1.f / ws;
    const float inv_bn = rsqrtf(1.0f + 1e-5f);
    float4 bA = ((const float4*)bias)[lane];
    float4 gA = ((const float4*)bn_g)[lane];
    float4 cA = ((const float4*)bn_b)[lane];
    float4 o;
    o.x = lrelu(acc.x * inv + bA.x, 0.01f) * (gA.x * inv_bn) + cA.x;
    o.y = lrelu(acc.y * inv + bA.y, 0.01f) * (gA.y * inv_bn) + cA.y;
    o.z = lrelu(acc.z * inv + bA.z, 0.01f) * (gA.z * inv_bn) + cA.z;
    o.w = lrelu(acc.w * inv + bA.w, 0.01f) * (gA.w * inv_bn) + cA.w;
    ((float4*)xout)[(size_t)node * 32 + lane] = o;
}

// ---------------- GCN (fp16 gather) -------------------------------------------
__global__ void k_gcn_agg(const __half* __restrict__ h, const float* __restrict__ dis,
                          const float* __restrict__ bg,
                          const int* __restrict__ rowstart, const int* __restrict__ col,
                          float* __restrict__ xout, int n) {
    int node = blockIdx.x * 8 + (threadIdx.x >> 5);
    int lane = threadIdx.x & 31;
    if (node >= n) return;
    int rs = rowstart[node], re = rowstart[node + 1];
    float wi = dis[node];
    const __half2* h2 = (const __half2*)h;      // row = 32 half2
    float2 acc = make_float2(0.f, 0.f);
    for (int base = rs; base < re; base += 32) {
        int idx = base + lane;
        int ck = col[idx < re ? idx : re - 1];
        int cnt = min(32, re - base);
        for (int j = 0; j < cnt; j++) {
            int s = __shfl_sync(0xffffffffu, ck, j);
            float w = dis[s] * wi;
            float2 v = __half22float2(h2[(size_t)s * 32 + lane]);
            acc.x += v.x * w; acc.y += v.y * w;
        }
    }
    float2 bgv = ((const float2*)bg)[lane];
    float2 o;
    o.x = lrelu(acc.x + bgv.x, 0.01f);
    o.y = lrelu(acc.y + bgv.y, 0.01f);
    ((float2*)xout)[(size_t)node * 32 + lane] = o;
}

// ---------------- pooling + MLP ----------------------------------------------
__global__ void k_zero2(float* p, int n, float* q, int m) {
    int i = blockIdx.x * blockDim.x + threadIdx.x;
    if (i < n) p[i] = 0.f;
    if (i < m) q[i] = 0.f;
}

__global__ void k_pool(const float* __restrict__ x3, const int* __restrict__ batch,
                       float* pool, float* cnt, int n) {
    int node = blockIdx.x * 8 + (threadIdx.x >> 5);
    int lane = threadIdx.x & 31;
    if (node >= n) return;
    int b = batch[node];
    float2 v = ((const float2*)x3)[(size_t)node * 32 + lane];
    atomicAdd(&pool[b * D3 + 2 * lane], v.x);
    atomicAdd(&pool[b * D3 + 2 * lane + 1], v.y);
    if (lane == 0) atomicAdd(&cnt[b], 1.f);
}

__global__ void __launch_bounds__(128) k_mlp(const float* __restrict__ pool,
                                             const float* __restrict__ cnt,
                                             const float* __restrict__ l1W,
                                             const float* __restrict__ l1b,
                                             const float* __restrict__ g3,
                                             const float* __restrict__ b3,
                                             const float* __restrict__ l2W,
                                             const float* __restrict__ l2b,
                                             float* __restrict__ out) {
    int b = blockIdx.x;
    int t = threadIdx.x;
    __shared__ float sp[64];
    __shared__ float sy[128];
    if (t < 64) sp[t] = pool[b * D3 + t] / fmaxf(cnt[b], 1.f);
    __syncthreads();
    float v = l1b[t];
#pragma unroll
    for (int k = 0; k < 64; k++) v += sp[k] * l1W[k * 128 + t];
    v = v * (g3[t] * rsqrtf(1.0f + 1e-5f)) + b3[t];
    v = lrelu(v, 0.01f);
    sy[t] = v;
    __syncthreads();
    if (t < NCc) {
        float o = l2b[t];
#pragma unroll
        for (int k = 0; k < 128; k++) o += sy[k] * l2W[k * NCc + t];
        out[b * NCc + t] = o;
    }
}

// ---------------- launch -----------------------------------------------------
extern "C" void kernel_launch(void* const* d_in, const int* in_sizes, int n_in,
                              void* d_out, int out_size) {
    const float* x      = (const float*)d_in[0];
    const int*   ei     = (const int*)d_in[1];
    const int*   batch  = (const int*)d_in[2];
    const float* W1     = (const float*)d_in[3];
    const float* a_src1 = (const float*)d_in[4];
    const float* a_dst1 = (const float*)d_in[5];
    const float* b1     = (const float*)d_in[6];
    const float* W2     = (const float*)d_in[7];
    const float* a_src2 = (const float*)d_in[8];
    const float* a_dst2 = (const float*)d_in[9];
    const float* b2     = (const float*)d_in[10];
    const float* Wg     = (const float*)d_in[11];
    const float* bg     = (const float*)d_in[12];
    const float* bn1g   = (const float*)d_in[13];
    const float* bn1b   = (const float*)d_in[14];
    const float* bn2g   = (const float*)d_in[15];
    const float* bn2b   = (const float*)d_in[16];
    const float* bn3g   = (const float*)d_in[17];
    const float* bn3b   = (const float*)d_in[18];
    const float* l1W    = (const float*)d_in[19];
    const float* l1b    = (const float*)d_in[20];
    const float* l2W    = (const float*)d_in[21];
    const float* l2b    = (const float*)d_in[22];
    float* out = (float*)d_out;

    int *deg, *rowstart, *cursor, *col, *partials;
    __half *h1, *h2, *h3;
    float *x1, *x2, *x3, *scs1, *scd1, *scs2, *scd2, *dis, *pool, *cnt;
    cudaGetSymbolAddress((void**)&deg, g_deg);
    cudaGetSymbolAddress((void**)&rowstart, g_rowstart);
    cudaGetSymbolAddress((void**)&cursor, g_cursor);
    cudaGetSymbolAddress((void**)&col, g_col);
    cudaGetSymbolAddress((void**)&partials, g_partials);
    cudaGetSymbolAddress((void**)&h1, g_h1);
    cudaGetSymbolAddress((void**)&x1, g_x1);
    cudaGetSymbolAddress((void**)&h2, g_h2);
    cudaGetSymbolAddress((void**)&x2, g_x2);
    cudaGetSymbolAddress((void**)&h3, g_h3);
    cudaGetSymbolAddress((void**)&x3, g_x3);
    cudaGetSymbolAddress((void**)&scs1, g_scs1);
    cudaGetSymbolAddress((void**)&scd1, g_scd1);
    cudaGetSymbolAddress((void**)&scs2, g_scs2);
    cudaGetSymbolAddress((void**)&scd2, g_scd2);
    cudaGetSymbolAddress((void**)&dis, g_dis);
    cudaGetSymbolAddress((void**)&pool, g_pool);
    cudaGetSymbolAddress((void**)&cnt, g_cnt);

    const int* src = ei;
    const int* dst = ei + Ee;

    static cudaStream_t s2 = nullptr;
    static cudaEvent_t evFork = nullptr, evJoin = nullptr;
    if (!s2) {
        cudaStreamCreateWithFlags(&s2, cudaStreamNonBlocking);
        cudaEventCreateWithFlags(&evFork, cudaEventDisableTiming);
        cudaEventCreateWithFlags(&evJoin, cudaEventDisableTiming);
    }

    // ---- fork: CSR build on s2, GEMM1+scores on main stream ----
    cudaEventRecord(evFork, 0);
    cudaStreamWaitEvent(s2, evFork, 0);

    k_init_deg<<<(Nn + 255) / 256, 256, 0, s2>>>(deg, Nn);
    k_deg_scatter<<<(Ee + 255) / 256, 256, 0, s2>>>(dst, deg, Ee);
    k_scan_block<<<NB_SCAN, 1024, 0, s2>>>(deg, rowstart, partials, Nn);
    k_scan_partials<<<1, 64, 0, s2>>>(partials, rowstart, NB_SCAN, Nn);
    k_scan_finalize<<<NB_SCAN, 1024, 0, s2>>>(deg, rowstart, partials, Nn);
    k_fill_self<<<(Nn + 255) / 256, 256, 0, s2>>>(rowstart, col, cursor, deg, dis, Nn);
    k_scatter_edges<<<(Ee + 255) / 256, 256, 0, s2>>>(src, dst, cursor, col, Ee);
    k_zero2<<<(Bb * D3 + 255) / 256, 256, 0, s2>>>(pool, Bb * D3, cnt, Bb);
    cudaEventRecord(evJoin, s2);

    k_gemm_tc<<<dim3((Nn + 127) / 128, D1 / 64), 256>>>(x, W1, h1, Nn, D1, Fdim);
    k_scores4<<<(Nn + 7) / 8, 256>>>(h1, a_src1, a_dst1, scs1, scd1, Nn);

    cudaStreamWaitEvent(0, evJoin, 0);

    // ---- GAT layer 1 aggregation ----
    k_gat_agg4<<<(Nn + 7) / 8, 256>>>(h1, scs1, scd1, b1, bn1g, bn1b,
                                      rowstart, col, x1, Nn);

    // ---- GAT layer 2: 256 -> 1 head x 128 ----
    k_gemm_tc<<<dim3((Nn + 127) / 128, D2 / 64), 256>>>(x1, W2, h2, Nn, D2, D1);
    k_scores1<<<(Nn + 7) / 8, 256>>>(h2, a_src2, a_dst2, scs2, scd2, Nn);
    k_gat_agg1<<<(Nn + 7) / 8, 256>>>(h2, scs2, scd2, b2, bn2g, bn2b,
                                      rowstart, col, x2, Nn);

    // ---- GCN: 128 -> 64 ----
    k_gemm_tc<<<dim3((Nn + 127) / 128, D3 / 64), 256>>>(x2, Wg, h3, Nn, D3, D2);
    k_gcn_agg<<<(Nn + 7) / 8, 256>>>(h3, dis, bg, rowstart, col, x3, Nn);

    // ---- global mean pool + MLP head ----
    k_pool<<<(Nn + 7) / 8, 256>>>(x3, batch, pool, cnt, Nn);
    k_mlp<<<Bb, 128>>>(pool, cnt, l1W, l1b, bn3g, bn3b, l2W, l2b, out);
}

// round 6
// speedup vs baseline: 1.3431x; 1.0215x over previous
#include <cuda_runtime.h>
#include <cuda_fp16.h>
#include <math_constants.h>
#include <cstdint>

// Problem constants (fixed by reference setup_inputs)
#define Nn   50000
#define Ee   800000
#define E2   (Ee + Nn)
#define Fdim 128
#define D1   256   // 4 heads x 64
#define D2   128   // 1 head x 128
#define D3   64    // GCN out
#define Bb   512
#define NCc  10
#define NB_SCAN ((Nn + 1023) / 1024)

typedef unsigned int u32;

// ---------------- scratch (device globals; no allocation allowed) -----------
__device__ __align__(16) int   g_deg[Nn];
__device__ __align__(16) int   g_rowstart[Nn + 1];
__device__ __align__(16) int   g_cursor[Nn];
__device__ __align__(16) int   g_col[E2];
__device__ __align__(16) int   g_partials[NB_SCAN + 1];

__device__ __align__(16) __half g_h1[(size_t)Nn * D1];
__device__ __align__(16) float  g_x1[(size_t)Nn * D1];
__device__ __align__(16) __half g_h2[(size_t)Nn * D2];
__device__ __align__(16) float  g_x2[(size_t)Nn * D2];
__device__ __align__(16) __half g_h3[(size_t)Nn * D3];
__device__ __align__(16) float  g_x3[(size_t)Nn * D3];
__device__ __align__(16) float  g_scs1[Nn * 4];
__device__ __align__(16) float  g_scd1[Nn * 4];
__device__ __align__(16) float  g_scs2[Nn];
__device__ __align__(16) float  g_scd2[Nn];
__device__ __align__(16) float  g_dis[Nn];
__device__ __align__(16) float  g_pool[Bb * D3];
__device__ __align__(16) float  g_cnt[Bb];

// ---------------- small helpers ---------------------------------------------
__device__ __forceinline__ float lrelu(float v, float s) { return v > 0.f ? v : s * v; }

__device__ __forceinline__ u32 f2tf32(float x) {
    u32 r;
    asm("cvt.rna.tf32.f32 %0, %1;" : "=r"(r) : "f"(x));
    return r;
}

__device__ __forceinline__ void mma_tf32(float* c, const u32* a, const u32* b) {
    asm volatile(
        "mma.sync.aligned.m16n8k8.row.col.f32.tf32.tf32.f32 "
        "{%0,%1,%2,%3}, {%4,%5,%6,%7}, {%8,%9}, {%0,%1,%2,%3};"
        : "+f"(c[0]), "+f"(c[1]), "+f"(c[2]), "+f"(c[3])
        : "r"(a[0]), "r"(a[1]), "r"(a[2]), "r"(a[3]), "r"(b[0]), "r"(b[1]));
}

// ---------------- CSR build --------------------------------------------------
__global__ void k_init_deg(int* deg, int n) {
    int i = blockIdx.x * blockDim.x + threadIdx.x;
    if (i < n) deg[i] = 1;  // self-loop
}

__global__ void k_deg_scatter(const int* __restrict__ dst, int* deg, int e) {
    int i = blockIdx.x * blockDim.x + threadIdx.x;
    if (i < e) atomicAdd(&deg[dst[i]], 1);
}

__global__ void k_scan_block(const int* __restrict__ deg, int* __restrict__ rowstart,
                             int* __restrict__ partials, int n) {
    __shared__ int s[1024];
    int t = threadIdx.x;
    int gi = blockIdx.x * 1024 + t;
    int v = (gi < n) ? deg[gi] : 0;
    s[t] = v;
    __syncthreads();
#pragma unroll
    for (int off = 1; off < 1024; off <<= 1) {
        int xv = (t >= off) ? s[t - off] : 0;
        __syncthreads();
        s[t] += xv;
        __syncthreads();
    }
    if (gi < n) rowstart[gi] = s[t];          // block-inclusive
    if (t == 1023) partials[blockIdx.x] = s[t];
}

__global__ void k_scan_partials(int* partials, int* rowstart, int nb, int n) {
    __shared__ int wsum[2];
    int t = threadIdx.x;
    int lane = t & 31, w = t >> 5;
    int orig = (t < nb) ? partials[t] : 0;
    int v = orig;
#pragma unroll
    for (int o = 1; o < 32; o <<= 1) {
        int xv = __shfl_up_sync(0xffffffffu, v, o);
        if (lane >= o) v += xv;
    }
    if (lane == 31) wsum[w] = v;
    __syncthreads();
    if (w == 1) v += wsum[0];
    if (t < nb) partials[t] = v - orig;   // exclusive
    if (t == 63) rowstart[n] = v;         // total (= N + E)
}

__global__ void k_scan_finalize(const int* __restrict__ deg, int* __restrict__ rowstart,
                                const int* __restrict__ partials, int n) {
    int gi = blockIdx.x * 1024 + threadIdx.x;
    if (gi < n) rowstart[gi] = rowstart[gi] - deg[gi] + partials[blockIdx.x];
}

__global__ void k_fill_self(const int* __restrict__ rowstart, int* __restrict__ col,
                            int* __restrict__ cursor, const int* __restrict__ deg,
                            float* __restrict__ dis, int n) {
    int i = blockIdx.x * blockDim.x + threadIdx.x;
    if (i < n) {
        int rs = rowstart[i];
        col[rs] = i;
        cursor[i] = rs + 1;
        dis[i] = rsqrtf((float)deg[i]);
    }
}

__global__ void k_scatter_edges(const int* __restrict__ src, const int* __restrict__ dst,
                                int* cursor, int* __restrict__ col, int e) {
    int i = blockIdx.x * blockDim.x + threadIdx.x;
    if (i < e) {
        int pos = atomicAdd(&cursor[dst[i]], 1);
        col[pos] = src[i];
    }
}

// ---------------- 3xTF32 tensor-core GEMM, fp16 output -----------------------
__global__ void __launch_bounds__(256) k_gemm_tc(const float* __restrict__ A,
                                                 const float* __restrict__ B,
                                                 __half* __restrict__ C,
                                                 int M, int N, int K) {
    __shared__ u32 As_hi[128][20], As_lo[128][20];
    __shared__ u32 Bs_hi[16][72], Bs_lo[16][72];

    int tid = threadIdx.x;
    int bm0 = blockIdx.x * 128, bn0 = blockIdx.y * 64;
    int w = tid >> 5, lane = tid & 31;
    int wm = (w & 3) * 32, wn = (w >> 2) * 32;
    int g = lane >> 2, t = lane & 3;

    float acc[2][4][4] = {};

    for (int kt = 0; kt < K; kt += 16) {
#pragma unroll
        for (int i = 0; i < 2; i++) {
            int idx = tid + i * 256;
            int r = idx >> 2, c4 = (idx & 3) << 2;
            float4 v = make_float4(0.f, 0.f, 0.f, 0.f);
            int gr = bm0 + r;
            if (gr < M) v = *(const float4*)(A + (size_t)gr * K + kt + c4);
            u32 hx = f2tf32(v.x), hy = f2tf32(v.y), hz = f2tf32(v.z), hw = f2tf32(v.w);
            As_hi[r][c4 + 0] = hx; As_hi[r][c4 + 1] = hy;
            As_hi[r][c4 + 2] = hz; As_hi[r][c4 + 3] = hw;
            As_lo[r][c4 + 0] = f2tf32(v.x - __uint_as_float(hx));
            As_lo[r][c4 + 1] = f2tf32(v.y - __uint_as_float(hy));
            As_lo[r][c4 + 2] = f2tf32(v.z - __uint_as_float(hz));
            As_lo[r][c4 + 3] = f2tf32(v.w - __uint_as_float(hw));
        }
        {
            int r = tid >> 4, c4 = (tid & 15) << 2;
            float4 v = *(const float4*)(B + (size_t)(kt + r) * N + bn0 + c4);
            u32 hx = f2tf32(v.x), hy = f2tf32(v.y), hz = f2tf32(v.z), hw = f2tf32(v.w);
            Bs_hi[r][c4 + 0] = hx; Bs_hi[r][c4 + 1] = hy;
            Bs_hi[r][c4 + 2] = hz; Bs_hi[r][c4 + 3] = hw;
            Bs_lo[r][c4 + 0] = f2tf32(v.x - __uint_as_float(hx));
            Bs_lo[r][c4 + 1] = f2tf32(v.y - __uint_as_float(hy));
            Bs_lo[r][c4 + 2] = f2tf32(v.z - __uint_as_float(hz));
            Bs_lo[r][c4 + 3] = f2tf32(v.w - __uint_as_float(hw));
        }
        __syncthreads();

#pragma unroll
        for (int kk = 0; kk < 2; kk++) {
            int k0 = kk * 8;
            u32 ah[2][4], al[2][4], bh[4][2], bl[4][2];
#pragma unroll
            for (int mt = 0; mt < 2; mt++) {
                int r = wm + mt * 16 + g;
                ah[mt][0] = As_hi[r][k0 + t];     ah[mt][1] = As_hi[r + 8][k0 + t];
                ah[mt][2] = As_hi[r][k0 + t + 4]; ah[mt][3] = As_hi[r + 8][k0 + t + 4];
                al[mt][0] = As_lo[r][k0 + t];     al[mt][1] = As_lo[r + 8][k0 + t];
                al[mt][2] = As_lo[r][k0 + t + 4]; al[mt][3] = As_lo[r + 8][k0 + t + 4];
            }
#pragma unroll
            for (int nt = 0; nt < 4; nt++) {
                int c = wn + nt * 8 + g;
                bh[nt][0] = Bs_hi[k0 + t][c]; bh[nt][1] = Bs_hi[k0 + t + 4][c];
                bl[nt][0] = Bs_lo[k0 + t][c]; bl[nt][1] = Bs_lo[k0 + t + 4][c];
            }
#pragma unroll
            for (int mt = 0; mt < 2; mt++)
#pragma unroll
                for (int nt = 0; nt < 4; nt++) {
                    mma_tf32(acc[mt][nt], ah[mt], bh[nt]);
                    mma_tf32(acc[mt][nt], ah[mt], bl[nt]);
                    mma_tf32(acc[mt][nt], al[mt], bh[nt]);
                }
        }
        __syncthreads();
    }

#pragma unroll
    for (int mt = 0; mt < 2; mt++) {
        int r0 = bm0 + wm + mt * 16 + g;
#pragma unroll
        for (int nt = 0; nt < 4; nt++) {
            int c = bn0 + wn + nt * 8 + 2 * t;
            if (r0 < M)
                *(__half2*)(C + (size_t)r0 * N + c) =
                    __floats2half2_rn(acc[mt][nt][0], acc[mt][nt][1]);
            if (r0 + 8 < M)
                *(__half2*)(C + (size_t)(r0 + 8) * N + c) =
                    __floats2half2_rn(acc[mt][nt][2], acc[mt][nt][3]);
        }
    }
}

// ---------------- GAT attention scores (fp16 h) -------------------------------
__global__ void k_scores4(const __half* __restrict__ h, const float* __restrict__ a_src,
                          const float* __restrict__ a_dst, float* __restrict__ scs,
                          float* __restrict__ scd, int n) {
    int node = blockIdx.x * 8 + (threadIdx.x >> 5);
    int lane = threadIdx.x & 31;
    if (node >= n) return;
#pragma unroll
    for (int hd = 0; hd < 4; hd++) {
        float2 hv = __half22float2(*(const __half2*)(h + (size_t)node * D1 + hd * 64 + 2 * lane));
        float2 as = *(const float2*)(a_src + hd * 64 + 2 * lane);
        float2 ad = *(const float2*)(a_dst + hd * 64 + 2 * lane);
        float ps = hv.x * as.x + hv.y * as.y;
        float pd = hv.x * ad.x + hv.y * ad.y;
#pragma unroll
        for (int off = 16; off; off >>= 1) {
            ps += __shfl_xor_sync(0xffffffffu, ps, off);
            pd += __shfl_xor_sync(0xffffffffu, pd, off);
        }
        if (lane == 0) { scs[node * 4 + hd] = ps; scd[node * 4 + hd] = pd; }
    }
}

__global__ void k_scores1(const __half* __restrict__ h, const float* __restrict__ a_src,
                          const float* __restrict__ a_dst, float* __restrict__ scs,
                          float* __restrict__ scd, int n) {
    int node = blockIdx.x * 8 + (threadIdx.x >> 5);
    int lane = threadIdx.x & 31;
    if (node >= n) return;
    uint2 raw = *(const uint2*)(h + (size_t)node * D2 + 4 * lane);
    float2 f0 = __half22float2(*(const __half2*)&raw.x);
    float2 f1 = __half22float2(*(const __half2*)&raw.y);
    float4 as = *(const float4*)(a_src + 4 * lane);
    float4 ad = *(const float4*)(a_dst + 4 * lane);
    float ps = f0.x * as.x + f0.y * as.y + f1.x * as.z + f1.y * as.w;
    float pd = f0.x * ad.x + f0.y * ad.y + f1.x * ad.z + f1.y * ad.w;
#pragma unroll
    for (int off = 16; off; off >>= 1) {
        ps += __shfl_xor_sync(0xffffffffu, ps, off);
        pd += __shfl_xor_sync(0xffffffffu, pd, off);
    }
    if (lane == 0) { scs[node] = ps; scd[node] = pd; }
}

// ---------------- GAT aggregation: single pass, 4-edge batched ---------------
__global__ void k_gat_agg4(const __half* __restrict__ h, const float* __restrict__ scs,
                           const float* __restrict__ scd_arr,
                           const float* __restrict__ bias,
                           const float* __restrict__ bn_g, const float* __restrict__ bn_b,
                           const int* __restrict__ rowstart, const int* __restrict__ col,
                           float* __restrict__ xout, int n) {
    int node = blockIdx.x * 8 + (threadIdx.x >> 5);
    int lane = threadIdx.x & 31;
    if (node >= n) return;
    int rs = rowstart[node], re = rowstart[node + 1];

    float4 scd4 = *(const float4*)(scd_arr + node * 4);
    bool lo = lane < 16;
    float scdA = lo ? scd4.x : scd4.y;
    float scdB = lo ? scd4.z : scd4.w;

    const uint2* hu = (const uint2*)h;          // 4 halves per uint2; row = 64 uint2
    const float4* scs4 = (const float4*)scs;

    float4 accA = make_float4(0.f, 0.f, 0.f, 0.f);
    float4 accB = make_float4(0.f, 0.f, 0.f, 0.f);
    float wsA = 0.f, wsB = 0.f;

#define ACC_EDGE4(sv, ra, rb)                                                  \
    {                                                                          \
        float wa = __expf(lrelu((lo ? sv.x : sv.y) + scdA, 0.2f));             \
        float wb = __expf(lrelu((lo ? sv.z : sv.w) + scdB, 0.2f));             \
        float2 a0 = __half22float2(*(const __half2*)&ra.x);                    \
        float2 a1 = __half22float2(*(const __half2*)&ra.y);                    \
        float2 b0 = __half22float2(*(const __half2*)&rb.x);                    \
        float2 b1 = __half22float2(*(const __half2*)&rb.y);                    \
        accA.x += a0.x * wa; accA.y += a0.y * wa;                              \
        accA.z += a1.x * wa; accA.w += a1.y * wa;                              \
        accB.x += b0.x * wb; accB.y += b0.y * wb;                              \
        accB.z += b1.x * wb; accB.w += b1.y * wb;                              \
        wsA += wa; wsB += wb;                                                  \
    }

    for (int base = rs; base < re; base += 32) {
        int idx = base + lane;
        int ck = col[idx < re ? idx : re - 1];
        int cnt = min(32, re - base);
        int j = 0;
        for (; j + 4 <= cnt; j += 4) {
            int s0 = __shfl_sync(0xffffffffu, ck, j + 0);
            int s1 = __shfl_sync(0xffffffffu, ck, j + 1);
            int s2 = __shfl_sync(0xffffffffu, ck, j + 2);
            int s3 = __shfl_sync(0xffffffffu, ck, j + 3);
            float4 sv0 = scs4[s0], sv1 = scs4[s1], sv2 = scs4[s2], sv3 = scs4[s3];
            uint2 ra0 = hu[(size_t)s0 * 64 + lane], rb0 = hu[(size_t)s0 * 64 + 32 + lane];
            uint2 ra1 = hu[(size_t)s1 * 64 + lane], rb1 = hu[(size_t)s1 * 64 + 32 + lane];
            uint2 ra2 = hu[(size_t)s2 * 64 + lane], rb2 = hu[(size_t)s2 * 64 + 32 + lane];
            uint2 ra3 = hu[(size_t)s3 * 64 + lane], rb3 = hu[(size_t)s3 * 64 + 32 + lane];
            ACC_EDGE4(sv0, ra0, rb0)
            ACC_EDGE4(sv1, ra1, rb1)
            ACC_EDGE4(sv2, ra2, rb2)
            ACC_EDGE4(sv3, ra3, rb3)
        }
        for (; j < cnt; j++) {
            int s = __shfl_sync(0xffffffffu, ck, j);
            float4 sv = scs4[s];
            uint2 ra = hu[(size_t)s * 64 + lane], rb = hu[(size_t)s * 64 + 32 + lane];
            ACC_EDGE4(sv, ra, rb)
        }
    }
#undef ACC_EDGE4

    float ia = 1.f / wsA, ib = 1.f / wsB;
    const float inv_bn = rsqrtf(1.0f + 1e-5f);
    float4 bA = ((const float4*)bias)[lane],  bB = ((const float4*)bias)[lane + 32];
    float4 gA = ((const float4*)bn_g)[lane],  gB = ((const float4*)bn_g)[lane + 32];
    float4 cA = ((const float4*)bn_b)[lane],  cB = ((const float4*)bn_b)[lane + 32];
    float4 oA, oB;
    oA.x = lrelu(accA.x * ia + bA.x, 0.01f) * (gA.x * inv_bn) + cA.x;
    oA.y = lrelu(accA.y * ia + bA.y, 0.01f) * (gA.y * inv_bn) + cA.y;
    oA.z = lrelu(accA.z * ia + bA.z, 0.01f) * (gA.z * inv_bn) + cA.z;
    oA.w = lrelu(accA.w * ia + bA.w, 0.01f) * (gA.w * inv_bn) + cA.w;
    oB.x = lrelu(accB.x * ib + bB.x, 0.01f) * (gB.x * inv_bn) + cB.x;
    oB.y = lrelu(accB.y * ib + bB.y, 0.01f) * (gB.y * inv_bn) + cB.y;
    oB.z = lrelu(accB.z * ib + bB.z, 0.01f) * (gB.z * inv_bn) + cB.z;
    oB.w = lrelu(accB.w * ib + bB.w, 0.01f) * (gB.w * inv_bn) + cB.w;
    ((float4*)xout)[(size_t)node * 64 + lane]      = oA;
    ((float4*)xout)[(size_t)node * 64 + lane + 32] = oB;
}

// 1 head x 128ch, fp16 gather, 4-edge batched.
__global__ void k_gat_agg1(const __half* __restrict__ h, const float* __restrict__ scs,
                           const float* __restrict__ scd_arr,
                           const float* __restrict__ bias,
                           const float* __restrict__ bn_g, const float* __restrict__ bn_b,
                           const int* __restrict__ rowstart, const int* __restrict__ col,
                           float* __restrict__ xout, int n) {
    int node = blockIdx.x * 8 + (threadIdx.x >> 5);
    int lane = threadIdx.x & 31;
    if (node >= n) return;
    int rs = rowstart[node], re = rowstart[node + 1];

    float scd0 = scd_arr[node];
    const uint2* hu = (const uint2*)h;          // row = 32 uint2

    float4 acc = make_float4(0.f, 0.f, 0.f, 0.f);
    float ws = 0.f;

#define ACC_EDGE1(e, r)                                                        \
    {                                                                          \
        float wv = __expf(lrelu(e + scd0, 0.2f));                              \
        float2 f0 = __half22float2(*(const __half2*)&r.x);                     \
        float2 f1 = __half22float2(*(const __half2*)&r.y);                     \
        acc.x += f0.x * wv; acc.y += f0.y * wv;                                \
        acc.z += f1.x * wv; acc.w += f1.y * wv;                                \
        ws += wv;                                                              \
    }

    for (int base = rs; base < re; base += 32) {
        int idx = base + lane;
        int ck = col[idx < re ? idx : re - 1];
        int cnt = min(32, re - base);
        int j = 0;
        for (; j + 4 <= cnt; j += 4) {
            int s0 = __shfl_sync(0xffffffffu, ck, j + 0);
            int s1 = __shfl_sync(0xffffffffu, ck, j + 1);
            int s2 = __shfl_sync(0xffffffffu, ck, j + 2);
            int s3 = __shfl_sync(0xffffffffu, ck, j + 3);
            float e0 = scs[s0], e1 = scs[s1], e2 = scs[s2], e3 = scs[s3];
            uint2 r0 = hu[(size_t)s0 * 32 + lane];
            uint2 r1 = hu[(size_t)s1 * 32 + lane];
            uint2 r2 = hu[(size_t)s2 * 32 + lane];
            uint2 r3 = hu[(size_t)s3 * 32 + lane];
            ACC_EDGE1(e0, r0)
            ACC_EDGE1(e1, r1)
            ACC_EDGE1(e2, r2)
            ACC_EDGE1(e3, r3)
        }
        for (; j < cnt; j++) {
            int s = __shfl_sync(0xffffffffu, ck, j);
            float e = scs[s];
            uint2 r = hu[(size_t)s * 32 + lane];
            ACC_EDGE1(e, r)
        }
    }
#undef ACC_EDGE1

    float inv = 1.f / ws;
    const float inv_bn = rsqrtf(1.0f + 1e-5f);
    float4 bA = ((const float4*)bias)[lane];
    float4 gA = ((const float4*)bn_g)[lane];
    float4 cA = ((const float4*)bn_b)[lane];
    float4 o;
    o.x = lrelu(acc.x * inv + bA.x, 0.01f) * (gA.x * inv_bn) + cA.x;
    o.y = lrelu(acc.y * inv + bA.y, 0.01f) * (gA.y * inv_bn) + cA.y;
    o.z = lrelu(acc.z * inv + bA.z, 0.01f) * (gA.z * inv_bn) + cA.z;
    o.w = lrelu(acc.w * inv + bA.w, 0.01f) * (gA.w * inv_bn) + cA.w;
    ((float4*)xout)[(size_t)node * 32 + lane] = o;
}

// ---------------- GCN (fp16 gather, 4-edge batched) ---------------------------
__global__ void k_gcn_agg(const __half* __restrict__ h, const float* __restrict__ dis,
                          const float* __restrict__ bg,
                          const int* __restrict__ rowstart, const int* __restrict__ col,
                          float* __restrict__ xout, int n) {
    int node = blockIdx.x * 8 + (threadIdx.x >> 5);
    int lane = threadIdx.x & 31;
    if (node >= n) return;
    int rs = rowstart[node], re = rowstart[node + 1];
    float wi = dis[node];
    const __half2* h2 = (const __half2*)h;      // row = 32 half2
    float2 acc = make_float2(0.f, 0.f);

    for (int base = rs; base < re; base += 32) {
        int idx = base + lane;
        int ck = col[idx < re ? idx : re - 1];
        int cnt = min(32, re - base);
        int j = 0;
        for (; j + 4 <= cnt; j += 4) {
            int s0 = __shfl_sync(0xffffffffu, ck, j + 0);
            int s1 = __shfl_sync(0xffffffffu, ck, j + 1);
            int s2 = __shfl_sync(0xffffffffu, ck, j + 2);
            int s3 = __shfl_sync(0xffffffffu, ck, j + 3);
            float w0 = dis[s0] * wi, w1 = dis[s1] * wi;
            float w2 = dis[s2] * wi, w3 = dis[s3] * wi;
            float2 v0 = __half22float2(h2[(size_t)s0 * 32 + lane]);
            float2 v1 = __half22float2(h2[(size_t)s1 * 32 + lane]);
            float2 v2 = __half22float2(h2[(size_t)s2 * 32 + lane]);
            float2 v3 = __half22float2(h2[(size_t)s3 * 32 + lane]);
            acc.x += v0.x * w0; acc.y += v0.y * w0;
            acc.x += v1.x * w1; acc.y += v1.y * w1;
            acc.x += v2.x * w2; acc.y += v2.y * w2;
            acc.x += v3.x * w3; acc.y += v3.y * w3;
        }
        for (; j < cnt; j++) {
            int s = __shfl_sync(0xffffffffu, ck, j);
            float w = dis[s] * wi;
            float2 v = __half22float2(h2[(size_t)s * 32 + lane]);
            acc.x += v.x * w; acc.y += v.y * w;
        }
    }
    float2 bgv = ((const float2*)bg)[lane];
    float2 o;
    o.x = lrelu(acc.x + bgv.x, 0.01f);
    o.y = lrelu(acc.y + bgv.y, 0.01f);
    ((float2*)xout)[(size_t)node * 32 + lane] = o;
}

// ---------------- pooling + MLP ----------------------------------------------
__global__ void k_zero2(float* p, int n, float* q, int m) {
    int i = blockIdx.x * blockDim.x + threadIdx.x;
    if (i < n) p[i] = 0.f;
    if (i < m) q[i] = 0.f;
}

__global__ void k_pool(const float* __restrict__ x3, const int* __restrict__ batch,
                       float* pool, float* cnt, int n) {
    int node = blockIdx.x * 8 + (threadIdx.x >> 5);
    int lane = threadIdx.x & 31;
    if (node >= n) return;
    int b = batch[node];
    float2 v = ((const float2*)x3)[(size_t)node * 32 + lane];
    atomicAdd(&pool[b * D3 + 2 * lane], v.x);
    atomicAdd(&pool[b * D3 + 2 * lane + 1], v.y);
    if (lane == 0) atomicAdd(&cnt[b], 1.f);
}

__global__ void __launch_bounds__(128) k_mlp(const float* __restrict__ pool,
                                             const float* __restrict__ cnt,
                                             const float* __restrict__ l1W,
                                             const float* __restrict__ l1b,
                                             const float* __restrict__ g3,
                                             const float* __restrict__ b3,
                                             const float* __restrict__ l2W,
                                             const float* __restrict__ l2b,
                                             float* __restrict__ out) {
    int b = blockIdx.x;
    int t = threadIdx.x;
    __shared__ float sp[64];
    __shared__ float sy[128];
    if (t < 64) sp[t] = pool[b * D3 + t] / fmaxf(cnt[b], 1.f);
    __syncthreads();
    float v = l1b[t];
#pragma unroll
    for (int k = 0; k < 64; k++) v += sp[k] * l1W[k * 128 + t];
    v = v * (g3[t] * rsqrtf(1.0f + 1e-5f)) + b3[t];
    v = lrelu(v, 0.01f);
    sy[t] = v;
    __syncthreads();
    if (t < NCc) {
        float o = l2b[t];
#pragma unroll
        for (int k = 0; k < 128; k++) o += sy[k] * l2W[k * NCc + t];
        out[b * NCc + t] = o;
    }
}

// ---------------- launch -----------------------------------------------------
extern "C" void kernel_launch(void* const* d_in, const int* in_sizes, int n_in,
                              void* d_out, int out_size) {
    const float* x      = (const float*)d_in[0];
    const int*   ei     = (const int*)d_in[1];
    const int*   batch  = (const int*)d_in[2];
    const float* W1     = (const float*)d_in[3];
    const float* a_src1 = (const float*)d_in[4];
    const float* a_dst1 = (const float*)d_in[5];
    const float* b1     = (const float*)d_in[6];
    const float* W2     = (const float*)d_in[7];
    const float* a_src2 = (const float*)d_in[8];
    const float* a_dst2 = (const float*)d_in[9];
    const float* b2     = (const float*)d_in[10];
    const float* Wg     = (const float*)d_in[11];
    const float* bg     = (const float*)d_in[12];
    const float* bn1g   = (const float*)d_in[13];
    const float* bn1b   = (const float*)d_in[14];
    const float* bn2g   = (const float*)d_in[15];
    const float* bn2b   = (const float*)d_in[16];
    const float* bn3g   = (const float*)d_in[17];
    const float* bn3b   = (const float*)d_in[18];
    const float* l1W    = (const float*)d_in[19];
    const float* l1b    = (const float*)d_in[20];
    const float* l2W    = (const float*)d_in[21];
    const float* l2b    = (const float*)d_in[22];
    float* out = (float*)d_out;

    int *deg, *rowstart, *cursor, *col, *partials;
    __half *h1, *h2, *h3;
    float *x1, *x2, *x3, *scs1, *scd1, *scs2, *scd2, *dis, *pool, *cnt;
    cudaGetSymbolAddress((void**)&deg, g_deg);
    cudaGetSymbolAddress((void**)&rowstart, g_rowstart);
    cudaGetSymbolAddress((void**)&cursor, g_cursor);
    cudaGetSymbolAddress((void**)&col, g_col);
    cudaGetSymbolAddress((void**)&partials, g_partials);
    cudaGetSymbolAddress((void**)&h1, g_h1);
    cudaGetSymbolAddress((void**)&x1, g_x1);
    cudaGetSymbolAddress((void**)&h2, g_h2);
    cudaGetSymbolAddress((void**)&x2, g_x2);
    cudaGetSymbolAddress((void**)&h3, g_h3);
    cudaGetSymbolAddress((void**)&x3, g_x3);
    cudaGetSymbolAddress((void**)&scs1, g_scs1);
    cudaGetSymbolAddress((void**)&scd1, g_scd1);
    cudaGetSymbolAddress((void**)&scs2, g_scs2);
    cudaGetSymbolAddress((void**)&scd2, g_scd2);
    cudaGetSymbolAddress((void**)&dis, g_dis);
    cudaGetSymbolAddress((void**)&pool, g_pool);
    cudaGetSymbolAddress((void**)&cnt, g_cnt);

    const int* src = ei;
    const int* dst = ei + Ee;

    static cudaStream_t s2 = nullptr;
    static cudaEvent_t evFork = nullptr, evJoin = nullptr;
    if (!s2) {
        cudaStreamCreateWithFlags(&s2, cudaStreamNonBlocking);
        cudaEventCreateWithFlags(&evFork, cudaEventDisableTiming);
        cudaEventCreateWithFlags(&evJoin, cudaEventDisableTiming);
    }

    // ---- fork: CSR build on s2, GEMM1+scores on main stream ----
    cudaEventRecord(evFork, 0);
    cudaStreamWaitEvent(s2, evFork, 0);

    k_init_deg<<<(Nn + 255) / 256, 256, 0, s2>>>(deg, Nn);
    k_deg_scatter<<<(Ee + 255) / 256, 256, 0, s2>>>(dst, deg, Ee);
    k_scan_block<<<NB_SCAN, 1024, 0, s2>>>(deg, rowstart, partials, Nn);
    k_scan_partials<<<1, 64, 0, s2>>>(partials, rowstart, NB_SCAN, Nn);
    k_scan_finalize<<<NB_SCAN, 1024, 0, s2>>>(deg, rowstart, partials, Nn);
    k_fill_self<<<(Nn + 255) / 256, 256, 0, s2>>>(rowstart, col, cursor, deg, dis, Nn);
    k_scatter_edges<<<(Ee + 255) / 256, 256, 0, s2>>>(src, dst, cursor, col, Ee);
    k_zero2<<<(Bb * D3 + 255) / 256, 256, 0, s2>>>(pool, Bb * D3, cnt, Bb);
    cudaEventRecord(evJoin, s2);

    k_gemm_tc<<<dim3((Nn + 127) / 128, D1 / 64), 256>>>(x, W1, h1, Nn, D1, Fdim);
    k_scores4<<<(Nn + 7) / 8, 256>>>(h1, a_src1, a_dst1, scs1, scd1, Nn);

    cudaStreamWaitEvent(0, evJoin, 0);

    // ---- GAT layer 1 aggregation ----
    k_gat_agg4<<<(Nn + 7) / 8, 256>>>(h1, scs1, scd1, b1, bn1g, bn1b,
                                      rowstart, col, x1, Nn);

    // ---- GAT layer 2: 256 -> 1 head x 128 ----
    k_gemm_tc<<<dim3((Nn + 127) / 128, D2 / 64), 256>>>(x1, W2, h2, Nn, D2, D1);
    k_scores1<<<(Nn + 7) / 8, 256>>>(h2, a_src2, a_dst2, scs2, scd2, Nn);
    k_gat_agg1<<<(Nn + 7) / 8, 256>>>(h2, scs2, scd2, b2, bn2g, bn2b,
                                      rowstart, col, x2, Nn);

    // ---- GCN: 128 -> 64 ----
    k_gemm_tc<<<dim3((Nn + 127) / 128, D3 / 64), 256>>>(x2, Wg, h3, Nn, D3, D2);
    k_gcn_agg<<<(Nn + 7) / 8, 256>>>(h3, dis, bg, rowstart, col, x3, Nn);

    // ---- global mean pool + MLP head ----
    k_pool<<<(Nn + 7) / 8, 256>>>(x3, batch, pool, cnt, Nn);
    k_mlp<<<Bb, 128>>>(pool, cnt, l1W, l1b, bn3g, bn3b, l2W, l2b, out);
}

// round 7
// speedup vs baseline: 1.5571x; 1.1594x over previous
#include <cuda_runtime.h>
#include <cuda_fp16.h>
#include <math_constants.h>
#include <cstdint>

// Problem constants (fixed by reference setup_inputs)
#define Nn   50000
#define Ee   800000
#define E2   (Ee + Nn)
#define Fdim 128
#define D1   256   // 4 heads x 64
#define D2   128   // 1 head x 128
#define D3   64    // GCN out
#define Bb   512
#define NCc  10
#define NB_SCAN ((Nn + 1023) / 1024)

typedef unsigned int u32;

// ---------------- scratch (device globals; no allocation allowed) -----------
__device__ __align__(16) int   g_deg[Nn];
__device__ __align__(16) int   g_rowstart[Nn + 1];
__device__ __align__(16) int   g_cursor[Nn];
__device__ __align__(16) int   g_col[E2];
__device__ __align__(16) int   g_partials[NB_SCAN + 1];

__device__ __align__(16) __half g_h1[(size_t)Nn * D1];
__device__ __align__(16) __half g_x1[(size_t)Nn * D1];
__device__ __align__(16) __half g_h2[(size_t)Nn * D2];
__device__ __align__(16) __half g_x2[(size_t)Nn * D2];
__device__ __align__(16) __half g_h3[(size_t)Nn * D3];
__device__ __align__(16) float  g_x3[(size_t)Nn * D3];
__device__ __align__(16) float  g_scs1[Nn * 4];
__device__ __align__(16) float  g_scd1[Nn * 4];
__device__ __align__(16) float  g_scs2[Nn];
__device__ __align__(16) float  g_scd2[Nn];
__device__ __align__(16) float  g_dis[Nn];
__device__ __align__(16) float  g_pool[Bb * D3];
__device__ __align__(16) float  g_cnt[Bb];

// ---------------- small helpers ---------------------------------------------
__device__ __forceinline__ float lrelu(float v, float s) { return v > 0.f ? v : s * v; }

__device__ __forceinline__ u32 pack_half2(float x, float y) {
    __half2 h = __floats2half2_rn(x, y);
    return *(u32*)&h;
}

__device__ __forceinline__ void mma_f16(float* c, const u32* a, const u32* b) {
    asm volatile(
        "mma.sync.aligned.m16n8k16.row.col.f32.f16.f16.f32 "
        "{%0,%1,%2,%3}, {%4,%5,%6,%7}, {%8,%9}, {%0,%1,%2,%3};"
        : "+f"(c[0]), "+f"(c[1]), "+f"(c[2]), "+f"(c[3])
        : "r"(a[0]), "r"(a[1]), "r"(a[2]), "r"(a[3]), "r"(b[0]), "r"(b[1]));
}

// ---------------- CSR build --------------------------------------------------
__global__ void k_init_deg(int* deg, int n) {
    int i = blockIdx.x * blockDim.x + threadIdx.x;
    if (i < n) deg[i] = 1;  // self-loop
}

__global__ void k_deg_scatter(const int* __restrict__ dst, int* deg, int e) {
    int i = blockIdx.x * blockDim.x + threadIdx.x;
    if (i < e) atomicAdd(&deg[dst[i]], 1);
}

__global__ void k_scan_block(const int* __restrict__ deg, int* __restrict__ rowstart,
                             int* __restrict__ partials, int n) {
    __shared__ int s[1024];
    int t = threadIdx.x;
    int gi = blockIdx.x * 1024 + t;
    int v = (gi < n) ? deg[gi] : 0;
    s[t] = v;
    __syncthreads();
#pragma unroll
    for (int off = 1; off < 1024; off <<= 1) {
        int xv = (t >= off) ? s[t - off] : 0;
        __syncthreads();
        s[t] += xv;
        __syncthreads();
    }
    if (gi < n) rowstart[gi] = s[t];          // block-inclusive
    if (t == 1023) partials[blockIdx.x] = s[t];
}

__global__ void k_scan_partials(int* partials, int* rowstart, int nb, int n) {
    __shared__ int wsum[2];
    int t = threadIdx.x;
    int lane = t & 31, w = t >> 5;
    int orig = (t < nb) ? partials[t] : 0;
    int v = orig;
#pragma unroll
    for (int o = 1; o < 32; o <<= 1) {
        int xv = __shfl_up_sync(0xffffffffu, v, o);
        if (lane >= o) v += xv;
    }
    if (lane == 31) wsum[w] = v;
    __syncthreads();
    if (w == 1) v += wsum[0];
    if (t < nb) partials[t] = v - orig;   // exclusive
    if (t == 63) rowstart[n] = v;         // total (= N + E)
}

__global__ void k_scan_finalize(const int* __restrict__ deg, int* __restrict__ rowstart,
                                const int* __restrict__ partials, int n) {
    int gi = blockIdx.x * 1024 + threadIdx.x;
    if (gi < n) rowstart[gi] = rowstart[gi] - deg[gi] + partials[blockIdx.x];
}

__global__ void k_fill_self(const int* __restrict__ rowstart, int* __restrict__ col,
                            int* __restrict__ cursor, const int* __restrict__ deg,
                            float* __restrict__ dis, int n) {
    int i = blockIdx.x * blockDim.x + threadIdx.x;
    if (i < n) {
        int rs = rowstart[i];
        col[rs] = i;
        cursor[i] = rs + 1;
        dis[i] = rsqrtf((float)deg[i]);
    }
}

__global__ void k_scatter_edges(const int* __restrict__ src, const int* __restrict__ dst,
                                int* cursor, int* __restrict__ col, int e) {
    int i = blockIdx.x * blockDim.x + threadIdx.x;
    if (i < e) {
        int pos = atomicAdd(&cursor[dst[i]], 1);
        col[pos] = src[i];
    }
}

// ---------------- fp16 tensor-core GEMM (A fp16, B hi+lo split) --------------
// C[M,N] = A[M,K] @ B[K,N].  BM=128, BN=64, BK=32, 256 threads (8 warps, 4x2),
// warp tile 32x32 via m16n8k16. A rounded to fp16 (inputs); B split hi+lo so
// weight precision ~2^-22. 2 MMAs per k16 chunk.
template <typename AT>
__global__ void __launch_bounds__(256) k_gemm_f16(const AT* __restrict__ A,
                                                  const float* __restrict__ B,
                                                  __half* __restrict__ C,
                                                  int M, int N, int K) {
    // u32 = 2 halves packed (k, k+1). stride 20: frag bank = 4g+t perm -> conflict-free
    __shared__ u32 As[128][20];
    __shared__ u32 Bhi[64][20];
    __shared__ u32 Blo[64][20];

    int tid = threadIdx.x;
    int bm0 = blockIdx.x * 128, bn0 = blockIdx.y * 64;
    int w = tid >> 5, lane = tid & 31;
    int wm = (w & 3) * 32, wn = (w >> 2) * 32;
    int g = lane >> 2, t = lane & 3;

    float acc[2][4][4] = {};

    for (int kt = 0; kt < K; kt += 32) {
        // ---- load A tile 128x32 ----
        if constexpr (sizeof(AT) == 4) {
            const float* Af = (const float*)A;
            int r = tid >> 1, cb = (tid & 1) * 16;   // 16 floats per thread
            bool ok = (bm0 + r) < M;
#pragma unroll
            for (int i = 0; i < 4; i++) {
                float4 v = make_float4(0.f, 0.f, 0.f, 0.f);
                if (ok) v = *(const float4*)(Af + (size_t)(bm0 + r) * K + kt + cb + 4 * i);
                As[r][(cb >> 1) + 2 * i]     = pack_half2(v.x, v.y);
                As[r][(cb >> 1) + 2 * i + 1] = pack_half2(v.z, v.w);
            }
        } else {
            const __half* Ah = (const __half*)A;
#pragma unroll
            for (int it = 0; it < 2; it++) {
                int idx = tid + it * 256;
                int r = idx >> 2, ch = (idx & 3) * 8;   // 8 halves per thread
                uint4 v = make_uint4(0u, 0u, 0u, 0u);
                if (bm0 + r < M) v = *(const uint4*)(Ah + (size_t)(bm0 + r) * K + kt + ch);
                As[r][(ch >> 1) + 0] = v.x; As[r][(ch >> 1) + 1] = v.y;
                As[r][(ch >> 1) + 2] = v.z; As[r][(ch >> 1) + 3] = v.w;
            }
        }
        // ---- load B tile 32x64, pack k-pairs per n column, hi+lo split ----
        {
            int r2 = tid >> 4;            // k-pair index 0..15
            int c4 = (tid & 15) * 4;      // n column
            float4 v0 = *(const float4*)(B + (size_t)(kt + 2 * r2) * N + bn0 + c4);
            float4 v1 = *(const float4*)(B + (size_t)(kt + 2 * r2 + 1) * N + bn0 + c4);
            const float* p0 = &v0.x;
            const float* p1 = &v1.x;
#pragma unroll
            for (int i = 0; i < 4; i++) {
                float x0 = p0[i], x1 = p1[i];
                __half h0 = __float2half_rn(x0), h1 = __float2half_rn(x1);
                __half2 hh = __halves2half2(h0, h1);
                Bhi[c4 + i][r2] = *(u32*)&hh;
                Blo[c4 + i][r2] = pack_half2(x0 - __half2float(h0), x1 - __half2float(h1));
            }
        }
        __syncthreads();

#pragma unroll
        for (int kk = 0; kk < 2; kk++) {
            int kb = kk * 8;
            u32 af[2][4], bh[4][2], bl[4][2];
#pragma unroll
            for (int mt = 0; mt < 2; mt++) {
                int r = wm + mt * 16 + g;
                af[mt][0] = As[r][kb + t];       af[mt][1] = As[r + 8][kb + t];
                af[mt][2] = As[r][kb + 4 + t];   af[mt][3] = As[r + 8][kb + 4 + t];
            }
#pragma unroll
            for (int nt = 0; nt < 4; nt++) {
                int c = wn + nt * 8 + g;
                bh[nt][0] = Bhi[c][kb + t]; bh[nt][1] = Bhi[c][kb + 4 + t];
                bl[nt][0] = Blo[c][kb + t]; bl[nt][1] = Blo[c][kb + 4 + t];
            }
#pragma unroll
            for (int mt = 0; mt < 2; mt++)
#pragma unroll
                for (int nt = 0; nt < 4; nt++) {
                    mma_f16(acc[mt][nt], af[mt], bh[nt]);
                    mma_f16(acc[mt][nt], af[mt], bl[nt]);
                }
        }
        __syncthreads();
    }

    // ---- store fp16 ----
#pragma unroll
    for (int mt = 0; mt < 2; mt++) {
        int r0 = bm0 + wm + mt * 16 + g;
#pragma unroll
        for (int nt = 0; nt < 4; nt++) {
            int c = bn0 + wn + nt * 8 + 2 * t;
            if (r0 < M)
                *(__half2*)(C + (size_t)r0 * N + c) =
                    __floats2half2_rn(acc[mt][nt][0], acc[mt][nt][1]);
            if (r0 + 8 < M)
                *(__half2*)(C + (size_t)(r0 + 8) * N + c) =
                    __floats2half2_rn(acc[mt][nt][2], acc[mt][nt][3]);
        }
    }
}

// ---------------- GAT attention scores (fp16 h) -------------------------------
__global__ void k_scores4(const __half* __restrict__ h, const float* __restrict__ a_src,
                          const float* __restrict__ a_dst, float* __restrict__ scs,
                          float* __restrict__ scd, int n) {
    int node = blockIdx.x * 8 + (threadIdx.x >> 5);
    int lane = threadIdx.x & 31;
    if (node >= n) return;
#pragma unroll
    for (int hd = 0; hd < 4; hd++) {
        float2 hv = __half22float2(*(const __half2*)(h + (size_t)node * D1 + hd * 64 + 2 * lane));
        float2 as = *(const float2*)(a_src + hd * 64 + 2 * lane);
        float2 ad = *(const float2*)(a_dst + hd * 64 + 2 * lane);
        float ps = hv.x * as.x + hv.y * as.y;
        float pd = hv.x * ad.x + hv.y * ad.y;
#pragma unroll
        for (int off = 16; off; off >>= 1) {
            ps += __shfl_xor_sync(0xffffffffu, ps, off);
            pd += __shfl_xor_sync(0xffffffffu, pd, off);
        }
        if (lane == 0) { scs[node * 4 + hd] = ps; scd[node * 4 + hd] = pd; }
    }
}

__global__ void k_scores1(const __half* __restrict__ h, const float* __restrict__ a_src,
                          const float* __restrict__ a_dst, float* __restrict__ scs,
                          float* __restrict__ scd, int n) {
    int node = blockIdx.x * 8 + (threadIdx.x >> 5);
    int lane = threadIdx.x & 31;
    if (node >= n) return;
    uint2 raw = *(const uint2*)(h + (size_t)node * D2 + 4 * lane);
    float2 f0 = __half22float2(*(const __half2*)&raw.x);
    float2 f1 = __half22float2(*(const __half2*)&raw.y);
    float4 as = *(const float4*)(a_src + 4 * lane);
    float4 ad = *(const float4*)(a_dst + 4 * lane);
    float ps = f0.x * as.x + f0.y * as.y + f1.x * as.z + f1.y * as.w;
    float pd = f0.x * ad.x + f0.y * ad.y + f1.x * ad.z + f1.y * ad.w;
#pragma unroll
    for (int off = 16; off; off >>= 1) {
        ps += __shfl_xor_sync(0xffffffffu, ps, off);
        pd += __shfl_xor_sync(0xffffffffu, pd, off);
    }
    if (lane == 0) { scs[node] = ps; scd[node] = pd; }
}

// ---------------- GAT aggregation: single pass, 4-edge batched ---------------
__global__ void k_gat_agg4(const __half* __restrict__ h, const float* __restrict__ scs,
                           const float* __restrict__ scd_arr,
                           const float* __restrict__ bias,
                           const float* __restrict__ bn_g, const float* __restrict__ bn_b,
                           const int* __restrict__ rowstart, const int* __restrict__ col,
                           __half* __restrict__ xout, int n) {
    int node = blockIdx.x * 8 + (threadIdx.x >> 5);
    int lane = threadIdx.x & 31;
    if (node >= n) return;
    int rs = rowstart[node], re = rowstart[node + 1];

    float4 scd4 = *(const float4*)(scd_arr + node * 4);
    bool lo = lane < 16;
    float scdA = lo ? scd4.x : scd4.y;
    float scdB = lo ? scd4.z : scd4.w;

    const uint2* hu = (const uint2*)h;          // 4 halves per uint2; row = 64 uint2
    const float4* scs4 = (const float4*)scs;

    float4 accA = make_float4(0.f, 0.f, 0.f, 0.f);
    float4 accB = make_float4(0.f, 0.f, 0.f, 0.f);
    float wsA = 0.f, wsB = 0.f;

#define ACC_EDGE4(sv, ra, rb)                                                  \
    {                                                                          \
        float wa = __expf(lrelu((lo ? sv.x : sv.y) + scdA, 0.2f));             \
        float wb = __expf(lrelu((lo ? sv.z : sv.w) + scdB, 0.2f));             \
        float2 a0 = __half22float2(*(const __half2*)&ra.x);                    \
        float2 a1 = __half22float2(*(const __half2*)&ra.y);                    \
        float2 b0 = __half22float2(*(const __half2*)&rb.x);                    \
        float2 b1 = __half22float2(*(const __half2*)&rb.y);                    \
        accA.x += a0.x * wa; accA.y += a0.y * wa;                              \
        accA.z += a1.x * wa; accA.w += a1.y * wa;                              \
        accB.x += b0.x * wb; accB.y += b0.y * wb;                              \
        accB.z += b1.x * wb; accB.w += b1.y * wb;                              \
        wsA += wa; wsB += wb;                                                  \
    }

    for (int base = rs; base < re; base += 32) {
        int idx = base + lane;
        int ck = col[idx < re ? idx : re - 1];
        int cnt = min(32, re - base);
        int j = 0;
        for (; j + 4 <= cnt; j += 4) {
            int s0 = __shfl_sync(0xffffffffu, ck, j + 0);
            int s1 = __shfl_sync(0xffffffffu, ck, j + 1);
            int s2 = __shfl_sync(0xffffffffu, ck, j + 2);
            int s3 = __shfl_sync(0xffffffffu, ck, j + 3);
            float4 sv0 = scs4[s0], sv1 = scs4[s1], sv2 = scs4[s2], sv3 = scs4[s3];
            uint2 ra0 = hu[(size_t)s0 * 64 + lane], rb0 = hu[(size_t)s0 * 64 + 32 + lane];
            uint2 ra1 = hu[(size_t)s1 * 64 + lane], rb1 = hu[(size_t)s1 * 64 + 32 + lane];
            uint2 ra2 = hu[(size_t)s2 * 64 + lane], rb2 = hu[(size_t)s2 * 64 + 32 + lane];
            uint2 ra3 = hu[(size_t)s3 * 64 + lane], rb3 = hu[(size_t)s3 * 64 + 32 + lane];
            ACC_EDGE4(sv0, ra0, rb0)
            ACC_EDGE4(sv1, ra1, rb1)
            ACC_EDGE4(sv2, ra2, rb2)
            ACC_EDGE4(sv3, ra3, rb3)
        }
        for (; j < cnt; j++) {
            int s = __shfl_sync(0xffffffffu, ck, j);
            float4 sv = scs4[s];
            uint2 ra = hu[(size_t)s * 64 + lane], rb = hu[(size_t)s * 64 + 32 + lane];
            ACC_EDGE4(sv, ra, rb)
        }
    }
#undef ACC_EDGE4

    float ia = 1.f / wsA, ib = 1.f / wsB;
    const float inv_bn = rsqrtf(1.0f + 1e-5f);
    float4 bA = ((const float4*)bias)[lane],  bB = ((const float4*)bias)[lane + 32];
    float4 gA = ((const float4*)bn_g)[lane],  gB = ((const float4*)bn_g)[lane + 32];
    float4 cA = ((const float4*)bn_b)[lane],  cB = ((const float4*)bn_b)[lane + 32];
    float4 oA, oB;
    oA.x = lrelu(accA.x * ia + bA.x, 0.01f) * (gA.x * inv_bn) + cA.x;
    oA.y = lrelu(accA.y * ia + bA.y, 0.01f) * (gA.y * inv_bn) + cA.y;
    oA.z = lrelu(accA.z * ia + bA.z, 0.01f) * (gA.z * inv_bn) + cA.z;
    oA.w = lrelu(accA.w * ia + bA.w, 0.01f) * (gA.w * inv_bn) + cA.w;
    oB.x = lrelu(accB.x * ib + bB.x, 0.01f) * (gB.x * inv_bn) + cB.x;
    oB.y = lrelu(accB.y * ib + bB.y, 0.01f) * (gB.y * inv_bn) + cB.y;
    oB.z = lrelu(accB.z * ib + bB.z, 0.01f) * (gB.z * inv_bn) + cB.z;
    oB.w = lrelu(accB.w * ib + bB.w, 0.01f) * (gB.w * inv_bn) + cB.w;
    uint2 pA, pB;
    pA.x = pack_half2(oA.x, oA.y); pA.y = pack_half2(oA.z, oA.w);
    pB.x = pack_half2(oB.x, oB.y); pB.y = pack_half2(oB.z, oB.w);
    ((uint2*)xout)[(size_t)node * 64 + lane]      = pA;
    ((uint2*)xout)[(size_t)node * 64 + 32 + lane] = pB;
}

// 1 head x 128ch, fp16 gather, 4-edge batched, fp16 output.
__global__ void k_gat_agg1(const __half* __restrict__ h, const float* __restrict__ scs,
                           const float* __restrict__ scd_arr,
                           const float* __restrict__ bias,
                           const float* __restrict__ bn_g, const float* __restrict__ bn_b,
                           const int* __restrict__ rowstart, const int* __restrict__ col,
                           __half* __restrict__ xout, int n) {
    int node = blockIdx.x * 8 + (threadIdx.x >> 5);
    int lane = threadIdx.x & 31;
    if (node >= n) return;
    int rs = rowstart[node], re = rowstart[node + 1];

    float scd0 = scd_arr[node];
    const uint2* hu = (const uint2*)h;          // row = 32 uint2

    float4 acc = make_float4(0.f, 0.f, 0.f, 0.f);
    float ws = 0.f;

#define ACC_EDGE1(e, r)                                                        \
    {                                                                          \
        float wv = __expf(lrelu(e + scd0, 0.2f));                              \
        float2 f0 = __half22float2(*(const __half2*)&r.x);                     \
        float2 f1 = __half22float2(*(const __half2*)&r.y);                     \
        acc.x += f0.x * wv; acc.y += f0.y * wv;                                \
        acc.z += f1.x * wv; acc.w += f1.y * wv;                                \
        ws += wv;                                                              \
    }

    for (int base = rs; base < re; base += 32) {
        int idx = base + lane;
        int ck = col[idx < re ? idx : re - 1];
        int cnt = min(32, re - base);
        int j = 0;
        for (; j + 4 <= cnt; j += 4) {
            int s0 = __shfl_sync(0xffffffffu, ck, j + 0);
            int s1 = __shfl_sync(0xffffffffu, ck, j + 1);
            int s2 = __shfl_sync(0xffffffffu, ck, j + 2);
            int s3 = __shfl_sync(0xffffffffu, ck, j + 3);
            float e0 = scs[s0], e1 = scs[s1], e2 = scs[s2], e3 = scs[s3];
            uint2 r0 = hu[(size_t)s0 * 32 + lane];
            uint2 r1 = hu[(size_t)s1 * 32 + lane];
            uint2 r2 = hu[(size_t)s2 * 32 + lane];
            uint2 r3 = hu[(size_t)s3 * 32 + lane];
            ACC_EDGE1(e0, r0)
            ACC_EDGE1(e1, r1)
            ACC_EDGE1(e2, r2)
            ACC_EDGE1(e3, r3)
        }
        for (; j < cnt; j++) {
            int s = __shfl_sync(0xffffffffu, ck, j);
            float e = scs[s];
            uint2 r = hu[(size_t)s * 32 + lane];
            ACC_EDGE1(e, r)
        }
    }
#undef ACC_EDGE1

    float inv = 1.f / ws;
    const float inv_bn = rsqrtf(1.0f + 1e-5f);
    float4 bA = ((const float4*)bias)[lane];
    float4 gA = ((const float4*)bn_g)[lane];
    float4 cA = ((const float4*)bn_b)[lane];
    float4 o;
    o.x = lrelu(acc.x * inv + bA.x, 0.01f) * (gA.x * inv_bn) + cA.x;
    o.y = lrelu(acc.y * inv + bA.y, 0.01f) * (gA.y * inv_bn) + cA.y;
    o.z = lrelu(acc.z * inv + bA.z, 0.01f) * (gA.z * inv_bn) + cA.z;
    o.w = lrelu(acc.w * inv + bA.w, 0.01f) * (gA.w * inv_bn) + cA.w;
    uint2 p;
    p.x = pack_half2(o.x, o.y); p.y = pack_half2(o.z, o.w);
    ((uint2*)xout)[(size_t)node * 32 + lane] = p;
}

// ---------------- GCN (fp16 gather, 4-edge batched) ---------------------------
__global__ void k_gcn_agg(const __half* __restrict__ h, const float* __restrict__ dis,
                          const float* __restrict__ bg,
                          const int* __restrict__ rowstart, const int* __restrict__ col,
                          float* __restrict__ xout, int n) {
    int node = blockIdx.x * 8 + (threadIdx.x >> 5);
    int lane = threadIdx.x & 31;
    if (node >= n) return;
    int rs = rowstart[node], re = rowstart[node + 1];
    float wi = dis[node];
    const __half2* h2 = (const __half2*)h;      // row = 32 half2
    float2 acc = make_float2(0.f, 0.f);

    for (int base = rs; base < re; base += 32) {
        int idx = base + lane;
        int ck = col[idx < re ? idx : re - 1];
        int cnt = min(32, re - base);
        int j = 0;
        for (; j + 4 <= cnt; j += 4) {
            int s0 = __shfl_sync(0xffffffffu, ck, j + 0);
            int s1 = __shfl_sync(0xffffffffu, ck, j + 1);
            int s2 = __shfl_sync(0xffffffffu, ck, j + 2);
            int s3 = __shfl_sync(0xffffffffu, ck, j + 3);
            float w0 = dis[s0] * wi, w1 = dis[s1] * wi;
            float w2 = dis[s2] * wi, w3 = dis[s3] * wi;
            float2 v0 = __half22float2(h2[(size_t)s0 * 32 + lane]);
            float2 v1 = __half22float2(h2[(size_t)s1 * 32 + lane]);
            float2 v2 = __half22float2(h2[(size_t)s2 * 32 + lane]);
            float2 v3 = __half22float2(h2[(size_t)s3 * 32 + lane]);
            acc.x += v0.x * w0; acc.y += v0.y * w0;
            acc.x += v1.x * w1; acc.y += v1.y * w1;
            acc.x += v2.x * w2; acc.y += v2.y * w2;
            acc.x += v3.x * w3; acc.y += v3.y * w3;
        }
        for (; j < cnt; j++) {
            int s = __shfl_sync(0xffffffffu, ck, j);
            float w = dis[s] * wi;
            float2 v = __half22float2(h2[(size_t)s * 32 + lane]);
            acc.x += v.x * w; acc.y += v.y * w;
        }
    }
    float2 bgv = ((const float2*)bg)[lane];
    float2 o;
    o.x = lrelu(acc.x + bgv.x, 0.01f);
    o.y = lrelu(acc.y + bgv.y, 0.01f);
    ((float2*)xout)[(size_t)node * 32 + lane] = o;
}

// ---------------- pooling + MLP ----------------------------------------------
__global__ void k_zero2(float* p, int n, float* q, int m) {
    int i = blockIdx.x * blockDim.x + threadIdx.x;
    if (i < n) p[i] = 0.f;
    if (i < m) q[i] = 0.f;
}

__global__ void k_pool(const float* __restrict__ x3, const int* __restrict__ batch,
                       float* pool, float* cnt, int n) {
    int node = blockIdx.x * 8 + (threadIdx.x >> 5);
    int lane = threadIdx.x & 31;
    if (node >= n) return;
    int b = batch[node];
    float2 v = ((const float2*)x3)[(size_t)node * 32 + lane];
    atomicAdd(&pool[b * D3 + 2 * lane], v.x);
    atomicAdd(&pool[b * D3 + 2 * lane + 1], v.y);
    if (lane == 0) atomicAdd(&cnt[b], 1.f);
}

__global__ void __launch_bounds__(128) k_mlp(const float* __restrict__ pool,
                                             const float* __restrict__ cnt,
                                             const float* __restrict__ l1W,
                                             const float* __restrict__ l1b,
                                             const float* __restrict__ g3,
                                             const float* __restrict__ b3,
                                             const float* __restrict__ l2W,
                                             const float* __restrict__ l2b,
                                             float* __restrict__ out) {
    int b = blockIdx.x;
    int t = threadIdx.x;
    __shared__ float sp[64];
    __shared__ float sy[128];
    if (t < 64) sp[t] = pool[b * D3 + t] / fmaxf(cnt[b], 1.f);
    __syncthreads();
    float v = l1b[t];
#pragma unroll
    for (int k = 0; k < 64; k++) v += sp[k] * l1W[k * 128 + t];
    v = v * (g3[t] * rsqrtf(1.0f + 1e-5f)) + b3[t];
    v = lrelu(v, 0.01f);
    sy[t] = v;
    __syncthreads();
    if (t < NCc) {
        float o = l2b[t];
#pragma unroll
        for (int k = 0; k < 128; k++) o += sy[k] * l2W[k * NCc + t];
        out[b * NCc + t] = o;
    }
}

// ---------------- launch -----------------------------------------------------
extern "C" void kernel_launch(void* const* d_in, const int* in_sizes, int n_in,
                              void* d_out, int out_size) {
    const float* x      = (const float*)d_in[0];
    const int*   ei     = (const int*)d_in[1];
    const int*   batch  = (const int*)d_in[2];
    const float* W1     = (const float*)d_in[3];
    const float* a_src1 = (const float*)d_in[4];
    const float* a_dst1 = (const float*)d_in[5];
    const float* b1     = (const float*)d_in[6];
    const float* W2     = (const float*)d_in[7];
    const float* a_src2 = (const float*)d_in[8];
    const float* a_dst2 = (const float*)d_in[9];
    const float* b2     = (const float*)d_in[10];
    const float* Wg     = (const float*)d_in[11];
    const float* bg     = (const float*)d_in[12];
    const float* bn1g   = (const float*)d_in[13];
    const float* bn1b   = (const float*)d_in[14];
    const float* bn2g   = (const float*)d_in[15];
    const float* bn2b   = (const float*)d_in[16];
    const float* bn3g   = (const float*)d_in[17];
    const float* bn3b   = (const float*)d_in[18];
    const float* l1W    = (const float*)d_in[19];
    const float* l1b    = (const float*)d_in[20];
    const float* l2W    = (const float*)d_in[21];
    const float* l2b    = (const float*)d_in[22];
    float* out = (float*)d_out;

    int *deg, *rowstart, *cursor, *col, *partials;
    __half *h1, *h2, *h3, *x1, *x2;
    float *x3, *scs1, *scd1, *scs2, *scd2, *dis, *pool, *cnt;
    cudaGetSymbolAddress((void**)&deg, g_deg);
    cudaGetSymbolAddress((void**)&rowstart, g_rowstart);
    cudaGetSymbolAddress((void**)&cursor, g_cursor);
    cudaGetSymbolAddress((void**)&col, g_col);
    cudaGetSymbolAddress((void**)&partials, g_partials);
    cudaGetSymbolAddress((void**)&h1, g_h1);
    cudaGetSymbolAddress((void**)&x1, g_x1);
    cudaGetSymbolAddress((void**)&h2, g_h2);
    cudaGetSymbolAddress((void**)&x2, g_x2);
    cudaGetSymbolAddress((void**)&h3, g_h3);
    cudaGetSymbolAddress((void**)&x3, g_x3);
    cudaGetSymbolAddress((void**)&scs1, g_scs1);
    cudaGetSymbolAddress((void**)&scd1, g_scd1);
    cudaGetSymbolAddress((void**)&scs2, g_scs2);
    cudaGetSymbolAddress((void**)&scd2, g_scd2);
    cudaGetSymbolAddress((void**)&dis, g_dis);
    cudaGetSymbolAddress((void**)&pool, g_pool);
    cudaGetSymbolAddress((void**)&cnt, g_cnt);

    const int* src = ei;
    const int* dst = ei + Ee;

    static cudaStream_t s2 = nullptr;
    static cudaEvent_t evFork = nullptr, evJoin = nullptr;
    if (!s2) {
        cudaStreamCreateWithFlags(&s2, cudaStreamNonBlocking);
        cudaEventCreateWithFlags(&evFork, cudaEventDisableTiming);
        cudaEventCreateWithFlags(&evJoin, cudaEventDisableTiming);
    }

    // ---- fork: CSR build on s2, GEMM1+scores on main stream ----
    cudaEventRecord(evFork, 0);
    cudaStreamWaitEvent(s2, evFork, 0);

    k_init_deg<<<(Nn + 255) / 256, 256, 0, s2>>>(deg, Nn);
    k_deg_scatter<<<(Ee + 255) / 256, 256, 0, s2>>>(dst, deg, Ee);
    k_scan_block<<<NB_SCAN, 1024, 0, s2>>>(deg, rowstart, partials, Nn);
    k_scan_partials<<<1, 64, 0, s2>>>(partials, rowstart, NB_SCAN, Nn);
    k_scan_finalize<<<NB_SCAN, 1024, 0, s2>>>(deg, rowstart, partials, Nn);
    k_fill_self<<<(Nn + 255) / 256, 256, 0, s2>>>(rowstart, col, cursor, deg, dis, Nn);
    k_scatter_edges<<<(Ee + 255) / 256, 256, 0, s2>>>(src, dst, cursor, col, Ee);
    k_zero2<<<(Bb * D3 + 255) / 256, 256, 0, s2>>>(pool, Bb * D3, cnt, Bb);
    cudaEventRecord(evJoin, s2);

    k_gemm_f16<float><<<dim3((Nn + 127) / 128, D1 / 64), 256>>>(x, W1, h1, Nn, D1, Fdim);
    k_scores4<<<(Nn + 7) / 8, 256>>>(h1, a_src1, a_dst1, scs1, scd1, Nn);

    cudaStreamWaitEvent(0, evJoin, 0);

    // ---- GAT layer 1 aggregation ----
    k_gat_agg4<<<(Nn + 7) / 8, 256>>>(h1, scs1, scd1, b1, bn1g, bn1b,
                                      rowstart, col, x1, Nn);

    // ---- GAT layer 2: 256 -> 1 head x 128 ----
    k_gemm_f16<__half><<<dim3((Nn + 127) / 128, D2 / 64), 256>>>(x1, W2, h2, Nn, D2, D1);
    k_scores1<<<(Nn + 7) / 8, 256>>>(h2, a_src2, a_dst2, scs2, scd2, Nn);
    k_gat_agg1<<<(Nn + 7) / 8, 256>>>(h2, scs2, scd2, b2, bn2g, bn2b,
                                      rowstart, col, x2, Nn);

    // ---- GCN: 128 -> 64 ----
    k_gemm_f16<__half><<<dim3((Nn + 127) / 128, D3 / 64), 256>>>(x2, Wg, h3, Nn, D3, D2);
    k_gcn_agg<<<(Nn + 7) / 8, 256>>>(h3, dis, bg, rowstart, col, x3, Nn);

    // ---- global mean pool + MLP head ----
    k_pool<<<(Nn + 7) / 8, 256>>>(x3, batch, pool, cnt, Nn);
    k_mlp<<<Bb, 128>>>(pool, cnt, l1W, l1b, bn3g, bn3b, l2W, l2b, out);
}

// round 8
// speedup vs baseline: 1.7869x; 1.1476x over previous
#include <cuda_runtime.h>
#include <cuda_fp16.h>
#include <math_constants.h>
#include <cstdint>

// Problem constants (fixed by reference setup_inputs)
#define Nn   50000
#define Ee   800000
#define E2   (Ee + Nn)
#define Fdim 128
#define D1   256   // 4 heads x 64
#define D2   128   // 1 head x 128
#define D3   64    // GCN out
#define Bb   512
#define NCc  10
#define NB_SCAN ((Nn + 1023) / 1024)

typedef unsigned int u32;

// ---------------- scratch (device globals; no allocation allowed) -----------
__device__ __align__(16) int   g_deg[Nn];
__device__ __align__(16) int   g_rowstart[Nn + 1];
__device__ __align__(16) int   g_cursor[Nn];
__device__ __align__(16) int   g_col[E2];
__device__ __align__(16) int   g_partials[NB_SCAN + 1];

__device__ __align__(16) __half g_h1[(size_t)Nn * D1];
__device__ __align__(16) __half g_x1[(size_t)Nn * D1];
__device__ __align__(16) __half g_h2[(size_t)Nn * D2];
__device__ __align__(16) __half g_x2[(size_t)Nn * D2];
__device__ __align__(16) __half g_h3[(size_t)Nn * D3];
__device__ __align__(16) float  g_x3[(size_t)Nn * D3];
__device__ __align__(16) float  g_scs1[Nn * 4];
__device__ __align__(16) float  g_scd1[Nn * 4];
__device__ __align__(16) float  g_scs2[Nn];
__device__ __align__(16) float  g_scd2[Nn];
__device__ __align__(16) float  g_dis[Nn];

// ---------------- small helpers ---------------------------------------------
__device__ __forceinline__ float lrelu(float v, float s) { return v > 0.f ? v : s * v; }

__device__ __forceinline__ u32 pack_half2(float x, float y) {
    __half2 h = __floats2half2_rn(x, y);
    return *(u32*)&h;
}

__device__ __forceinline__ void mma_f16(float* c, const u32* a, const u32* b) {
    asm volatile(
        "mma.sync.aligned.m16n8k16.row.col.f32.f16.f16.f32 "
        "{%0,%1,%2,%3}, {%4,%5,%6,%7}, {%8,%9}, {%0,%1,%2,%3};"
        : "+f"(c[0]), "+f"(c[1]), "+f"(c[2]), "+f"(c[3])
        : "r"(a[0]), "r"(a[1]), "r"(a[2]), "r"(a[3]), "r"(b[0]), "r"(b[1]));
}

__device__ __forceinline__ int lbound(const int* __restrict__ a, int n, int key) {
    int l = 0, r = n;
    while (l < r) { int m = (l + r) >> 1; if (a[m] < key) l = m + 1; else r = m; }
    return l;
}

// ---------------- CSR build --------------------------------------------------
__global__ void k_init_deg(int* deg, int n) {
    int i = blockIdx.x * blockDim.x + threadIdx.x;
    if (i < n) deg[i] = 1;  // self-loop
}

__global__ void k_deg_scatter(const int* __restrict__ dst, int* deg, int e) {
    int i = blockIdx.x * blockDim.x + threadIdx.x;
    if (i < e) atomicAdd(&deg[dst[i]], 1);
}

__global__ void k_scan_block(const int* __restrict__ deg, int* __restrict__ rowstart,
                             int* __restrict__ partials, int n) {
    __shared__ int s[1024];
    int t = threadIdx.x;
    int gi = blockIdx.x * 1024 + t;
    int v = (gi < n) ? deg[gi] : 0;
    s[t] = v;
    __syncthreads();
#pragma unroll
    for (int off = 1; off < 1024; off <<= 1) {
        int xv = (t >= off) ? s[t - off] : 0;
        __syncthreads();
        s[t] += xv;
        __syncthreads();
    }
    if (gi < n) rowstart[gi] = s[t];          // block-inclusive
    if (t == 1023) partials[blockIdx.x] = s[t];
}

__global__ void k_scan_partials(int* partials, int* rowstart, int nb, int n) {
    __shared__ int wsum[2];
    int t = threadIdx.x;
    int lane = t & 31, w = t >> 5;
    int orig = (t < nb) ? partials[t] : 0;
    int v = orig;
#pragma unroll
    for (int o = 1; o < 32; o <<= 1) {
        int xv = __shfl_up_sync(0xffffffffu, v, o);
        if (lane >= o) v += xv;
    }
    if (lane == 31) wsum[w] = v;
    __syncthreads();
    if (w == 1) v += wsum[0];
    if (t < nb) partials[t] = v - orig;   // exclusive
    if (t == 63) rowstart[n] = v;         // total (= N + E)
}

__global__ void k_scan_finalize(const int* __restrict__ deg, int* __restrict__ rowstart,
                                const int* __restrict__ partials, int n) {
    int gi = blockIdx.x * 1024 + threadIdx.x;
    if (gi < n) rowstart[gi] = rowstart[gi] - deg[gi] + partials[blockIdx.x];
}

__global__ void k_fill_self(const int* __restrict__ rowstart, int* __restrict__ col,
                            int* __restrict__ cursor, const int* __restrict__ deg,
                            float* __restrict__ dis, int n) {
    int i = blockIdx.x * blockDim.x + threadIdx.x;
    if (i < n) {
        int rs = rowstart[i];
        col[rs] = i;
        cursor[i] = rs + 1;
        dis[i] = rsqrtf((float)deg[i]);
    }
}

__global__ void k_scatter_edges(const int* __restrict__ src, const int* __restrict__ dst,
                                int* cursor, int* __restrict__ col, int e) {
    int i = blockIdx.x * blockDim.x + threadIdx.x;
    if (i < e) {
        int pos = atomicAdd(&cursor[dst[i]], 1);
        col[pos] = src[i];
    }
}

// ---------------- fp16 tensor-core GEMM --------------------------------------
// C[M,N] = A[M,K] @ B[K,N].  BM=128, BN=64, BK=32, 256 threads (8 warps, 4x2),
// warp tile 32x32 via m16n8k16. A and B rounded to fp16, fp32 accumulate.
template <typename AT>
__global__ void __launch_bounds__(256) k_gemm_f16(const AT* __restrict__ A,
                                                  const float* __restrict__ B,
                                                  __half* __restrict__ C,
                                                  int M, int N, int K) {
    // u32 = 2 halves packed (k, k+1). stride 20: frag bank = 4g+t perm -> conflict-free
    __shared__ u32 As[128][20];
    __shared__ u32 Bhi[64][20];

    int tid = threadIdx.x;
    int bm0 = blockIdx.x * 128, bn0 = blockIdx.y * 64;
    int w = tid >> 5, lane = tid & 31;
    int wm = (w & 3) * 32, wn = (w >> 2) * 32;
    int g = lane >> 2, t = lane & 3;

    float acc[2][4][4] = {};

    for (int kt = 0; kt < K; kt += 32) {
        // ---- load A tile 128x32 ----
        if constexpr (sizeof(AT) == 4) {
            const float* Af = (const float*)A;
            int r = tid >> 1, cb = (tid & 1) * 16;   // 16 floats per thread
            bool ok = (bm0 + r) < M;
#pragma unroll
            for (int i = 0; i < 4; i++) {
                float4 v = make_float4(0.f, 0.f, 0.f, 0.f);
                if (ok) v = *(const float4*)(Af + (size_t)(bm0 + r) * K + kt + cb + 4 * i);
                As[r][(cb >> 1) + 2 * i]     = pack_half2(v.x, v.y);
                As[r][(cb >> 1) + 2 * i + 1] = pack_half2(v.z, v.w);
            }
        } else {
            const __half* Ah = (const __half*)A;
#pragma unroll
            for (int it = 0; it < 2; it++) {
                int idx = tid + it * 256;
                int r = idx >> 2, ch = (idx & 3) * 8;   // 8 halves per thread
                uint4 v = make_uint4(0u, 0u, 0u, 0u);
                if (bm0 + r < M) v = *(const uint4*)(Ah + (size_t)(bm0 + r) * K + kt + ch);
                As[r][(ch >> 1) + 0] = v.x; As[r][(ch >> 1) + 1] = v.y;
                As[r][(ch >> 1) + 2] = v.z; As[r][(ch >> 1) + 3] = v.w;
            }
        }
        // ---- load B tile 32x64, pack k-pairs per n column ----
        {
            int r2 = tid >> 4;            // k-pair index 0..15
            int c4 = (tid & 15) * 4;      // n column
            float4 v0 = *(const float4*)(B + (size_t)(kt + 2 * r2) * N + bn0 + c4);
            float4 v1 = *(const float4*)(B + (size_t)(kt + 2 * r2 + 1) * N + bn0 + c4);
            const float* p0 = &v0.x;
            const float* p1 = &v1.x;
#pragma unroll
            for (int i = 0; i < 4; i++)
                Bhi[c4 + i][r2] = pack_half2(p0[i], p1[i]);
        }
        __syncthreads();

#pragma unroll
        for (int kk = 0; kk < 2; kk++) {
            int kb = kk * 8;
            u32 af[2][4], bh[4][2];
#pragma unroll
            for (int mt = 0; mt < 2; mt++) {
                int r = wm + mt * 16 + g;
                af[mt][0] = As[r][kb + t];       af[mt][1] = As[r + 8][kb + t];
                af[mt][2] = As[r][kb + 4 + t];   af[mt][3] = As[r + 8][kb + 4 + t];
            }
#pragma unroll
            for (int nt = 0; nt < 4; nt++) {
                int c = wn + nt * 8 + g;
                bh[nt][0] = Bhi[c][kb + t]; bh[nt][1] = Bhi[c][kb + 4 + t];
            }
#pragma unroll
            for (int mt = 0; mt < 2; mt++)
#pragma unroll
                for (int nt = 0; nt < 4; nt++)
                    mma_f16(acc[mt][nt], af[mt], bh[nt]);
        }
        __syncthreads();
    }

    // ---- store fp16 ----
#pragma unroll
    for (int mt = 0; mt < 2; mt++) {
        int r0 = bm0 + wm + mt * 16 + g;
#pragma unroll
        for (int nt = 0; nt < 4; nt++) {
            int c = bn0 + wn + nt * 8 + 2 * t;
            if (r0 < M)
                *(__half2*)(C + (size_t)r0 * N + c) =
                    __floats2half2_rn(acc[mt][nt][0], acc[mt][nt][1]);
            if (r0 + 8 < M)
                *(__half2*)(C + (size_t)(r0 + 8) * N + c) =
                    __floats2half2_rn(acc[mt][nt][2], acc[mt][nt][3]);
        }
    }
}

// ---------------- GAT attention scores (fp16 h) -------------------------------
__global__ void k_scores4(const __half* __restrict__ h, const float* __restrict__ a_src,
                          const float* __restrict__ a_dst, float* __restrict__ scs,
                          float* __restrict__ scd, int n) {
    int node = blockIdx.x * 8 + (threadIdx.x >> 5);
    int lane = threadIdx.x & 31;
    if (node >= n) return;
#pragma unroll
    for (int hd = 0; hd < 4; hd++) {
        float2 hv = __half22float2(*(const __half2*)(h + (size_t)node * D1 + hd * 64 + 2 * lane));
        float2 as = *(const float2*)(a_src + hd * 64 + 2 * lane);
        float2 ad = *(const float2*)(a_dst + hd * 64 + 2 * lane);
        float ps = hv.x * as.x + hv.y * as.y;
        float pd = hv.x * ad.x + hv.y * ad.y;
#pragma unroll
        for (int off = 16; off; off >>= 1) {
            ps += __shfl_xor_sync(0xffffffffu, ps, off);
            pd += __shfl_xor_sync(0xffffffffu, pd, off);
        }
        if (lane == 0) { scs[node * 4 + hd] = ps; scd[node * 4 + hd] = pd; }
    }
}

__global__ void k_scores1(const __half* __restrict__ h, const float* __restrict__ a_src,
                          const float* __restrict__ a_dst, float* __restrict__ scs,
                          float* __restrict__ scd, int n) {
    int node = blockIdx.x * 8 + (threadIdx.x >> 5);
    int lane = threadIdx.x & 31;
    if (node >= n) return;
    uint2 raw = *(const uint2*)(h + (size_t)node * D2 + 4 * lane);
    float2 f0 = __half22float2(*(const __half2*)&raw.x);
    float2 f1 = __half22float2(*(const __half2*)&raw.y);
    float4 as = *(const float4*)(a_src + 4 * lane);
    float4 ad = *(const float4*)(a_dst + 4 * lane);
    float ps = f0.x * as.x + f0.y * as.y + f1.x * as.z + f1.y * as.w;
    float pd = f0.x * ad.x + f0.y * ad.y + f1.x * ad.z + f1.y * ad.w;
#pragma unroll
    for (int off = 16; off; off >>= 1) {
        ps += __shfl_xor_sync(0xffffffffu, ps, off);
        pd += __shfl_xor_sync(0xffffffffu, pd, off);
    }
    if (lane == 0) { scs[node] = ps; scd[node] = pd; }
}

// ---------------- GAT aggregation: single pass, 4-edge batched ---------------
__global__ void k_gat_agg4(const __half* __restrict__ h, const float* __restrict__ scs,
                           const float* __restrict__ scd_arr,
                           const float* __restrict__ bias,
                           const float* __restrict__ bn_g, const float* __restrict__ bn_b,
                           const int* __restrict__ rowstart, const int* __restrict__ col,
                           __half* __restrict__ xout, int n) {
    int node = blockIdx.x * 8 + (threadIdx.x >> 5);
    int lane = threadIdx.x & 31;
    if (node >= n) return;
    int rs = rowstart[node], re = rowstart[node + 1];

    float4 scd4 = *(const float4*)(scd_arr + node * 4);
    bool lo = lane < 16;
    float scdA = lo ? scd4.x : scd4.y;
    float scdB = lo ? scd4.z : scd4.w;

    const uint2* hu = (const uint2*)h;          // 4 halves per uint2; row = 64 uint2
    const float4* scs4 = (const float4*)scs;

    float4 accA = make_float4(0.f, 0.f, 0.f, 0.f);
    float4 accB = make_float4(0.f, 0.f, 0.f, 0.f);
    float wsA = 0.f, wsB = 0.f;

#define ACC_EDGE4(sv, ra, rb)                                                  \
    {                                                                          \
        float wa = __expf(lrelu((lo ? sv.x : sv.y) + scdA, 0.2f));             \
        float wb = __expf(lrelu((lo ? sv.z : sv.w) + scdB, 0.2f));             \
        float2 a0 = __half22float2(*(const __half2*)&ra.x);                    \
        float2 a1 = __half22float2(*(const __half2*)&ra.y);                    \
        float2 b0 = __half22float2(*(const __half2*)&rb.x);                    \
        float2 b1 = __half22float2(*(const __half2*)&rb.y);                    \
        accA.x += a0.x * wa; accA.y += a0.y * wa;                              \
        accA.z += a1.x * wa; accA.w += a1.y * wa;                              \
        accB.x += b0.x * wb; accB.y += b0.y * wb;                              \
        accB.z += b1.x * wb; accB.w += b1.y * wb;                              \
        wsA += wa; wsB += wb;                                                  \
    }

    for (int base = rs; base < re; base += 32) {
        int idx = base + lane;
        int ck = col[idx < re ? idx : re - 1];
        int cnt = min(32, re - base);
        int j = 0;
        for (; j + 4 <= cnt; j += 4) {
            int s0 = __shfl_sync(0xffffffffu, ck, j + 0);
            int s1 = __shfl_sync(0xffffffffu, ck, j + 1);
            int s2 = __shfl_sync(0xffffffffu, ck, j + 2);
            int s3 = __shfl_sync(0xffffffffu, ck, j + 3);
            float4 sv0 = scs4[s0], sv1 = scs4[s1], sv2 = scs4[s2], sv3 = scs4[s3];
            uint2 ra0 = hu[(size_t)s0 * 64 + lane], rb0 = hu[(size_t)s0 * 64 + 32 + lane];
            uint2 ra1 = hu[(size_t)s1 * 64 + lane], rb1 = hu[(size_t)s1 * 64 + 32 + lane];
            uint2 ra2 = hu[(size_t)s2 * 64 + lane], rb2 = hu[(size_t)s2 * 64 + 32 + lane];
            uint2 ra3 = hu[(size_t)s3 * 64 + lane], rb3 = hu[(size_t)s3 * 64 + 32 + lane];
            ACC_EDGE4(sv0, ra0, rb0)
            ACC_EDGE4(sv1, ra1, rb1)
            ACC_EDGE4(sv2, ra2, rb2)
            ACC_EDGE4(sv3, ra3, rb3)
        }
        for (; j < cnt; j++) {
            int s = __shfl_sync(0xffffffffu, ck, j);
            float4 sv = scs4[s];
            uint2 ra = hu[(size_t)s * 64 + lane], rb = hu[(size_t)s * 64 + 32 + lane];
            ACC_EDGE4(sv, ra, rb)
        }
    }
#undef ACC_EDGE4

    float ia = 1.f / wsA, ib = 1.f / wsB;
    const float inv_bn = rsqrtf(1.0f + 1e-5f);
    float4 bA = ((const float4*)bias)[lane],  bB = ((const float4*)bias)[lane + 32];
    float4 gA = ((const float4*)bn_g)[lane],  gB = ((const float4*)bn_g)[lane + 32];
    float4 cA = ((const float4*)bn_b)[lane],  cB = ((const float4*)bn_b)[lane + 32];
    float4 oA, oB;
    oA.x = lrelu(accA.x * ia + bA.x, 0.01f) * (gA.x * inv_bn) + cA.x;
    oA.y = lrelu(accA.y * ia + bA.y, 0.01f) * (gA.y * inv_bn) + cA.y;
    oA.z = lrelu(accA.z * ia + bA.z, 0.01f) * (gA.z * inv_bn) + cA.z;
    oA.w = lrelu(accA.w * ia + bA.w, 0.01f) * (gA.w * inv_bn) + cA.w;
    oB.x = lrelu(accB.x * ib + bB.x, 0.01f) * (gB.x * inv_bn) + cB.x;
    oB.y = lrelu(accB.y * ib + bB.y, 0.01f) * (gB.y * inv_bn) + cB.y;
    oB.z = lrelu(accB.z * ib + bB.z, 0.01f) * (gB.z * inv_bn) + cB.z;
    oB.w = lrelu(accB.w * ib + bB.w, 0.01f) * (gB.w * inv_bn) + cB.w;
    uint2 pA, pB;
    pA.x = pack_half2(oA.x, oA.y); pA.y = pack_half2(oA.z, oA.w);
    pB.x = pack_half2(oB.x, oB.y); pB.y = pack_half2(oB.z, oB.w);
    ((uint2*)xout)[(size_t)node * 64 + lane]      = pA;
    ((uint2*)xout)[(size_t)node * 64 + 32 + lane] = pB;
}

// 1 head x 128ch, fp16 gather, 4-edge batched, fp16 output.
__global__ void k_gat_agg1(const __half* __restrict__ h, const float* __restrict__ scs,
                           const float* __restrict__ scd_arr,
                           const float* __restrict__ bias,
                           const float* __restrict__ bn_g, const float* __restrict__ bn_b,
                           const int* __restrict__ rowstart, const int* __restrict__ col,
                           __half* __restrict__ xout, int n) {
    int node = blockIdx.x * 8 + (threadIdx.x >> 5);
    int lane = threadIdx.x & 31;
    if (node >= n) return;
    int rs = rowstart[node], re = rowstart[node + 1];

    float scd0 = scd_arr[node];
    const uint2* hu = (const uint2*)h;          // row = 32 uint2

    float4 acc = make_float4(0.f, 0.f, 0.f, 0.f);
    float ws = 0.f;

#define ACC_EDGE1(e, r)                                                        \
    {                                                                          \
        float wv = __expf(lrelu(e + scd0, 0.2f));                              \
        float2 f0 = __half22float2(*(const __half2*)&r.x);                     \
        float2 f1 = __half22float2(*(const __half2*)&r.y);                     \
        acc.x += f0.x * wv; acc.y += f0.y * wv;                                \
        acc.z += f1.x * wv; acc.w += f1.y * wv;                                \
        ws += wv;                                                              \
    }

    for (int base = rs; base < re; base += 32) {
        int idx = base + lane;
        int ck = col[idx < re ? idx : re - 1];
        int cnt = min(32, re - base);
        int j = 0;
        for (; j + 4 <= cnt; j += 4) {
            int s0 = __shfl_sync(0xffffffffu, ck, j + 0);
            int s1 = __shfl_sync(0xffffffffu, ck, j + 1);
            int s2 = __shfl_sync(0xffffffffu, ck, j + 2);
            int s3 = __shfl_sync(0xffffffffu, ck, j + 3);
            float e0 = scs[s0], e1 = scs[s1], e2 = scs[s2], e3 = scs[s3];
            uint2 r0 = hu[(size_t)s0 * 32 + lane];
            uint2 r1 = hu[(size_t)s1 * 32 + lane];
            uint2 r2 = hu[(size_t)s2 * 32 + lane];
            uint2 r3 = hu[(size_t)s3 * 32 + lane];
            ACC_EDGE1(e0, r0)
            ACC_EDGE1(e1, r1)
            ACC_EDGE1(e2, r2)
            ACC_EDGE1(e3, r3)
        }
        for (; j < cnt; j++) {
            int s = __shfl_sync(0xffffffffu, ck, j);
            float e = scs[s];
            uint2 r = hu[(size_t)s * 32 + lane];
            ACC_EDGE1(e, r)
        }
    }
#undef ACC_EDGE1

    float inv = 1.f / ws;
    const float inv_bn = rsqrtf(1.0f + 1e-5f);
    float4 bA = ((const float4*)bias)[lane];
    float4 gA = ((const float4*)bn_g)[lane];
    float4 cA = ((const float4*)bn_b)[lane];
    float4 o;
    o.x = lrelu(acc.x * inv + bA.x, 0.01f) * (gA.x * inv_bn) + cA.x;
    o.y = lrelu(acc.y * inv + bA.y, 0.01f) * (gA.y * inv_bn) + cA.y;
    o.z = lrelu(acc.z * inv + bA.z, 0.01f) * (gA.z * inv_bn) + cA.z;
    o.w = lrelu(acc.w * inv + bA.w, 0.01f) * (gA.w * inv_bn) + cA.w;
    uint2 p;
    p.x = pack_half2(o.x, o.y); p.y = pack_half2(o.z, o.w);
    ((uint2*)xout)[(size_t)node * 32 + lane] = p;
}

// ---------------- GCN (fp16 gather, 4-edge batched) ---------------------------
__global__ void k_gcn_agg(const __half* __restrict__ h, const float* __restrict__ dis,
                          const float* __restrict__ bg,
                          const int* __restrict__ rowstart, const int* __restrict__ col,
                          float* __restrict__ xout, int n) {
    int node = blockIdx.x * 8 + (threadIdx.x >> 5);
    int lane = threadIdx.x & 31;
    if (node >= n) return;
    int rs = rowstart[node], re = rowstart[node + 1];
    float wi = dis[node];
    const __half2* h2 = (const __half2*)h;      // row = 32 half2
    float2 acc = make_float2(0.f, 0.f);

    for (int base = rs; base < re; base += 32) {
        int idx = base + lane;
        int ck = col[idx < re ? idx : re - 1];
        int cnt = min(32, re - base);
        int j = 0;
        for (; j + 4 <= cnt; j += 4) {
            int s0 = __shfl_sync(0xffffffffu, ck, j + 0);
            int s1 = __shfl_sync(0xffffffffu, ck, j + 1);
            int s2 = __shfl_sync(0xffffffffu, ck, j + 2);
            int s3 = __shfl_sync(0xffffffffu, ck, j + 3);
            float w0 = dis[s0] * wi, w1 = dis[s1] * wi;
            float w2 = dis[s2] * wi, w3 = dis[s3] * wi;
            float2 v0 = __half22float2(h2[(size_t)s0 * 32 + lane]);
            float2 v1 = __half22float2(h2[(size_t)s1 * 32 + lane]);
            float2 v2 = __half22float2(h2[(size_t)s2 * 32 + lane]);
            float2 v3 = __half22float2(h2[(size_t)s3 * 32 + lane]);
            acc.x += v0.x * w0; acc.y += v0.y * w0;
            acc.x += v1.x * w1; acc.y += v1.y * w1;
            acc.x += v2.x * w2; acc.y += v2.y * w2;
            acc.x += v3.x * w3; acc.y += v3.y * w3;
        }
        for (; j < cnt; j++) {
            int s = __shfl_sync(0xffffffffu, ck, j);
            float w = dis[s] * wi;
            float2 v = __half22float2(h2[(size_t)s * 32 + lane]);
            acc.x += v.x * w; acc.y += v.y * w;
        }
    }
    float2 bgv = ((const float2*)bg)[lane];
    float2 o;
    o.x = lrelu(acc.x + bgv.x, 0.01f);
    o.y = lrelu(acc.y + bgv.y, 0.01f);
    ((float2*)xout)[(size_t)node * 32 + lane] = o;
}

// ---------------- fused pool (segment sum) + MLP ------------------------------
// batch is sorted; block b finds its node range via binary search, computes the
// mean over its nodes, then applies lin1+BN+lrelu and lin2.
__global__ void __launch_bounds__(128) k_pool_mlp(const float* __restrict__ x3,
                                                  const int* __restrict__ batch,
                                                  const float* __restrict__ l1W,
                                                  const float* __restrict__ l1b,
                                                  const float* __restrict__ g3,
                                                  const float* __restrict__ b3,
                                                  const float* __restrict__ l2W,
                                                  const float* __restrict__ l2b,
                                                  float* __restrict__ out) {
    int b = blockIdx.x;
    int t = threadIdx.x;
    __shared__ int seg[2];
    __shared__ float sp2[2][64];
    __shared__ float spool[64];
    __shared__ float sy[128];

    if (t < 2) seg[t] = lbound(batch, Nn, b + t);
    __syncthreads();
    int lo = seg[0], hi = seg[1];

    int ch = t & 63, half = t >> 6;
    float s = 0.f;
    for (int node = lo + half; node < hi; node += 2)
        s += x3[(size_t)node * D3 + ch];
    sp2[half][ch] = s;
    __syncthreads();
    if (t < 64) {
        float cnt = fmaxf((float)(hi - lo), 1.f);
        spool[t] = (sp2[0][t] + sp2[1][t]) / cnt;
    }
    __syncthreads();

    float v = l1b[t];
#pragma unroll
    for (int k = 0; k < 64; k++) v += spool[k] * l1W[k * 128 + t];
    v = v * (g3[t] * rsqrtf(1.0f + 1e-5f)) + b3[t];
    v = lrelu(v, 0.01f);
    sy[t] = v;
    __syncthreads();
    if (t < NCc) {
        float o = l2b[t];
#pragma unroll
        for (int k = 0; k < 128; k++) o += sy[k] * l2W[k * NCc + t];
        out[b * NCc + t] = o;
    }
}

// ---------------- launch -----------------------------------------------------
extern "C" void kernel_launch(void* const* d_in, const int* in_sizes, int n_in,
                              void* d_out, int out_size) {
    const float* x      = (const float*)d_in[0];
    const int*   ei     = (const int*)d_in[1];
    const int*   batch  = (const int*)d_in[2];
    const float* W1     = (const float*)d_in[3];
    const float* a_src1 = (const float*)d_in[4];
    const float* a_dst1 = (const float*)d_in[5];
    const float* b1     = (const float*)d_in[6];
    const float* W2     = (const float*)d_in[7];
    const float* a_src2 = (const float*)d_in[8];
    const float* a_dst2 = (const float*)d_in[9];
    const float* b2     = (const float*)d_in[10];
    const float* Wg     = (const float*)d_in[11];
    const float* bg     = (const float*)d_in[12];
    const float* bn1g   = (const float*)d_in[13];
    const float* bn1b   = (const float*)d_in[14];
    const float* bn2g   = (const float*)d_in[15];
    const float* bn2b   = (const float*)d_in[16];
    const float* bn3g   = (const float*)d_in[17];
    const float* bn3b   = (const float*)d_in[18];
    const float* l1W    = (const float*)d_in[19];
    const float* l1b    = (const float*)d_in[20];
    const float* l2W    = (const float*)d_in[21];
    const float* l2b    = (const float*)d_in[22];
    float* out = (float*)d_out;

    int *deg, *rowstart, *cursor, *col, *partials;
    __half *h1, *h2, *h3, *x1, *x2;
    float *x3, *scs1, *scd1, *scs2, *scd2, *dis;
    cudaGetSymbolAddress((void**)&deg, g_deg);
    cudaGetSymbolAddress((void**)&rowstart, g_rowstart);
    cudaGetSymbolAddress((void**)&cursor, g_cursor);
    cudaGetSymbolAddress((void**)&col, g_col);
    cudaGetSymbolAddress((void**)&partials, g_partials);
    cudaGetSymbolAddress((void**)&h1, g_h1);
    cudaGetSymbolAddress((void**)&x1, g_x1);
    cudaGetSymbolAddress((void**)&h2, g_h2);
    cudaGetSymbolAddress((void**)&x2, g_x2);
    cudaGetSymbolAddress((void**)&h3, g_h3);
    cudaGetSymbolAddress((void**)&x3, g_x3);
    cudaGetSymbolAddress((void**)&scs1, g_scs1);
    cudaGetSymbolAddress((void**)&scd1, g_scd1);
    cudaGetSymbolAddress((void**)&scs2, g_scs2);
    cudaGetSymbolAddress((void**)&scd2, g_scd2);
    cudaGetSymbolAddress((void**)&dis, g_dis);

    const int* src = ei;
    const int* dst = ei + Ee;

    static cudaStream_t s2 = nullptr;
    static cudaEvent_t evFork = nullptr, evJoin = nullptr;
    if (!s2) {
        cudaStreamCreateWithFlags(&s2, cudaStreamNonBlocking);
        cudaEventCreateWithFlags(&evFork, cudaEventDisableTiming);
        cudaEventCreateWithFlags(&evJoin, cudaEventDisableTiming);
    }

    // ---- fork: CSR build on s2, GEMM1+scores on main stream ----
    cudaEventRecord(evFork, 0);
    cudaStreamWaitEvent(s2, evFork, 0);

    k_init_deg<<<(Nn + 255) / 256, 256, 0, s2>>>(deg, Nn);
    k_deg_scatter<<<(Ee + 255) / 256, 256, 0, s2>>>(dst, deg, Ee);
    k_scan_block<<<NB_SCAN, 1024, 0, s2>>>(deg, rowstart, partials, Nn);
    k_scan_partials<<<1, 64, 0, s2>>>(partials, rowstart, NB_SCAN, Nn);
    k_scan_finalize<<<NB_SCAN, 1024, 0, s2>>>(deg, rowstart, partials, Nn);
    k_fill_self<<<(Nn + 255) / 256, 256, 0, s2>>>(rowstart, col, cursor, deg, dis, Nn);
    k_scatter_edges<<<(Ee + 255) / 256, 256, 0, s2>>>(src, dst, cursor, col, Ee);
    cudaEventRecord(evJoin, s2);

    k_gemm_f16<float><<<dim3((Nn + 127) / 128, D1 / 64), 256>>>(x, W1, h1, Nn, D1, Fdim);
    k_scores4<<<(Nn + 7) / 8, 256>>>(h1, a_src1, a_dst1, scs1, scd1, Nn);

    cudaStreamWaitEvent(0, evJoin, 0);

    // ---- GAT layer 1 aggregation ----
    k_gat_agg4<<<(Nn + 7) / 8, 256>>>(h1, scs1, scd1, b1, bn1g, bn1b,
                                      rowstart, col, x1, Nn);

    // ---- GAT layer 2: 256 -> 1 head x 128 ----
    k_gemm_f16<__half><<<dim3((Nn + 127) / 128, D2 / 64), 256>>>(x1, W2, h2, Nn, D2, D1);
    k_scores1<<<(Nn + 7) / 8, 256>>>(h2, a_src2, a_dst2, scs2, scd2, Nn);
    k_gat_agg1<<<(Nn + 7) / 8, 256>>>(h2, scs2, scd2, b2, bn2g, bn2b,
                                      rowstart, col, x2, Nn);

    // ---- GCN: 128 -> 64 ----
    k_gemm_f16<__half><<<dim3((Nn + 127) / 128, D3 / 64), 256>>>(x2, Wg, h3, Nn, D3, D2);
    k_gcn_agg<<<(Nn + 7) / 8, 256>>>(h3, dis, bg, rowstart, col, x3, Nn);

    // ---- fused global mean pool + MLP head ----
    k_pool_mlp<<<Bb, 128>>>(x3, batch, l1W, l1b, bn3g, bn3b, l2W, l2b, out);
}

// round 9
// speedup vs baseline: 1.8144x; 1.0154x over previous
#include <cuda_runtime.h>
#include <cuda_fp16.h>
#include <math_constants.h>
#include <cstdint>

// Problem constants (fixed by reference setup_inputs)
#define Nn   50000
#define Ee   800000
#define E2   (Ee + Nn)
#define Fdim 128
#define D1   256   // 4 heads x 64
#define D2   128   // 1 head x 128
#define D3   64    // GCN out
#define Bb   512
#define NCc  10
#define NB_SCAN ((Nn + 1023) / 1024)

typedef unsigned int u32;

// ---------------- scratch (device globals; no allocation allowed) -----------
__device__ __align__(16) int   g_deg[Nn];
__device__ __align__(16) int   g_rowstart[Nn + 1];
__device__ __align__(16) int   g_cursor[Nn];
__device__ __align__(16) int   g_col[E2];
__device__ __align__(16) int   g_partials[NB_SCAN + 1];

__device__ __align__(16) __half g_h1[(size_t)Nn * D1];
__device__ __align__(16) __half g_x1[(size_t)Nn * D1];
__device__ __align__(16) __half g_h2[(size_t)Nn * D2];
__device__ __align__(16) __half g_x2[(size_t)Nn * D2];
__device__ __align__(16) __half g_h3[(size_t)Nn * D3];
__device__ __align__(16) float  g_x3[(size_t)Nn * D3];
__device__ __align__(16) float  g_scs1[Nn * 4];
__device__ __align__(16) float  g_scd1[Nn * 4];
__device__ __align__(16) float  g_scs2[Nn];
__device__ __align__(16) float  g_scd2[Nn];
__device__ __align__(16) float  g_dis[Nn];

// ---------------- small helpers ---------------------------------------------
__device__ __forceinline__ float lrelu(float v, float s) { return v > 0.f ? v : s * v; }

__device__ __forceinline__ u32 pack_half2(float x, float y) {
    __half2 h = __floats2half2_rn(x, y);
    return *(u32*)&h;
}

__device__ __forceinline__ float sel4(float4 v, int i) {
    float lo = (i & 1) ? v.y : v.x;
    float hi = (i & 1) ? v.w : v.z;
    return (i & 2) ? hi : lo;
}

__device__ __forceinline__ void mma_f16(float* c, const u32* a, const u32* b) {
    asm volatile(
        "mma.sync.aligned.m16n8k16.row.col.f32.f16.f16.f32 "
        "{%0,%1,%2,%3}, {%4,%5,%6,%7}, {%8,%9}, {%0,%1,%2,%3};"
        : "+f"(c[0]), "+f"(c[1]), "+f"(c[2]), "+f"(c[3])
        : "r"(a[0]), "r"(a[1]), "r"(a[2]), "r"(a[3]), "r"(b[0]), "r"(b[1]));
}

__device__ __forceinline__ int lbound(const int* __restrict__ a, int n, int key) {
    int l = 0, r = n;
    while (l < r) { int m = (l + r) >> 1; if (a[m] < key) l = m + 1; else r = m; }
    return l;
}

// ---------------- CSR build --------------------------------------------------
__global__ void k_init_deg(int* deg, int n) {
    int i = blockIdx.x * blockDim.x + threadIdx.x;
    if (i < n) deg[i] = 1;  // self-loop
}

__global__ void k_deg_scatter(const int* __restrict__ dst, int* deg, int e) {
    int i = blockIdx.x * blockDim.x + threadIdx.x;
    if (i < e) atomicAdd(&deg[dst[i]], 1);
}

__global__ void k_scan_block(const int* __restrict__ deg, int* __restrict__ rowstart,
                             int* __restrict__ partials, int n) {
    __shared__ int s[1024];
    int t = threadIdx.x;
    int gi = blockIdx.x * 1024 + t;
    int v = (gi < n) ? deg[gi] : 0;
    s[t] = v;
    __syncthreads();
#pragma unroll
    for (int off = 1; off < 1024; off <<= 1) {
        int xv = (t >= off) ? s[t - off] : 0;
        __syncthreads();
        s[t] += xv;
        __syncthreads();
    }
    if (gi < n) rowstart[gi] = s[t];          // block-inclusive
    if (t == 1023) partials[blockIdx.x] = s[t];
}

__global__ void k_scan_partials(int* partials, int* rowstart, int nb, int n) {
    __shared__ int wsum[2];
    int t = threadIdx.x;
    int lane = t & 31, w = t >> 5;
    int orig = (t < nb) ? partials[t] : 0;
    int v = orig;
#pragma unroll
    for (int o = 1; o < 32; o <<= 1) {
        int xv = __shfl_up_sync(0xffffffffu, v, o);
        if (lane >= o) v += xv;
    }
    if (lane == 31) wsum[w] = v;
    __syncthreads();
    if (w == 1) v += wsum[0];
    if (t < nb) partials[t] = v - orig;   // exclusive
    if (t == 63) rowstart[n] = v;         // total (= N + E)
}

__global__ void k_scan_finalize(const int* __restrict__ deg, int* __restrict__ rowstart,
                                const int* __restrict__ partials, int n) {
    int gi = blockIdx.x * 1024 + threadIdx.x;
    if (gi < n) rowstart[gi] = rowstart[gi] - deg[gi] + partials[blockIdx.x];
}

__global__ void k_fill_self(const int* __restrict__ rowstart, int* __restrict__ col,
                            int* __restrict__ cursor, const int* __restrict__ deg,
                            float* __restrict__ dis, int n) {
    int i = blockIdx.x * blockDim.x + threadIdx.x;
    if (i < n) {
        int rs = rowstart[i];
        col[rs] = i;
        cursor[i] = rs + 1;
        dis[i] = rsqrtf((float)deg[i]);
    }
}

__global__ void k_scatter_edges(const int* __restrict__ src, const int* __restrict__ dst,
                                int* cursor, int* __restrict__ col, int e) {
    int i = blockIdx.x * blockDim.x + threadIdx.x;
    if (i < e) {
        int pos = atomicAdd(&cursor[dst[i]], 1);
        col[pos] = src[i];
    }
}

// ---------------- fp16 tensor-core GEMM --------------------------------------
// C[M,N] = A[M,K] @ B[K,N].  BM=128, BN=64, BK=32, 256 threads (8 warps, 4x2).
template <typename AT>
__global__ void __launch_bounds__(256) k_gemm_f16(const AT* __restrict__ A,
                                                  const float* __restrict__ B,
                                                  __half* __restrict__ C,
                                                  int M, int N, int K) {
    __shared__ u32 As[128][20];
    __shared__ u32 Bhi[64][20];

    int tid = threadIdx.x;
    int bm0 = blockIdx.x * 128, bn0 = blockIdx.y * 64;
    int w = tid >> 5, lane = tid & 31;
    int wm = (w & 3) * 32, wn = (w >> 2) * 32;
    int g = lane >> 2, t = lane & 3;

    float acc[2][4][4] = {};

    for (int kt = 0; kt < K; kt += 32) {
        if constexpr (sizeof(AT) == 4) {
            const float* Af = (const float*)A;
            int r = tid >> 1, cb = (tid & 1) * 16;
            bool ok = (bm0 + r) < M;
#pragma unroll
            for (int i = 0; i < 4; i++) {
                float4 v = make_float4(0.f, 0.f, 0.f, 0.f);
                if (ok) v = *(const float4*)(Af + (size_t)(bm0 + r) * K + kt + cb + 4 * i);
                As[r][(cb >> 1) + 2 * i]     = pack_half2(v.x, v.y);
                As[r][(cb >> 1) + 2 * i + 1] = pack_half2(v.z, v.w);
            }
        } else {
            const __half* Ah = (const __half*)A;
#pragma unroll
            for (int it = 0; it < 2; it++) {
                int idx = tid + it * 256;
                int r = idx >> 2, ch = (idx & 3) * 8;
                uint4 v = make_uint4(0u, 0u, 0u, 0u);
                if (bm0 + r < M) v = *(const uint4*)(Ah + (size_t)(bm0 + r) * K + kt + ch);
                As[r][(ch >> 1) + 0] = v.x; As[r][(ch >> 1) + 1] = v.y;
                As[r][(ch >> 1) + 2] = v.z; As[r][(ch >> 1) + 3] = v.w;
            }
        }
        {
            int r2 = tid >> 4;
            int c4 = (tid & 15) * 4;
            float4 v0 = *(const float4*)(B + (size_t)(kt + 2 * r2) * N + bn0 + c4);
            float4 v1 = *(const float4*)(B + (size_t)(kt + 2 * r2 + 1) * N + bn0 + c4);
            const float* p0 = &v0.x;
            const float* p1 = &v1.x;
#pragma unroll
            for (int i = 0; i < 4; i++)
                Bhi[c4 + i][r2] = pack_half2(p0[i], p1[i]);
        }
        __syncthreads();

#pragma unroll
        for (int kk = 0; kk < 2; kk++) {
            int kb = kk * 8;
            u32 af[2][4], bh[4][2];
#pragma unroll
            for (int mt = 0; mt < 2; mt++) {
                int r = wm + mt * 16 + g;
                af[mt][0] = As[r][kb + t];       af[mt][1] = As[r + 8][kb + t];
                af[mt][2] = As[r][kb + 4 + t];   af[mt][3] = As[r + 8][kb + 4 + t];
            }
#pragma unroll
            for (int nt = 0; nt < 4; nt++) {
                int c = wn + nt * 8 + g;
                bh[nt][0] = Bhi[c][kb + t]; bh[nt][1] = Bhi[c][kb + 4 + t];
            }
#pragma unroll
            for (int mt = 0; mt < 2; mt++)
#pragma unroll
                for (int nt = 0; nt < 4; nt++)
                    mma_f16(acc[mt][nt], af[mt], bh[nt]);
        }
        __syncthreads();
    }

#pragma unroll
    for (int mt = 0; mt < 2; mt++) {
        int r0 = bm0 + wm + mt * 16 + g;
#pragma unroll
        for (int nt = 0; nt < 4; nt++) {
            int c = bn0 + wn + nt * 8 + 2 * t;
            if (r0 < M)
                *(__half2*)(C + (size_t)r0 * N + c) =
                    __floats2half2_rn(acc[mt][nt][0], acc[mt][nt][1]);
            if (r0 + 8 < M)
                *(__half2*)(C + (size_t)(r0 + 8) * N + c) =
                    __floats2half2_rn(acc[mt][nt][2], acc[mt][nt][3]);
        }
    }
}

// ---------------- GAT attention scores (fp16 h) -------------------------------
__global__ void k_scores4(const __half* __restrict__ h, const float* __restrict__ a_src,
                          const float* __restrict__ a_dst, float* __restrict__ scs,
                          float* __restrict__ scd, int n) {
    int node = blockIdx.x * 8 + (threadIdx.x >> 5);
    int lane = threadIdx.x & 31;
    if (node >= n) return;
#pragma unroll
    for (int hd = 0; hd < 4; hd++) {
        float2 hv = __half22float2(*(const __half2*)(h + (size_t)node * D1 + hd * 64 + 2 * lane));
        float2 as = *(const float2*)(a_src + hd * 64 + 2 * lane);
        float2 ad = *(const float2*)(a_dst + hd * 64 + 2 * lane);
        float ps = hv.x * as.x + hv.y * as.y;
        float pd = hv.x * ad.x + hv.y * ad.y;
#pragma unroll
        for (int off = 16; off; off >>= 1) {
            ps += __shfl_xor_sync(0xffffffffu, ps, off);
            pd += __shfl_xor_sync(0xffffffffu, pd, off);
        }
        if (lane == 0) { scs[node * 4 + hd] = ps; scd[node * 4 + hd] = pd; }
    }
}

__global__ void k_scores1(const __half* __restrict__ h, const float* __restrict__ a_src,
                          const float* __restrict__ a_dst, float* __restrict__ scs,
                          float* __restrict__ scd, int n) {
    int node = blockIdx.x * 8 + (threadIdx.x >> 5);
    int lane = threadIdx.x & 31;
    if (node >= n) return;
    uint2 raw = *(const uint2*)(h + (size_t)node * D2 + 4 * lane);
    float2 f0 = __half22float2(*(const __half2*)&raw.x);
    float2 f1 = __half22float2(*(const __half2*)&raw.y);
    float4 as = *(const float4*)(a_src + 4 * lane);
    float4 ad = *(const float4*)(a_dst + 4 * lane);
    float ps = f0.x * as.x + f0.y * as.y + f1.x * as.z + f1.y * as.w;
    float pd = f0.x * ad.x + f0.y * ad.y + f1.x * ad.z + f1.y * ad.w;
#pragma unroll
    for (int off = 16; off; off >>= 1) {
        ps += __shfl_xor_sync(0xffffffffu, ps, off);
        pd += __shfl_xor_sync(0xffffffffu, pd, off);
    }
    if (lane == 0) { scs[node] = ps; scd[node] = pd; }
}

// ---------------- GAT1 aggregation: lane = 8 channels of one head -------------
// Row = 256 halves = 32 lanes x uint4. Weight is per-lane scalar (head = lane>>3).
__global__ void k_gat_agg4(const __half* __restrict__ h, const float* __restrict__ scs,
                           const float* __restrict__ scd_arr,
                           const float* __restrict__ bias,
                           const float* __restrict__ bn_g, const float* __restrict__ bn_b,
                           const int* __restrict__ rowstart, const int* __restrict__ col,
                           __half* __restrict__ xout, int n) {
    int node = blockIdx.x * 8 + (threadIdx.x >> 5);
    int lane = threadIdx.x & 31;
    if (node >= n) return;
    int rs = rowstart[node], re = rowstart[node + 1];
    int hd = lane >> 3;

    float scd_h = scd_arr[node * 4 + hd];
    const uint4* hu = (const uint4*)h;          // row = 32 uint4
    const float4* scs4 = (const float4*)scs;

    float acc[8] = {};
    float ws = 0.f;

#define ACC_E4(sv, r)                                                          \
    {                                                                          \
        float wv = __expf(lrelu(sel4(sv, hd) + scd_h, 0.2f));                  \
        float2 f;                                                              \
        f = __half22float2(*(const __half2*)&(r).x); acc[0] += f.x * wv; acc[1] += f.y * wv; \
        f = __half22float2(*(const __half2*)&(r).y); acc[2] += f.x * wv; acc[3] += f.y * wv; \
        f = __half22float2(*(const __half2*)&(r).z); acc[4] += f.x * wv; acc[5] += f.y * wv; \
        f = __half22float2(*(const __half2*)&(r).w); acc[6] += f.x * wv; acc[7] += f.y * wv; \
        ws += wv;                                                              \
    }

    for (int base = rs; base < re; base += 32) {
        int idx = base + lane;
        int ck = col[idx < re ? idx : re - 1];
        int cnt = min(32, re - base);
        int j = 0;
        for (; j + 4 <= cnt; j += 4) {
            int s0 = __shfl_sync(0xffffffffu, ck, j + 0);
            int s1 = __shfl_sync(0xffffffffu, ck, j + 1);
            int s2 = __shfl_sync(0xffffffffu, ck, j + 2);
            int s3 = __shfl_sync(0xffffffffu, ck, j + 3);
            float4 sv0 = scs4[s0], sv1 = scs4[s1], sv2 = scs4[s2], sv3 = scs4[s3];
            uint4 r0 = hu[(size_t)s0 * 32 + lane];
            uint4 r1 = hu[(size_t)s1 * 32 + lane];
            uint4 r2 = hu[(size_t)s2 * 32 + lane];
            uint4 r3 = hu[(size_t)s3 * 32 + lane];
            ACC_E4(sv0, r0)
            ACC_E4(sv1, r1)
            ACC_E4(sv2, r2)
            ACC_E4(sv3, r3)
        }
        for (; j < cnt; j++) {
            int s = __shfl_sync(0xffffffffu, ck, j);
            float4 sv = scs4[s];
            uint4 r = hu[(size_t)s * 32 + lane];
            ACC_E4(sv, r)
        }
    }
#undef ACC_E4

    float inv = 1.f / ws;
    const float inv_bn = rsqrtf(1.0f + 1e-5f);
    float4 b0 = ((const float4*)bias)[2 * lane],  b1 = ((const float4*)bias)[2 * lane + 1];
    float4 g0 = ((const float4*)bn_g)[2 * lane],  g1 = ((const float4*)bn_g)[2 * lane + 1];
    float4 c0 = ((const float4*)bn_b)[2 * lane],  c1 = ((const float4*)bn_b)[2 * lane + 1];
    float o[8];
    o[0] = lrelu(acc[0] * inv + b0.x, 0.01f) * (g0.x * inv_bn) + c0.x;
    o[1] = lrelu(acc[1] * inv + b0.y, 0.01f) * (g0.y * inv_bn) + c0.y;
    o[2] = lrelu(acc[2] * inv + b0.z, 0.01f) * (g0.z * inv_bn) + c0.z;
    o[3] = lrelu(acc[3] * inv + b0.w, 0.01f) * (g0.w * inv_bn) + c0.w;
    o[4] = lrelu(acc[4] * inv + b1.x, 0.01f) * (g1.x * inv_bn) + c1.x;
    o[5] = lrelu(acc[5] * inv + b1.y, 0.01f) * (g1.y * inv_bn) + c1.y;
    o[6] = lrelu(acc[6] * inv + b1.z, 0.01f) * (g1.z * inv_bn) + c1.z;
    o[7] = lrelu(acc[7] * inv + b1.w, 0.01f) * (g1.w * inv_bn) + c1.w;
    uint4 p;
    p.x = pack_half2(o[0], o[1]); p.y = pack_half2(o[2], o[3]);
    p.z = pack_half2(o[4], o[5]); p.w = pack_half2(o[6], o[7]);
    ((uint4*)xout)[(size_t)node * 32 + lane] = p;
}

// ---------------- GAT2 aggregation: 16-lane subgroups, 2 edges in flight -----
__global__ void k_gat_agg1(const __half* __restrict__ h, const float* __restrict__ scs,
                           const float* __restrict__ scd_arr,
                           const float* __restrict__ bias,
                           const float* __restrict__ bn_g, const float* __restrict__ bn_b,
                           const int* __restrict__ rowstart, const int* __restrict__ col,
                           __half* __restrict__ xout, int n) {
    int node = blockIdx.x * 8 + (threadIdx.x >> 5);
    int lane = threadIdx.x & 31;
    if (node >= n) return;
    int rs = rowstart[node], re = rowstart[node + 1];
    int sub = lane >> 4, sl = lane & 15;

    float scd0 = scd_arr[node];
    const uint4* hu = (const uint4*)h;          // row = 16 uint4

    float acc[8] = {};
    float ws = 0.f;

#define ACC_E1(e, r)                                                           \
    {                                                                          \
        float wv = __expf(lrelu((e) + scd0, 0.2f));                            \
        float2 f;                                                              \
        f = __half22float2(*(const __half2*)&(r).x); acc[0] += f.x * wv; acc[1] += f.y * wv; \
        f = __half22float2(*(const __half2*)&(r).y); acc[2] += f.x * wv; acc[3] += f.y * wv; \
        f = __half22float2(*(const __half2*)&(r).z); acc[4] += f.x * wv; acc[5] += f.y * wv; \
        f = __half22float2(*(const __half2*)&(r).w); acc[6] += f.x * wv; acc[7] += f.y * wv; \
        ws += wv;                                                              \
    }

    for (int base = rs; base < re; base += 32) {
        int idx = base + lane;
        int ck = col[idx < re ? idx : re - 1];
        int cnt = min(32, re - base);
        int j = 0;
        for (; j + 4 <= cnt; j += 4) {
            int sa = __shfl_sync(0xffffffffu, ck, j + sub);
            int sb = __shfl_sync(0xffffffffu, ck, j + 2 + sub);
            float ea = scs[sa], eb = scs[sb];
            uint4 ra = hu[(size_t)sa * 16 + sl];
            uint4 rb = hu[(size_t)sb * 16 + sl];
            ACC_E1(ea, ra)
            ACC_E1(eb, rb)
        }
        for (; j < cnt; j++) {
            int s = __shfl_sync(0xffffffffu, ck, j);
            if ((j & 1) == sub) {
                float e = scs[s];
                uint4 r = hu[(size_t)s * 16 + sl];
                ACC_E1(e, r)
            }
        }
    }
#undef ACC_E1

    // merge the two subgroups (same channels at lane ^ 16)
#pragma unroll
    for (int i = 0; i < 8; i++) acc[i] += __shfl_xor_sync(0xffffffffu, acc[i], 16);
    ws += __shfl_xor_sync(0xffffffffu, ws, 16);

    float inv = 1.f / ws;
    const float inv_bn = rsqrtf(1.0f + 1e-5f);
    float4 b0 = ((const float4*)bias)[2 * sl],  b1 = ((const float4*)bias)[2 * sl + 1];
    float4 g0 = ((const float4*)bn_g)[2 * sl],  g1 = ((const float4*)bn_g)[2 * sl + 1];
    float4 c0 = ((const float4*)bn_b)[2 * sl],  c1 = ((const float4*)bn_b)[2 * sl + 1];
    float o[8];
    o[0] = lrelu(acc[0] * inv + b0.x, 0.01f) * (g0.x * inv_bn) + c0.x;
    o[1] = lrelu(acc[1] * inv + b0.y, 0.01f) * (g0.y * inv_bn) + c0.y;
    o[2] = lrelu(acc[2] * inv + b0.z, 0.01f) * (g0.z * inv_bn) + c0.z;
    o[3] = lrelu(acc[3] * inv + b0.w, 0.01f) * (g0.w * inv_bn) + c0.w;
    o[4] = lrelu(acc[4] * inv + b1.x, 0.01f) * (g1.x * inv_bn) + c1.x;
    o[5] = lrelu(acc[5] * inv + b1.y, 0.01f) * (g1.y * inv_bn) + c1.y;
    o[6] = lrelu(acc[6] * inv + b1.z, 0.01f) * (g1.z * inv_bn) + c1.z;
    o[7] = lrelu(acc[7] * inv + b1.w, 0.01f) * (g1.w * inv_bn) + c1.w;
    if (sub == 0) {
        uint4 p;
        p.x = pack_half2(o[0], o[1]); p.y = pack_half2(o[2], o[3]);
        p.z = pack_half2(o[4], o[5]); p.w = pack_half2(o[6], o[7]);
        ((uint4*)xout)[(size_t)node * 16 + sl] = p;
    }
}

// ---------------- GCN aggregation: 8-lane subgroups, 4 edges in flight -------
__global__ void k_gcn_agg(const __half* __restrict__ h, const float* __restrict__ dis,
                          const float* __restrict__ bg,
                          const int* __restrict__ rowstart, const int* __restrict__ col,
                          float* __restrict__ xout, int n) {
    int node = blockIdx.x * 8 + (threadIdx.x >> 5);
    int lane = threadIdx.x & 31;
    if (node >= n) return;
    int rs = rowstart[node], re = rowstart[node + 1];
    int sub = lane >> 3, sl = lane & 7;
    float wi = dis[node];
    const uint4* hu = (const uint4*)h;          // row = 8 uint4

    float acc[8] = {};

#define ACC_G(wv, r)                                                           \
    {                                                                          \
        float2 f;                                                              \
        f = __half22float2(*(const __half2*)&(r).x); acc[0] += f.x * (wv); acc[1] += f.y * (wv); \
        f = __half22float2(*(const __half2*)&(r).y); acc[2] += f.x * (wv); acc[3] += f.y * (wv); \
        f = __half22float2(*(const __half2*)&(r).z); acc[4] += f.x * (wv); acc[5] += f.y * (wv); \
        f = __half22float2(*(const __half2*)&(r).w); acc[6] += f.x * (wv); acc[7] += f.y * (wv); \
    }

    for (int base = rs; base < re; base += 32) {
        int idx = base + lane;
        int ck = col[idx < re ? idx : re - 1];
        int cnt = min(32, re - base);
        int j = 0;
        for (; j + 4 <= cnt; j += 4) {
            int s = __shfl_sync(0xffffffffu, ck, j + sub);
            float w = dis[s] * wi;
            uint4 r = hu[(size_t)s * 8 + sl];
            ACC_G(w, r)
        }
        for (; j < cnt; j++) {
            int s = __shfl_sync(0xffffffffu, ck, j);
            if ((j & 3) == sub) {
                float w = dis[s] * wi;
                uint4 r = hu[(size_t)s * 8 + sl];
                ACC_G(w, r)
            }
        }
    }
#undef ACC_G

    // merge 4 subgroups (channels match at lane^8, lane^16)
#pragma unroll
    for (int i = 0; i < 8; i++) {
        acc[i] += __shfl_xor_sync(0xffffffffu, acc[i], 8);
        acc[i] += __shfl_xor_sync(0xffffffffu, acc[i], 16);
    }

    if (sub == 0) {
        float4 bg0 = ((const float4*)bg)[2 * sl], bg1 = ((const float4*)bg)[2 * sl + 1];
        float4 o0, o1;
        o0.x = lrelu(acc[0] + bg0.x, 0.01f); o0.y = lrelu(acc[1] + bg0.y, 0.01f);
        o0.z = lrelu(acc[2] + bg0.z, 0.01f); o0.w = lrelu(acc[3] + bg0.w, 0.01f);
        o1.x = lrelu(acc[4] + bg1.x, 0.01f); o1.y = lrelu(acc[5] + bg1.y, 0.01f);
        o1.z = lrelu(acc[6] + bg1.z, 0.01f); o1.w = lrelu(acc[7] + bg1.w, 0.01f);
        ((float4*)xout)[(size_t)node * 16 + 2 * sl]     = o0;
        ((float4*)xout)[(size_t)node * 16 + 2 * sl + 1] = o1;
    }
}

// ---------------- fused pool (segment sum) + MLP ------------------------------
__global__ void __launch_bounds__(128) k_pool_mlp(const float* __restrict__ x3,
                                                  const int* __restrict__ batch,
                                                  const float* __restrict__ l1W,
                                                  const float* __restrict__ l1b,
                                                  const float* __restrict__ g3,
                                                  const float* __restrict__ b3,
                                                  const float* __restrict__ l2W,
                                                  const float* __restrict__ l2b,
                                                  float* __restrict__ out) {
    int b = blockIdx.x;
    int t = threadIdx.x;
    __shared__ int seg[2];
    __shared__ float sp2[2][64];
    __shared__ float spool[64];
    __shared__ float sy[128];

    if (t < 2) seg[t] = lbound(batch, Nn, b + t);
    __syncthreads();
    int lo = seg[0], hi = seg[1];

    int ch = t & 63, half = t >> 6;
    float s = 0.f;
    for (int node = lo + half; node < hi; node += 2)
        s += x3[(size_t)node * D3 + ch];
    sp2[half][ch] = s;
    __syncthreads();
    if (t < 64) {
        float cnt = fmaxf((float)(hi - lo), 1.f);
        spool[t] = (sp2[0][t] + sp2[1][t]) / cnt;
    }
    __syncthreads();

    float v = l1b[t];
#pragma unroll
    for (int k = 0; k < 64; k++) v += spool[k] * l1W[k * 128 + t];
    v = v * (g3[t] * rsqrtf(1.0f + 1e-5f)) + b3[t];
    v = lrelu(v, 0.01f);
    sy[t] = v;
    __syncthreads();
    if (t < NCc) {
        float o = l2b[t];
#pragma unroll
        for (int k = 0; k < 128; k++) o += sy[k] * l2W[k * NCc + t];
        out[b * NCc + t] = o;
    }
}

// ---------------- launch -----------------------------------------------------
extern "C" void kernel_launch(void* const* d_in, const int* in_sizes, int n_in,
                              void* d_out, int out_size) {
    const float* x      = (const float*)d_in[0];
    const int*   ei     = (const int*)d_in[1];
    const int*   batch  = (const int*)d_in[2];
    const float* W1     = (const float*)d_in[3];
    const float* a_src1 = (const float*)d_in[4];
    const float* a_dst1 = (const float*)d_in[5];
    const float* b1     = (const float*)d_in[6];
    const float* W2     = (const float*)d_in[7];
    const float* a_src2 = (const float*)d_in[8];
    const float* a_dst2 = (const float*)d_in[9];
    const float* b2     = (const float*)d_in[10];
    const float* Wg     = (const float*)d_in[11];
    const float* bg     = (const float*)d_in[12];
    const float* bn1g   = (const float*)d_in[13];
    const float* bn1b   = (const float*)d_in[14];
    const float* bn2g   = (const float*)d_in[15];
    const float* bn2b   = (const float*)d_in[16];
    const float* bn3g   = (const float*)d_in[17];
    const float* bn3b   = (const float*)d_in[18];
    const float* l1W    = (const float*)d_in[19];
    const float* l1b    = (const float*)d_in[20];
    const float* l2W    = (const float*)d_in[21];
    const float* l2b    = (const float*)d_in[22];
    float* out = (float*)d_out;

    int *deg, *rowstart, *cursor, *col, *partials;
    __half *h1, *h2, *h3, *x1, *x2;
    float *x3, *scs1, *scd1, *scs2, *scd2, *dis;
    cudaGetSymbolAddress((void**)&deg, g_deg);
    cudaGetSymbolAddress((void**)&rowstart, g_rowstart);
    cudaGetSymbolAddress((void**)&cursor, g_cursor);
    cudaGetSymbolAddress((void**)&col, g_col);
    cudaGetSymbolAddress((void**)&partials, g_partials);
    cudaGetSymbolAddress((void**)&h1, g_h1);
    cudaGetSymbolAddress((void**)&x1, g_x1);
    cudaGetSymbolAddress((void**)&h2, g_h2);
    cudaGetSymbolAddress((void**)&x2, g_x2);
    cudaGetSymbolAddress((void**)&h3, g_h3);
    cudaGetSymbolAddress((void**)&x3, g_x3);
    cudaGetSymbolAddress((void**)&scs1, g_scs1);
    cudaGetSymbolAddress((void**)&scd1, g_scd1);
    cudaGetSymbolAddress((void**)&scs2, g_scs2);
    cudaGetSymbolAddress((void**)&scd2, g_scd2);
    cudaGetSymbolAddress((void**)&dis, g_dis);

    const int* src = ei;
    const int* dst = ei + Ee;

    static cudaStream_t s2 = nullptr;
    static cudaEvent_t evFork = nullptr, evJoin = nullptr;
    if (!s2) {
        cudaStreamCreateWithFlags(&s2, cudaStreamNonBlocking);
        cudaEventCreateWithFlags(&evFork, cudaEventDisableTiming);
        cudaEventCreateWithFlags(&evJoin, cudaEventDisableTiming);
    }

    // ---- fork: CSR build on s2, GEMM1+scores on main stream ----
    cudaEventRecord(evFork, 0);
    cudaStreamWaitEvent(s2, evFork, 0);

    k_init_deg<<<(Nn + 255) / 256, 256, 0, s2>>>(deg, Nn);
    k_deg_scatter<<<(Ee + 255) / 256, 256, 0, s2>>>(dst, deg, Ee);
    k_scan_block<<<NB_SCAN, 1024, 0, s2>>>(deg, rowstart, partials, Nn);
    k_scan_partials<<<1, 64, 0, s2>>>(partials, rowstart, NB_SCAN, Nn);
    k_scan_finalize<<<NB_SCAN, 1024, 0, s2>>>(deg, rowstart, partials, Nn);
    k_fill_self<<<(Nn + 255) / 256, 256, 0, s2>>>(rowstart, col, cursor, deg, dis, Nn);
    k_scatter_edges<<<(Ee + 255) / 256, 256, 0, s2>>>(src, dst, cursor, col, Ee);
    cudaEventRecord(evJoin, s2);

    k_gemm_f16<float><<<dim3((Nn + 127) / 128, D1 / 64), 256>>>(x, W1, h1, Nn, D1, Fdim);
    k_scores4<<<(Nn + 7) / 8, 256>>>(h1, a_src1, a_dst1, scs1, scd1, Nn);

    cudaStreamWaitEvent(0, evJoin, 0);

    // ---- GAT layer 1 aggregation ----
    k_gat_agg4<<<(Nn + 7) / 8, 256>>>(h1, scs1, scd1, b1, bn1g, bn1b,
                                      rowstart, col, x1, Nn);

    // ---- GAT layer 2: 256 -> 1 head x 128 ----
    k_gemm_f16<__half><<<dim3((Nn + 127) / 128, D2 / 64), 256>>>(x1, W2, h2, Nn, D2, D1);
    k_scores1<<<(Nn + 7) / 8, 256>>>(h2, a_src2, a_dst2, scs2, scd2, Nn);
    k_gat_agg1<<<(Nn + 7) / 8, 256>>>(h2, scs2, scd2, b2, bn2g, bn2b,
                                      rowstart, col, x2, Nn);

    // ---- GCN: 128 -> 64 ----
    k_gemm_f16<__half><<<dim3((Nn + 127) / 128, D3 / 64), 256>>>(x2, Wg, h3, Nn, D3, D2);
    k_gcn_agg<<<(Nn + 7) / 8, 256>>>(h3, dis, bg, rowstart, col, x3, Nn);

    // ---- fused global mean pool + MLP head ----
    k_pool_mlp<<<Bb, 128>>>(x3, batch, l1W, l1b, bn3g, bn3b, l2W, l2b, out);
}